// round 12
// baseline (speedup 1.0000x reference)
#include <cuda_runtime.h>
#include <cstdint>

#define NN 10000
#define NE 80000

__device__ float g_xn  [NN*576];
__device__ float g_rad [NE*384];
__device__ float g_val0[NE*128];
__device__ float g_gdir[NE*256];
__device__ float g_gten[NE*256];
__device__ float g_e   [NE*8];
__device__ float g_xjp [NN*1024];
__device__ float g_num [NN*1152];
__device__ float g_den [NN*8];
__device__ float g_x1  [NN*576];
__device__ float g_yn  [NN*576];
__device__ float g_h   [NN*1024];
__device__ float g_gsil[NN*128];
__device__ float g_gsig[NN*128];

// pre-converted tf32 weights in fragment-interleaved SMEM-image layout
__device__ __align__(16) uint32_t g_W1c [16896];
__device__ __align__(16) uint32_t g_W2c [50688];
__device__ __align__(16) uint32_t g_Wm0c[118272];
__device__ __align__(16) uint32_t g_Wc1c[50688];
__device__ __align__(16) uint32_t g_Wc2c[50688];
__device__ __align__(16) uint32_t g_Wpc [26112];
__device__ __align__(16) uint32_t g_Wf1c[25344];
__device__ __align__(16) uint32_t g_Wf2c[26112];
__device__ __align__(16) uint32_t g_Wxjc[8448];
__device__ __align__(16) uint32_t g_Wgc [8448];

__device__ __forceinline__ float sigm(float z) { return 1.f / (1.f + __expf(-z)); }

__device__ __forceinline__ uint32_t f2tf(float x) {
    uint32_t r; asm("cvt.rna.tf32.f32 %0, %1;" : "=r"(r) : "f"(x)); return r;
}
__device__ __forceinline__ void red2(float* p, float a, float b) {
    asm volatile("red.global.add.v2.f32 [%0], {%1,%2};" :: "l"(p), "f"(a), "f"(b) : "memory");
}
__device__ __forceinline__ void mma8(float* d, uint32_t a0,uint32_t a1,uint32_t a2,uint32_t a3,
                                     uint32_t b0,uint32_t b1) {
    asm volatile("mma.sync.aligned.m16n8k8.row.col.f32.tf32.tf32.f32 "
                 "{%0,%1,%2,%3},{%4,%5,%6,%7},{%8,%9},{%0,%1,%2,%3};"
                 : "+f"(d[0]),"+f"(d[1]),"+f"(d[2]),"+f"(d[3])
                 : "r"(a0),"r"(a1),"r"(a2),"r"(a3),"r"(b0),"r"(b1));
}

// ---- cp.async helpers ----
__device__ __forceinline__ void cp16(uint32_t saddr, const uint32_t* src) {
    asm volatile("cp.async.cg.shared.global [%0], [%1], 16;" :: "r"(saddr), "l"(src));
}
#define CP_COMMIT() asm volatile("cp.async.commit_group;" ::: "memory")
#define CP_WAIT0()  asm volatile("cp.async.wait_group 0;" ::: "memory")
#define CP_WAIT1()  asm volatile("cp.async.wait_group 1;" ::: "memory")

template<int N4, int NT>
__device__ __forceinline__ void cp_chunk(uint32_t* dst, const uint32_t* __restrict__ src, int t) {
    uint32_t d = (uint32_t)__cvta_generic_to_shared(dst);
    for (int i = t; i < N4; i += NT) cp16(d + i*16, src + i*4);
    CP_COMMIT();
}

__device__ __forceinline__ int pairpos(int k, int n, int QS) {
    return (k>>3)*4*QS + (k&3)*QS + n*2 + ((k>>2)&1);
}

template<int XST, int QS, int NK>
__device__ __forceinline__ void gemm_mma(const uint32_t* __restrict__ Ws,
                                         const uint32_t* __restrict__ Xs,
                                         int lane, int mg, int ng, float acc[8][4])
{
    const uint32_t* xb = Xs + (mg*32 + (lane>>2))*XST + (lane&3);
    const uint32_t* wb = Ws + (lane&3)*QS + (ng*32 + (lane>>2))*2;
#pragma unroll 4
    for (int kk = 0; kk < NK; kk++) {
        const uint32_t* xp = xb + kk*8;
        uint32_t a00 = xp[0],      a01 = xp[8*XST],   a02 = xp[4],        a03 = xp[8*XST+4];
        uint32_t a10 = xp[16*XST], a11 = xp[24*XST],  a12 = xp[16*XST+4], a13 = xp[24*XST+4];
        const uint32_t* wp = wb + kk*4*QS;
        uint2 b[4];
#pragma unroll
        for (int nt = 0; nt < 4; nt++) b[nt] = *(const uint2*)(wp + nt*16);
#pragma unroll
        for (int nt = 0; nt < 4; nt++) {
            mma8(acc[nt],   a00,a01,a02,a03, b[nt].x, b[nt].y);
            mma8(acc[4+nt], a10,a11,a12,a13, b[nt].x, b[nt].y);
        }
    }
}

// ---------------- weight pre-conversion ----------------
__global__ void __launch_bounds__(256) wconv_kernel(
    const float* __restrict__ W1, const float* __restrict__ W2,
    const float* __restrict__ Wm0, const float* __restrict__ Wc1,
    const float* __restrict__ Wc2, const float* __restrict__ Wp,
    const float* __restrict__ Wf1, const float* __restrict__ Wf2,
    const float* __restrict__ Wxj, const float* __restrict__ Wg)
{
    int i = blockIdx.x*256 + threadIdx.x;
    if (i < 16384) { int k=i>>7, n=i&127;
        g_W1c[pairpos(k,n,264)] = f2tf(W1[i]); return; } i -= 16384;
    if (i < 49152) { int j=i/16384, r=i&16383, k=r>>7, n=r&127;
        g_W2c[j*16896 + pairpos(k,n,264)] = f2tf(W2[k*384 + j*128 + n]); return; } i -= 49152;
    if (i < 114688){ int j=i/16384, r=i&16383, k=r>>7, n=r&127;
        g_Wm0c[j*16896 + pairpos(k,n,264)] = f2tf(Wm0[k*896 + j*128 + n]); return; } i -= 114688;
    if (i < 49152) { int d=i>>14, r=i&16383, k=r>>7, n=r&127;
        g_Wc1c[d*16896 + pairpos(k,n,264)] = f2tf(Wc1[i]); return; } i -= 49152;
    if (i < 49152) { int d=i>>14, r=i&16383, k=r>>7, n=r&127;
        g_Wc2c[d*16896 + pairpos(k,n,264)] = f2tf(Wc2[i]); return; } i -= 49152;
    if (i < 24576) { int d=i>>13, r=i&8191, k=r>>6, n=r&63;
        g_Wpc[d*8704 + pairpos(k,n,136)] = f2tf(Wp[i]); return; } i -= 24576;
    if (i < 16384) { int d=(i>>13)+1, r=i&8191, k=r>>7, n=r&127;
        g_Wf1c[d*8448 + pairpos(k,n,264)] = f2tf(Wf1[d*8192 + r]); return; } i -= 16384;
    if (i < 24576) { int d=i>>13, r=i&8191, k=r>>6, n=r&63;
        g_Wf2c[d*8704 + pairpos(k,n,136)] = f2tf(Wf2[i]); return; } i -= 24576;
    if (i < 8192)  { int k=i>>7, n=i&127;
        g_Wxjc[pairpos(k,n,264)] = f2tf(Wxj[i]); return; } i -= 8192;
    if (i < 8192)  { int k=i>>7, n=i&127;
        g_Wgc[pairpos(k,n,264)] = f2tf(Wg[i]); return; }
}
#define WCONV_N 360448

__global__ void zero_kernel() {
    size_t i = (size_t)blockIdx.x * blockDim.x + threadIdx.x;
    if (i < NN*1152/4) ((float4*)g_num)[i] = make_float4(0.f,0.f,0.f,0.f);
    if (i < NN*8)      g_den[i] = 0.f;
}

// ---------------- enorm ----------------
__global__ void __launch_bounds__(256) enorm_kernel(const float* __restrict__ src, float* __restrict__ dst) {
    int n = blockIdx.x*4 + (threadIdx.x >> 6);
    int c = threadIdx.x & 63;
    const float* p = src + (size_t)n*576 + c;
    float v[9];
#pragma unroll
    for (int k = 0; k < 9; k++) v[k] = p[k*64];
    float s0 = v[0]*v[0];
    float s1 = v[1]*v[1] + v[2]*v[2] + v[3]*v[3];
    float s2 = v[4]*v[4] + v[5]*v[5] + v[6]*v[6] + v[7]*v[7] + v[8]*v[8];
#pragma unroll
    for (int off = 16; off; off >>= 1) {
        s0 += __shfl_xor_sync(0xffffffffu, s0, off);
        s1 += __shfl_xor_sync(0xffffffffu, s1, off);
        s2 += __shfl_xor_sync(0xffffffffu, s2, off);
    }
    __shared__ float red[4][3][2];
    int g = threadIdx.x >> 6, hw = (c >> 5);
    if ((c & 31) == 0) { red[g][0][hw] = s0; red[g][1][hw] = s1; red[g][2][hw] = s2; }
    __syncthreads();
    float sc0 = rsqrtf((red[g][0][0]+red[g][0][1]) * (1.f/64.f)  + 1e-6f);
    float sc1 = rsqrtf((red[g][1][0]+red[g][1][1]) * (1.f/192.f) + 1e-6f);
    float sc2 = rsqrtf((red[g][2][0]+red[g][2][1]) * (1.f/320.f) + 1e-6f);
    float* q = dst + (size_t)n*576 + c;
    q[0] = v[0]*sc0;
#pragma unroll
    for (int k = 1; k < 4; k++) q[k*64] = v[k]*sc1;
#pragma unroll
    for (int k = 4; k < 9; k++) q[k*64] = v[k]*sc2;
}

// ---------------- xjp: 80000 rows x 128, K=64 ----------------
#define XJ_GRID 1250
__global__ void __launch_bounds__(256) xjp_mma()
{
    extern __shared__ uint32_t sm[];
    uint32_t* Xs = sm;            // 4352
    uint32_t* Ws = sm + 4352;     // 8448
    int rbase = blockIdx.x * 64;
    int t = threadIdx.x, lane = t & 31, w = t >> 5, mg = w & 1, ng = w >> 1;
    cp_chunk<2112,256>(Ws, g_Wxjc, t);
    {
        int r = t >> 2, q = t & 3;
        int gr = rbase + r;
        int node = gr >> 3, slot = 1 + (gr & 7);
        const float4* yp = (const float4*)&g_xn[(size_t)node*576 + slot*64 + q*16];
        uint32_t* col = Xs + r*68 + q*16;
#pragma unroll
        for (int i = 0; i < 4; i++) {
            float4 v = yp[i];
            *(uint4*)(col + i*4) = make_uint4(f2tf(v.x), f2tf(v.y), f2tf(v.z), f2tf(v.w));
        }
    }
    CP_WAIT0();
    __syncthreads();
    float acc[8][4] = {};
    gemm_mma<68,264,8>(Ws, Xs, lane, mg, ng, acc);
    int nbase = ng*32 + (lane&3)*2;
    int ebase = mg*32 + (lane>>2);
#pragma unroll
    for (int mt = 0; mt < 2; mt++)
#pragma unroll
    for (int hf = 0; hf < 2; hf++) {
        int gr = rbase + ebase + mt*16 + hf*8;
        int node = gr >> 3, slot = gr & 7;
        size_t ob = (size_t)node*1024 + (size_t)slot*128;
#pragma unroll
        for (int nt = 0; nt < 4; nt++) {
            int n = nbase + nt*8;
            *(float2*)&g_xjp[ob + n] =
                make_float2(acc[mt*4+nt][hf*2+0], acc[mt*4+nt][hf*2+1]);
        }
    }
}

// ---------------- gate: 10000 rows x 128, K=64 ----------------
#define GATE_GRID 157
__global__ void __launch_bounds__(256) gate_mma(const float* __restrict__ bg)
{
    extern __shared__ uint32_t sm[];
    uint32_t* Xs = sm;
    uint32_t* Ws = sm + 4352;
    int rbase = blockIdx.x * 64;
    int t = threadIdx.x, lane = t & 31, w = t >> 5, mg = w & 1, ng = w >> 1;
    cp_chunk<2112,256>(Ws, g_Wgc, t);
    {
        int r = t >> 2, q = t & 3;
        int node = rbase + r;
        uint32_t* col = Xs + r*68 + q*16;
        if (node < NN) {
            const float4* yp = (const float4*)&g_yn[(size_t)node*576 + q*16];
#pragma unroll
            for (int i = 0; i < 4; i++) {
                float4 v = yp[i];
                *(uint4*)(col + i*4) = make_uint4(f2tf(v.x), f2tf(v.y), f2tf(v.z), f2tf(v.w));
            }
        } else {
#pragma unroll
            for (int i = 0; i < 4; i++) *(uint4*)(col + i*4) = make_uint4(0,0,0,0);
        }
    }
    CP_WAIT0();
    __syncthreads();
    float acc[8][4] = {};
    gemm_mma<68,264,8>(Ws, Xs, lane, mg, ng, acc);
    int nbase = ng*32 + (lane&3)*2;
    int ebase = mg*32 + (lane>>2);
#pragma unroll
    for (int mt = 0; mt < 2; mt++)
#pragma unroll
    for (int hf = 0; hf < 2; hf++) {
        int node = rbase + ebase + mt*16 + hf*8;
        if (node >= NN) continue;
        size_t ob = (size_t)node*128;
#pragma unroll
        for (int nt = 0; nt < 4; nt++) {
            int n = nbase + nt*8;
            float z0 = acc[mt*4+nt][hf*2+0] + bg[n];
            float z1 = acc[mt*4+nt][hf*2+1] + bg[n+1];
            float s0 = sigm(z0), s1 = sigm(z1);
            *(float2*)&g_gsil[ob + n] = make_float2(z0*s0, z1*s1);
            *(float2*)&g_gsig[ob + n] = make_float2(s0, s1);
        }
    }
}

// ---------------- radial MLP: 128 edges/block, 16-quarter weight pipeline ----------------
__global__ void __launch_bounds__(512,2) rad_kernel(
    const float* __restrict__ edist, const float* __restrict__ semb,
    const float* __restrict__ temb,  const float* __restrict__ b1,
    const float* __restrict__ b2,    const int* __restrict__ anum,
    const int* __restrict__ eidx)
{
    extern __shared__ uint32_t sm[];
    uint32_t* ef = sm;            // 16896
    uint32_t* Ws = sm + 16896;    // 8448
    int* zsrc = (int*)(sm + 25344);
    int* ztgt = zsrc + 128;
    int e0 = blockIdx.x * 128, t = threadIdx.x;
    int lane = t & 31, w = t >> 5, mg = w & 3, ng = w >> 2;
    auto qsrc = [](int m) { return m < 4 ? g_W1c + m*4224 : g_W2c + (m-4)*4224; };
    cp_chunk<1056,512>(Ws,        qsrc(0), t);
    cp_chunk<1056,512>(Ws + 4224, qsrc(1), t);
    if (t < 128)      zsrc[t]     = anum[eidx[e0 + t]];
    else if (t < 256) ztgt[t-128] = anum[eidx[NE + e0 + t - 128]];
    __syncthreads();
    {
        int e = t >> 2, q = t & 3;
        const float4* xp;
        if (q < 2)      xp = (const float4*)&edist[(size_t)(e0+e)*64 + q*32];
        else if (q==2)  xp = (const float4*)&semb[(size_t)zsrc[e]*32];
        else            xp = (const float4*)&temb[(size_t)ztgt[e]*32];
        uint32_t* col = ef + e*132 + q*32;
#pragma unroll
        for (int i4 = 0; i4 < 8; i4++) {
            float4 v = xp[i4];
            *(uint4*)(col + i4*4) = make_uint4(f2tf(v.x), f2tf(v.y), f2tf(v.z), f2tf(v.w));
        }
    }
    int nbase = ng*32 + (lane&3)*2;
    int ebase = mg*32 + (lane>>2);
    int m = 0;
    {
        float acc[8][4] = {};
        for (int q = 0; q < 4; q++, m++) {
            if (m + 1 < 16) CP_WAIT1(); else CP_WAIT0();
            __syncthreads();
            gemm_mma<132,264,4>(Ws + (m&1)*4224, ef + q*32, lane, mg, ng, acc);
            __syncthreads();
            if (m + 2 < 16) cp_chunk<1056,512>(Ws + (m&1)*4224, qsrc(m+2), t);
        }
#pragma unroll
        for (int nt = 0; nt < 4; nt++) {
            int n = nbase + nt*8;
            float2 bb = *(const float2*)&b1[n];
#pragma unroll
            for (int mt = 0; mt < 2; mt++)
#pragma unroll
            for (int hf = 0; hf < 2; hf++) {
                int el = ebase + mt*16 + hf*8;
                float z0 = acc[mt*4+nt][hf*2+0] + bb.x;
                float z1 = acc[mt*4+nt][hf*2+1] + bb.y;
                *(uint2*)(ef + el*132 + n) = make_uint2(f2tf(z0*sigm(z0)), f2tf(z1*sigm(z1)));
            }
        }
    }
    for (int j = 0; j < 3; j++) {
        float acc[8][4] = {};
        for (int q = 0; q < 4; q++, m++) {
            if (m + 1 < 16) CP_WAIT1(); else CP_WAIT0();
            __syncthreads();
            gemm_mma<132,264,4>(Ws + (m&1)*4224, ef + q*32, lane, mg, ng, acc);
            __syncthreads();
            if (m + 2 < 16) cp_chunk<1056,512>(Ws + (m&1)*4224, qsrc(m+2), t);
        }
#pragma unroll
        for (int nt = 0; nt < 4; nt++) {
            int n = nbase + nt*8;
            float2 bb = *(const float2*)&b2[j*128 + n];
#pragma unroll
            for (int mt = 0; mt < 2; mt++)
#pragma unroll
            for (int hf = 0; hf < 2; hf++) {
                int el = ebase + mt*16 + hf*8;
                *(float2*)&g_rad[(size_t)(e0+el)*384 + j*128 + n] =
                    make_float2(acc[mt*4+nt][hf*2+0] + bb.x, acc[mt*4+nt][hf*2+1] + bb.y);
            }
        }
    }
}

// ---------------- extra: 28-quarter weight pipeline ----------------
__global__ void __launch_bounds__(512,2) extra_kernel(
    const float* __restrict__ lng, const float* __restrict__ lnb,
    const float* __restrict__ adot, const int* __restrict__ eidx)
{
    extern __shared__ uint32_t sm[];
    uint32_t* Xs = sm;
    uint32_t* Ws = sm + 16896;
    int* src_s = (int*)(sm + 25344);
    int* tgt_s = src_s + 128;
    int e0 = blockIdx.x * 128, t = threadIdx.x;
    int lane = t & 31, w = t >> 5, mg = w & 3, ng = w >> 2;
    cp_chunk<1056,512>(Ws,        g_Wm0c,        t);
    cp_chunk<1056,512>(Ws + 4224, g_Wm0c + 4224, t);
    if (t < 128)      src_s[t]     = eidx[e0 + t];
    else if (t < 256) tgt_s[t-128] = eidx[NE + e0 + t - 128];
    __syncthreads();
    {
        int e = t >> 2, q = t & 3;
        const float4* rp = (const float4*)&g_rad[(size_t)(e0+e)*384 + q*32];
        const float4* xp = (q < 2)
            ? (const float4*)&g_xn[(size_t)src_s[e]*576 + q*32]
            : (const float4*)&g_xn[(size_t)tgt_s[e]*576 + (q-2)*32];
        uint32_t* col = Xs + e*132 + q*32;
#pragma unroll
        for (int i4 = 0; i4 < 8; i4++) {
            float4 xv = xp[i4], rv = rp[i4];
            *(uint4*)(col + i4*4) =
                make_uint4(f2tf(xv.x*rv.x), f2tf(xv.y*rv.y), f2tf(xv.z*rv.z), f2tf(xv.w*rv.w));
        }
    }
    int nbase = ng*32 + (lane&3)*2;
    int ebase = mg*32 + (lane>>2);
    int m = 0;
    for (int oc = 0; oc < 7; oc++) {
        float acc[8][4] = {};
        for (int q = 0; q < 4; q++, m++) {
            if (m + 1 < 28) CP_WAIT1(); else CP_WAIT0();
            __syncthreads();
            gemm_mma<132,264,4>(Ws + (m&1)*4224, Xs + q*32, lane, mg, ng, acc);
            __syncthreads();
            if (m + 2 < 28) cp_chunk<1056,512>(Ws + (m&1)*4224, g_Wm0c + (m+2)*4224, t);
        }
        if (oc < 2) {
            int h = oc*4 + ng;
#pragma unroll
            for (int mt = 0; mt < 2; mt++)
#pragma unroll
            for (int hf = 0; hf < 2; hf++) {
                int el = ebase + mt*16 + hf*8;
                float sum = 0.f, ssq = 0.f;
#pragma unroll
                for (int nt = 0; nt < 4; nt++) {
                    float v0 = acc[mt*4+nt][hf*2+0], v1 = acc[mt*4+nt][hf*2+1];
                    sum += v0 + v1; ssq += v0*v0 + v1*v1;
                }
                sum += __shfl_xor_sync(0xffffffffu, sum, 1);
                sum += __shfl_xor_sync(0xffffffffu, sum, 2);
                ssq += __shfl_xor_sync(0xffffffffu, ssq, 1);
                ssq += __shfl_xor_sync(0xffffffffu, ssq, 2);
                float mean = sum * (1.f/32.f);
                float rs = rsqrtf(ssq * (1.f/32.f) - mean*mean + 1e-5f);
                float logit = 0.f;
#pragma unroll
                for (int nt = 0; nt < 4; nt++) {
                    int a = nt*8 + (lane&3)*2;
#pragma unroll
                    for (int jj = 0; jj < 2; jj++) {
                        float v = acc[mt*4+nt][hf*2+jj];
                        float an = (v - mean)*rs*lng[a+jj] + lnb[a+jj];
                        logit += (0.2f*an + 0.8f*an*sigm(an)) * adot[h*32 + a + jj];
                    }
                }
                logit += __shfl_xor_sync(0xffffffffu, logit, 1);
                logit += __shfl_xor_sync(0xffffffffu, logit, 2);
                if ((lane & 3) == 0) {
                    float ex = __expf(logit);
                    g_e[(size_t)(e0+el)*8 + h] = ex;
                    atomicAdd(&g_den[(size_t)tgt_s[el]*8 + h], ex);
                }
            }
        } else if (oc == 2) {
#pragma unroll
            for (int nt = 0; nt < 4; nt++) {
                int n = nbase + nt*8;
#pragma unroll
                for (int mt = 0; mt < 2; mt++)
#pragma unroll
                for (int hf = 0; hf < 2; hf++) {
                    int el = ebase + mt*16 + hf*8;
                    float z0 = acc[mt*4+nt][hf*2+0], z1 = acc[mt*4+nt][hf*2+1];
                    *(float2*)&g_val0[(size_t)(e0+el)*128 + n] =
                        make_float2(z0*sigm(z0), z1*sigm(z1));
                }
            }
        } else {
            int which = oc - 3;
            float* base = (which < 2) ? g_gdir : g_gten;
            int l = which & 1;
#pragma unroll
            for (int nt = 0; nt < 4; nt++) {
                int n = nbase + nt*8;
#pragma unroll
                for (int mt = 0; mt < 2; mt++)
#pragma unroll
                for (int hf = 0; hf < 2; hf++) {
                    int el = ebase + mt*16 + hf*8;
                    *(float2*)&base[(size_t)(e0+el)*256 + l*128 + n] =
                        make_float2(sigm(acc[mt*4+nt][hf*2+0]), sigm(acc[mt*4+nt][hf*2+1]));
                }
            }
        }
    }
}

// ---------------- fused conv1+conv2: 68-quarter pipeline, 2 blocks/SM ----------------
__device__ __forceinline__ const uint32_t* conv_qsrc(int m) {
    if (m < 4) return g_Wc2c + m*4224;
    m -= 4;
    int deg, rem;
    if (m < 24) { deg = 1; rem = m; } else { deg = 2; rem = m - 24; }
    int within = rem & 7;
    const uint32_t* base = (within < 4) ? g_Wc1c : g_Wc2c;
    return base + deg*16896 + (within & 3)*4224;
}

__global__ void __launch_bounds__(512,2) conv_kernel(
    const float* __restrict__ rl, const int* __restrict__ eidx)
{
    extern __shared__ uint32_t sm[];
    uint32_t* XV = sm;             // 16896
    uint32_t* Ws = sm + 16896;     // 8448 (2 x 4224)
    float* rl_s = (float*)(sm + 25344);   // 1024
    float* ee_s = (float*)(sm + 26368);   // 1024
    int* src_s = (int*)(sm + 27392);      // 128
    int* tgt_s = (int*)(sm + 27520);      // 128
    int e0 = blockIdx.x * 128, t = threadIdx.x;
    int lane = t & 31, w = t >> 5, mg = w & 3, ng = w >> 2;
    cp_chunk<1056,512>(Ws,        conv_qsrc(0), t);
    cp_chunk<1056,512>(Ws + 4224, conv_qsrc(1), t);
    if (t < 128)      src_s[t]     = eidx[e0 + t];
    else if (t < 256) tgt_s[t-128] = eidx[NE + e0 + t - 128];
    for (int i = t; i < 1024; i += 512) {
        rl_s[i] = rl[(size_t)e0*8 + i];
        ee_s[i] = g_e[(size_t)e0*8 + i];
    }
    int nbase = ng*32 + (lane&3)*2;
    int ebase = mg*32 + (lane>>2);
    int se = t >> 2, sq = t & 3;
    int m = 0;

    for (int k = 0; k < 9; k++) {
        int deg = (k == 0) ? 0 : ((k < 4) ? 1 : 2);
        // ---- stage XV (weights for this slot are in flight) ----
        if (k == 0) {
            const float4* vp = (const float4*)&g_val0[(size_t)(e0+se)*128 + sq*32];
            uint32_t* col = XV + se*132 + sq*32;
#pragma unroll
            for (int i4 = 0; i4 < 8; i4++) {
                float4 v = vp[i4];
                *(uint4*)(col + i4*4) = make_uint4(f2tf(v.x), f2tf(v.y), f2tf(v.z), f2tf(v.w));
            }
        } else {
            const float4* rp = (const float4*)&g_rad[(size_t)(e0+se)*384 + deg*128 + sq*32];
            const float4* xp = (sq < 2)
                ? (const float4*)&g_xn[(size_t)src_s[se]*576 + k*64 + sq*32]
                : (const float4*)&g_xn[(size_t)tgt_s[se]*576 + k*64 + (sq-2)*32];
            uint32_t* col = XV + se*132 + sq*32;
#pragma unroll
            for (int i4 = 0; i4 < 8; i4++) {
                float4 xv = xp[i4], rv = rp[i4];
                *(uint4*)(col + i4*4) =
                    make_uint4(f2tf(xv.x*rv.x), f2tf(xv.y*rv.y), f2tf(xv.z*rv.z), f2tf(xv.w*rv.w));
            }
        }
        __syncthreads();   // XV staged (and prior conv2 reads done)
        if (deg) {
            // ---- conv1 over 4 streamed quarters ----
            float acc[8][4] = {};
            for (int q = 0; q < 4; q++, m++) {
                if (m + 1 < 68) CP_WAIT1(); else CP_WAIT0();
                __syncthreads();
                gemm_mma<132,264,4>(Ws + (m&1)*4224, XV + q*32, lane, mg, ng, acc);
                __syncthreads();
                if (m + 2 < 68) cp_chunk<1056,512>(Ws + (m&1)*4224, conv_qsrc(m+2), t);
            }
            // ---- gate epilogue ----
            int l = (k < 4) ? 0 : 1;
#pragma unroll
            for (int mt = 0; mt < 2; mt++)
#pragma unroll
            for (int hf = 0; hf < 2; hf++) {
                int el = ebase + mt*16 + hf*8;
                size_t ge = (size_t)(e0 + el);
                float r = rl_s[el*8 + (k-1)];
                size_t gb = ge*256 + l*128;
                size_t xb = (size_t)src_s[el]*1024 + (size_t)(k-1)*128;
#pragma unroll
                for (int nt = 0; nt < 4; nt++) {
                    int n = nbase + nt*8;
                    float2 gd = *(const float2*)&g_gdir[gb + n];
                    float2 gt = *(const float2*)&g_gten[gb + n];
                    float2 xj = *(const float2*)&g_xjp[xb + n];
                    acc[mt*4+nt][hf*2+0] += r*gd.x + xj.x*gt.x;
                    acc[mt*4+nt][hf*2+1] += r*gd.y + xj.y*gt.y;
                }
            }
            __syncthreads();   // conv1 reads of XV done everywhere
#pragma unroll
            for (int mt = 0; mt < 2; mt++)
#pragma unroll
            for (int hf = 0; hf < 2; hf++) {
                int el = ebase + mt*16 + hf*8;
#pragma unroll
                for (int nt = 0; nt < 4; nt++) {
                    int n = nbase + nt*8;
                    *(uint2*)(XV + el*132 + n) =
                        make_uint2(f2tf(acc[mt*4+nt][hf*2+0]), f2tf(acc[mt*4+nt][hf*2+1]));
                }
            }
            __syncthreads();   // val visible
        }
        // ---- conv2 over 4 streamed quarters + scatter ----
        float acc[8][4] = {};
        for (int q = 0; q < 4; q++, m++) {
            if (m + 1 < 68) CP_WAIT1(); else CP_WAIT0();
            __syncthreads();
            gemm_mma<132,264,4>(Ws + (m&1)*4224, XV + q*32, lane, mg, ng, acc);
            __syncthreads();
            if (m + 2 < 68) cp_chunk<1056,512>(Ws + (m&1)*4224, conv_qsrc(m+2), t);
        }
#pragma unroll
        for (int mt = 0; mt < 2; mt++)
#pragma unroll
        for (int hf = 0; hf < 2; hf++) {
            int el = ebase + mt*16 + hf*8;
            size_t nb = (size_t)tgt_s[el]*1152 + (size_t)k*128;
#pragma unroll
            for (int nt = 0; nt < 4; nt++) {
                int n = nbase + nt*8;
                float s = ee_s[el*8 + (n >> 4)];
                red2(&g_num[nb + n], acc[mt*4+nt][hf*2+0]*s, acc[mt*4+nt][hf*2+1]*s);
            }
        }
        __syncthreads();
    }
}

// ---------------- node GEMMs ----------------
#define P_T0 79
#define P_T1 314
#define P_GRID 705
__device__ __forceinline__ void node_row(int b, int* deg, int* rbase,
                                         int* nslots, int* soff, int* nrows)
{
    if (b < P_T0)      { *deg=0; *rbase=b*128;          *nslots=1; *soff=0; *nrows=10000; }
    else if (b < P_T1) { *deg=1; *rbase=(b-P_T0)*128;   *nslots=3; *soff=1; *nrows=30000; }
    else               { *deg=2; *rbase=(b-P_T1)*128;   *nslots=5; *soff=4; *nrows=50000; }
}

__global__ void __launch_bounds__(256,2) proj_mma(
    const float* __restrict__ x, const float* __restrict__ bp)
{
    extern __shared__ uint32_t sm[];
    uint32_t* Xs = sm;            // 16896
    uint32_t* Ws = sm + 16896;    // 8704
    int deg, rbase, nslots, soff, nrows;
    node_row(blockIdx.x, &deg, &rbase, &nslots, &soff, &nrows);
    int t = threadIdx.x, lane = t & 31, w = t >> 5, mg = w & 3, ng = w >> 2;
    cp_chunk<2176,256>(Ws, g_Wpc + deg*8704, t);
    {
        int r = t >> 1, h2 = t & 1;
        int gr = rbase + r;
        uint32_t* col = Xs + r*132 + h2*64;
        if (gr < nrows) {
            int node = gr / nslots, slot = soff + gr % nslots;
            const float4* np = (const float4*)&g_num[(size_t)node*1152 + slot*128 + h2*64];
            float di[4];
#pragma unroll
            for (int q = 0; q < 4; q++) di[q] = 1.f / (g_den[node*8 + h2*4 + q] + 1e-30f);
#pragma unroll
            for (int i = 0; i < 16; i++) {
                float4 v = np[i]; float d = di[i>>2];
                *(uint4*)(col + i*4) = make_uint4(f2tf(v.x*d), f2tf(v.y*d), f2tf(v.z*d), f2tf(v.w*d));
            }
        } else {
#pragma unroll
            for (int i = 0; i < 16; i++) *(uint4*)(col + i*4) = make_uint4(0,0,0,0);
        }
    }
    CP_WAIT0();
    __syncthreads();
    float acc[8][4] = {};
    gemm_mma<132,136,16>(Ws, Xs, lane, mg, ng, acc);
    int nbase = ng*32 + (lane&3)*2;
    int ebase = mg*32 + (lane>>2);
#pragma unroll
    for (int mt = 0; mt < 2; mt++)
#pragma unroll
    for (int hf = 0; hf < 2; hf++) {
        int gr = rbase + ebase + mt*16 + hf*8;
        if (gr >= nrows) continue;
        int node = gr / nslots, slot = soff + gr % nslots;
        size_t ob = (size_t)node*576 + slot*64;
#pragma unroll
        for (int nt = 0; nt < 4; nt++) {
            int n = nbase + nt*8;
            float b0 = (slot == 0) ? bp[n] : 0.f, b1 = (slot == 0) ? bp[n+1] : 0.f;
            *(float2*)&g_x1[ob + n] = make_float2(
                x[ob + n]   + acc[mt*4+nt][hf*2+0] + b0,
                x[ob + n+1] + acc[mt*4+nt][hf*2+1] + b1);
        }
    }
}

__global__ void __launch_bounds__(256,2) ffn2_mma(
    const float* __restrict__ bf2, float* __restrict__ out)
{
    extern __shared__ uint32_t sm[];
    uint32_t* Xs = sm;
    uint32_t* Ws = sm + 16896;
    int deg, rbase, nslots, soff, nrows;
    node_row(blockIdx.x, &deg, &rbase, &nslots, &soff, &nrows);
    int t = threadIdx.x, lane = t & 31, w = t >> 5, mg = w & 3, ng = w >> 2;
    cp_chunk<2176,256>(Ws, g_Wf2c + deg*8704, t);
    {
        int r = t >> 1, h2 = t & 1;
        int gr = rbase + r;
        uint32_t* col = Xs + r*132 + h2*64;
        if (gr < nrows) {
            int node = gr / nslots, slot = soff + gr % nslots;
            const float4* hp = (slot == 0)
                ? (const float4*)&g_gsil[(size_t)node*128 + h2*64]
                : (const float4*)&g_h[(size_t)node*1024 + (size_t)(slot-1)*128 + h2*64];
#pragma unroll
            for (int i = 0; i < 16; i++) {
                float4 v = hp[i];
                *(uint4*)(col + i*4) = make_uint4(f2tf(v.x), f2tf(v.y), f2tf(v.z), f2tf(v.w));
            }
        } else {
#pragma unroll
            for (int i = 0; i < 16; i++) *(uint4*)(col + i*4) = make_uint4(0,0,0,0);
        }
    }
    CP_WAIT0();
    __syncthreads();
    float acc[8][4] = {};
    gemm_mma<132,136,16>(Ws, Xs, lane, mg, ng, acc);
    int nbase = ng*32 + (lane&3)*2;
    int ebase = mg*32 + (lane>>2);
#pragma unroll
    for (int mt = 0; mt < 2; mt++)
#pragma unroll
    for (int hf = 0; hf < 2; hf++) {
        int gr = rbase + ebase + mt*16 + hf*8;
        if (gr >= nrows) continue;
        int node = gr / nslots, slot = soff + gr % nslots;
        size_t ob = (size_t)node*576 + slot*64;
#pragma unroll
        for (int nt = 0; nt < 4; nt++) {
            int n = nbase + nt*8;
            float b0 = (slot == 0) ? bf2[n] : 0.f, b1 = (slot == 0) ? bf2[n+1] : 0.f;
            *(float2*)&out[ob + n] = make_float2(
                g_x1[ob + n]   + acc[mt*4+nt][hf*2+0] + b0,
                g_x1[ob + n+1] + acc[mt*4+nt][hf*2+1] + b1);
        }
    }
}

#define F_T1 469
#define F_GRID 1251
__global__ void __launch_bounds__(256) ffn1_mma()
{
    extern __shared__ uint32_t sm[];
    uint32_t* Xs = sm;            // 4352
    uint32_t* Ws = sm + 4352;     // 8448
    int b = blockIdx.x, deg, rbase, nslots, soff, nrows;
    if (b < F_T1) { deg=1; rbase=b*64;         nslots=3; soff=1; nrows=30000; }
    else          { deg=2; rbase=(b-F_T1)*64;  nslots=5; soff=4; nrows=50000; }
    int t = threadIdx.x, lane = t & 31, w = t >> 5, mg = w & 1, ng = w >> 1;
    cp_chunk<2112,256>(Ws, g_Wf1c + deg*8448, t);
    {
        int r = t >> 2, q = t & 3;
        int gr = rbase + r;
        uint32_t* col = Xs + r*68 + q*16;
        if (gr < nrows) {
            int node = gr / nslots, slot = soff + gr % nslots;
            const float4* yp = (const float4*)&g_yn[(size_t)node*576 + slot*64 + q*16];
#pragma unroll
            for (int i = 0; i < 4; i++) {
                float4 v = yp[i];
                *(uint4*)(col + i*4) = make_uint4(f2tf(v.x), f2tf(v.y), f2tf(v.z), f2tf(v.w));
            }
        } else {
#pragma unroll
            for (int i = 0; i < 4; i++) *(uint4*)(col + i*4) = make_uint4(0,0,0,0);
        }
    }
    CP_WAIT0();
    __syncthreads();
    float acc[8][4] = {};
    gemm_mma<68,264,8>(Ws, Xs, lane, mg, ng, acc);
    int nbase = ng*32 + (lane&3)*2;
    int ebase = mg*32 + (lane>>2);
#pragma unroll
    for (int mt = 0; mt < 2; mt++)
#pragma unroll
    for (int hf = 0; hf < 2; hf++) {
        int gr = rbase + ebase + mt*16 + hf*8;
        if (gr >= nrows) continue;
        int node = gr / nslots, slot = soff + gr % nslots;
        size_t hb = (size_t)node*1024 + (size_t)(slot-1)*128;
        size_t gsb = (size_t)node*128;
#pragma unroll
        for (int nt = 0; nt < 4; nt++) {
            int n = nbase + nt*8;
            float2 gs = *(const float2*)&g_gsig[gsb + n];
            *(float2*)&g_h[hb + n] = make_float2(
                acc[mt*4+nt][hf*2+0]*gs.x, acc[mt*4+nt][hf*2+1]*gs.y);
        }
    }
}

// ---------------- launch ----------------
extern "C" void kernel_launch(void* const* d_in, const int* in_sizes, int n_in,
                              void* d_out, int out_size)
{
    const float* x     = (const float*)d_in[0];
    const float* edist = (const float*)d_in[1];
    const float* rl    = (const float*)d_in[2];
    const float* semb  = (const float*)d_in[3];
    const float* temb  = (const float*)d_in[4];
    const float* W1    = (const float*)d_in[5];
    const float* b1    = (const float*)d_in[6];
    const float* W2    = (const float*)d_in[7];
    const float* b2    = (const float*)d_in[8];
    const float* Wc1   = (const float*)d_in[9];
    const float* Wm0   = (const float*)d_in[10];
    const float* lng   = (const float*)d_in[11];
    const float* lnb   = (const float*)d_in[12];
    const float* adot  = (const float*)d_in[13];
    const float* Wxj   = (const float*)d_in[14];
    const float* Wc2   = (const float*)d_in[15];
    const float* Wp    = (const float*)d_in[16];
    const float* bp    = (const float*)d_in[17];
    const float* Wg    = (const float*)d_in[18];
    const float* bg    = (const float*)d_in[19];
    const float* Wf1   = (const float*)d_in[20];
    const float* Wf2   = (const float*)d_in[22];
    const float* bf2   = (const float*)d_in[23];
    const int*   anum  = (const int*)d_in[24];
    const int*   eidx  = (const int*)d_in[25];
    float* out = (float*)d_out;

    float *p_xn, *p_x1, *p_yn;
    cudaGetSymbolAddress((void**)&p_xn, g_xn);
    cudaGetSymbolAddress((void**)&p_x1, g_x1);
    cudaGetSymbolAddress((void**)&p_yn, g_yn);

    static bool attr_set = false;
    if (!attr_set) {
        cudaFuncSetAttribute(rad_kernel,   cudaFuncAttributeMaxDynamicSharedMemorySize, 102400);
        cudaFuncSetAttribute(extra_kernel, cudaFuncAttributeMaxDynamicSharedMemorySize, 102400);
        cudaFuncSetAttribute(conv_kernel,  cudaFuncAttributeMaxDynamicSharedMemorySize, 110592);
        cudaFuncSetAttribute(proj_mma,     cudaFuncAttributeMaxDynamicSharedMemorySize, 102400);
        cudaFuncSetAttribute(ffn2_mma,     cudaFuncAttributeMaxDynamicSharedMemorySize, 102400);
        cudaFuncSetAttribute(ffn1_mma,     cudaFuncAttributeMaxDynamicSharedMemorySize, 51200);
        cudaFuncSetAttribute(xjp_mma,      cudaFuncAttributeMaxDynamicSharedMemorySize, 51200);
        cudaFuncSetAttribute(gate_mma,     cudaFuncAttributeMaxDynamicSharedMemorySize, 51200);
        attr_set = true;
    }

    wconv_kernel<<<(WCONV_N + 255)/256, 256>>>(W1, W2, Wm0, Wc1, Wc2, Wp, Wf1, Wf2, Wxj, Wg);
    zero_kernel<<<(NN*1152/4 + 255)/256, 256>>>();
    enorm_kernel<<<NN/4, 256>>>(x, p_xn);
    xjp_mma<<<XJ_GRID, 256, 51200>>>();
    rad_kernel<<<NE/128, 512, 102400>>>(edist, semb, temb, b1, b2, anum, eidx);
    extra_kernel<<<NE/128, 512, 102400>>>(lng, lnb, adot, eidx);
    conv_kernel<<<NE/128, 512, 110592>>>(rl, eidx);
    proj_mma<<<P_GRID, 256, 102400>>>(x, bp);
    enorm_kernel<<<NN/4, 256>>>(p_x1, p_yn);
    gate_mma<<<GATE_GRID, 256, 51200>>>(bg);
    ffn1_mma<<<F_GRID, 256, 51200>>>();
    ffn2_mma<<<P_GRID, 256, 102400>>>(bf2, out);
}

// round 13
// speedup vs baseline: 1.2593x; 1.2593x over previous
#include <cuda_runtime.h>
#include <cstdint>

#define NN 10000
#define NE 80000

__device__ float g_xn  [NN*576];
__device__ float g_rad [NE*384];
__device__ float g_val0[NE*128];
__device__ float g_gdir[NE*256];
__device__ float g_gten[NE*256];
__device__ float g_e   [NE*8];
__device__ float g_xjp [NN*1024];
__device__ float g_num [NN*1152];
__device__ float g_den [NN*8];
__device__ float g_x1  [NN*576];
__device__ float g_yn  [NN*576];
__device__ float g_h   [NN*1024];
__device__ float g_gsil[NN*128];
__device__ float g_gsig[NN*128];

// pre-converted bf16-pair weights in fragment-interleaved SMEM-image layout:
// word(k2,n) at (k2>>3)*4*QS + (k2&3)*QS + 2n + ((k2>>2)&1), packing W[2k2][n],W[2k2+1][n]
__device__ __align__(16) uint32_t g_W1c [8448];
__device__ __align__(16) uint32_t g_W2c [25344];
__device__ __align__(16) uint32_t g_Wm0c[59136];
__device__ __align__(16) uint32_t g_Wc1c[25344];
__device__ __align__(16) uint32_t g_Wc2c[25344];
__device__ __align__(16) uint32_t g_Wpc [13056];
__device__ __align__(16) uint32_t g_Wf1c[12672];
__device__ __align__(16) uint32_t g_Wf2c[13056];
__device__ __align__(16) uint32_t g_Wxjc[4224];
__device__ __align__(16) uint32_t g_Wgc [4224];

__device__ __forceinline__ float sigm(float z) { return 1.f / (1.f + __expf(-z)); }

__device__ __forceinline__ uint32_t f2bf2(float lo, float hi) {
    uint32_t r; asm("cvt.rn.bf16x2.f32 %0, %1, %2;" : "=r"(r) : "f"(hi), "f"(lo)); return r;
}
__device__ __forceinline__ void red2(float* p, float a, float b) {
    asm volatile("red.global.add.v2.f32 [%0], {%1,%2};" :: "l"(p), "f"(a), "f"(b) : "memory");
}
__device__ __forceinline__ void mma16(float* d, uint32_t a0,uint32_t a1,uint32_t a2,uint32_t a3,
                                      uint32_t b0,uint32_t b1) {
    asm volatile("mma.sync.aligned.m16n8k16.row.col.f32.bf16.bf16.f32 "
                 "{%0,%1,%2,%3},{%4,%5,%6,%7},{%8,%9},{%0,%1,%2,%3};"
                 : "+f"(d[0]),"+f"(d[1]),"+f"(d[2]),"+f"(d[3])
                 : "r"(a0),"r"(a1),"r"(a2),"r"(a3),"r"(b0),"r"(b1));
}

// ---- cp.async helpers ----
__device__ __forceinline__ void cp16(uint32_t saddr, const uint32_t* src) {
    asm volatile("cp.async.cg.shared.global [%0], [%1], 16;" :: "r"(saddr), "l"(src));
}
#define CP_COMMIT() asm volatile("cp.async.commit_group;" ::: "memory")
#define CP_WAIT0()  asm volatile("cp.async.wait_group 0;" ::: "memory")
#define CP_WAIT1()  asm volatile("cp.async.wait_group 1;" ::: "memory")

template<int N4, int NT>
__device__ __forceinline__ void cp_chunk(uint32_t* dst, const uint32_t* __restrict__ src, int t) {
    uint32_t d = (uint32_t)__cvta_generic_to_shared(dst);
    for (int i = t; i < N4; i += NT) cp16(d + i*16, src + i*4);
    CP_COMMIT();
}

__device__ __forceinline__ int bpairpos(int k2, int n, int QS) {
    return (k2>>3)*4*QS + (k2&3)*QS + 2*n + ((k2>>2)&1);
}

// Warp tile 32 rows x 32 cols, bf16 k16. Xs rows = packed k-pairs, stride XST words.
// NK = number of k16 steps.
template<int XST, int QS, int NK>
__device__ __forceinline__ void gemm_mma(const uint32_t* __restrict__ Ws,
                                         const uint32_t* __restrict__ Xs,
                                         int lane, int mg, int ng, float acc[8][4])
{
    const uint32_t* xb = Xs + (mg*32 + (lane>>2))*XST + (lane&3);
    const uint32_t* wb = Ws + (lane&3)*QS + (ng*32 + (lane>>2))*2;
#pragma unroll
    for (int kk = 0; kk < NK; kk++) {
        const uint32_t* xp = xb + kk*8;
        uint32_t a00 = xp[0],      a01 = xp[8*XST],   a02 = xp[4],        a03 = xp[8*XST+4];
        uint32_t a10 = xp[16*XST], a11 = xp[24*XST],  a12 = xp[16*XST+4], a13 = xp[24*XST+4];
        const uint32_t* wp = wb + kk*4*QS;
        uint2 b[4];
#pragma unroll
        for (int nt = 0; nt < 4; nt++) b[nt] = *(const uint2*)(wp + nt*16);
#pragma unroll
        for (int nt = 0; nt < 4; nt++) {
            mma16(acc[nt],   a00,a01,a02,a03, b[nt].x, b[nt].y);
            mma16(acc[4+nt], a10,a11,a12,a13, b[nt].x, b[nt].y);
        }
    }
}

// ---------------- weight pre-conversion (bf16 pairs) ----------------
__global__ void __launch_bounds__(256) wconv_kernel(
    const float* __restrict__ W1, const float* __restrict__ W2,
    const float* __restrict__ Wm0, const float* __restrict__ Wc1,
    const float* __restrict__ Wc2, const float* __restrict__ Wp,
    const float* __restrict__ Wf1, const float* __restrict__ Wf2,
    const float* __restrict__ Wxj, const float* __restrict__ Wg)
{
    int i = blockIdx.x*256 + threadIdx.x;
    if (i < 8192) { int k2=i>>7, n=i&127;
        g_W1c[bpairpos(k2,n,264)] = f2bf2(W1[2*k2*128+n], W1[(2*k2+1)*128+n]); return; } i -= 8192;
    if (i < 24576) { int j=i/8192, r=i&8191, k2=r>>7, n=r&127;
        g_W2c[j*8448 + bpairpos(k2,n,264)] =
            f2bf2(W2[2*k2*384 + j*128 + n], W2[(2*k2+1)*384 + j*128 + n]); return; } i -= 24576;
    if (i < 57344){ int j=i/8192, r=i&8191, k2=r>>7, n=r&127;
        g_Wm0c[j*8448 + bpairpos(k2,n,264)] =
            f2bf2(Wm0[2*k2*896 + j*128 + n], Wm0[(2*k2+1)*896 + j*128 + n]); return; } i -= 57344;
    if (i < 24576) { int d=i>>13, r=i&8191, k2=r>>7, n=r&127;
        g_Wc1c[d*8448 + bpairpos(k2,n,264)] =
            f2bf2(Wc1[d*16384 + 2*k2*128 + n], Wc1[d*16384 + (2*k2+1)*128 + n]); return; } i -= 24576;
    if (i < 24576) { int d=i>>13, r=i&8191, k2=r>>7, n=r&127;
        g_Wc2c[d*8448 + bpairpos(k2,n,264)] =
            f2bf2(Wc2[d*16384 + 2*k2*128 + n], Wc2[d*16384 + (2*k2+1)*128 + n]); return; } i -= 24576;
    if (i < 12288) { int d=i>>12, r=i&4095, k2=r>>6, n=r&63;
        g_Wpc[d*4352 + bpairpos(k2,n,136)] =
            f2bf2(Wp[d*8192 + 2*k2*64 + n], Wp[d*8192 + (2*k2+1)*64 + n]); return; } i -= 12288;
    if (i < 8192) { int d=(i>>12)+1, r=i&4095, k2=r>>7, n=r&127;
        g_Wf1c[d*4224 + bpairpos(k2,n,264)] =
            f2bf2(Wf1[d*8192 + 2*k2*128 + n], Wf1[d*8192 + (2*k2+1)*128 + n]); return; } i -= 8192;
    if (i < 12288) { int d=i>>12, r=i&4095, k2=r>>6, n=r&63;
        g_Wf2c[d*4352 + bpairpos(k2,n,136)] =
            f2bf2(Wf2[d*8192 + 2*k2*64 + n], Wf2[d*8192 + (2*k2+1)*64 + n]); return; } i -= 12288;
    if (i < 4096)  { int k2=i>>7, n=i&127;
        g_Wxjc[bpairpos(k2,n,264)] = f2bf2(Wxj[2*k2*128+n], Wxj[(2*k2+1)*128+n]); return; } i -= 4096;
    if (i < 4096)  { int k2=i>>7, n=i&127;
        g_Wgc[bpairpos(k2,n,264)] = f2bf2(Wg[2*k2*128+n], Wg[(2*k2+1)*128+n]); return; }
}
#define WCONV_N 180224

__global__ void zero_kernel() {
    size_t i = (size_t)blockIdx.x * blockDim.x + threadIdx.x;
    if (i < NN*1152/4) ((float4*)g_num)[i] = make_float4(0.f,0.f,0.f,0.f);
    if (i < NN*8)      g_den[i] = 0.f;
}

// ---------------- enorm ----------------
__global__ void __launch_bounds__(256) enorm_kernel(const float* __restrict__ src, float* __restrict__ dst) {
    int n = blockIdx.x*4 + (threadIdx.x >> 6);
    int c = threadIdx.x & 63;
    const float* p = src + (size_t)n*576 + c;
    float v[9];
#pragma unroll
    for (int k = 0; k < 9; k++) v[k] = p[k*64];
    float s0 = v[0]*v[0];
    float s1 = v[1]*v[1] + v[2]*v[2] + v[3]*v[3];
    float s2 = v[4]*v[4] + v[5]*v[5] + v[6]*v[6] + v[7]*v[7] + v[8]*v[8];
#pragma unroll
    for (int off = 16; off; off >>= 1) {
        s0 += __shfl_xor_sync(0xffffffffu, s0, off);
        s1 += __shfl_xor_sync(0xffffffffu, s1, off);
        s2 += __shfl_xor_sync(0xffffffffu, s2, off);
    }
    __shared__ float red[4][3][2];
    int g = threadIdx.x >> 6, hw = (c >> 5);
    if ((c & 31) == 0) { red[g][0][hw] = s0; red[g][1][hw] = s1; red[g][2][hw] = s2; }
    __syncthreads();
    float sc0 = rsqrtf((red[g][0][0]+red[g][0][1]) * (1.f/64.f)  + 1e-6f);
    float sc1 = rsqrtf((red[g][1][0]+red[g][1][1]) * (1.f/192.f) + 1e-6f);
    float sc2 = rsqrtf((red[g][2][0]+red[g][2][1]) * (1.f/320.f) + 1e-6f);
    float* q = dst + (size_t)n*576 + c;
    q[0] = v[0]*sc0;
#pragma unroll
    for (int k = 1; k < 4; k++) q[k*64] = v[k]*sc1;
#pragma unroll
    for (int k = 4; k < 9; k++) q[k*64] = v[k]*sc2;
}

// ---------------- xjp: 80000 rows x 128, K=64 ----------------
#define XJ_GRID 1250
__global__ void __launch_bounds__(256) xjp_mma()
{
    extern __shared__ uint32_t sm[];
    uint32_t* Xs = sm;            // 64*36 = 2304
    uint32_t* Ws = sm + 2304;     // 4224
    int rbase = blockIdx.x * 64;
    int t = threadIdx.x, lane = t & 31, w = t >> 5, mg = w & 1, ng = w >> 1;
    cp_chunk<1056,256>(Ws, g_Wxjc, t);
    {
        int r = t >> 2, q = t & 3;
        int gr = rbase + r;
        int node = gr >> 3, slot = 1 + (gr & 7);
        const float4* yp = (const float4*)&g_xn[(size_t)node*576 + slot*64 + q*16];
        uint32_t* col = Xs + r*36 + q*8;
#pragma unroll
        for (int i = 0; i < 4; i++) {
            float4 v = yp[i];
            *(uint2*)(col + i*2) = make_uint2(f2bf2(v.x, v.y), f2bf2(v.z, v.w));
        }
    }
    CP_WAIT0();
    __syncthreads();
    float acc[8][4] = {};
    gemm_mma<36,264,4>(Ws, Xs, lane, mg, ng, acc);
    int nbase = ng*32 + (lane&3)*2;
    int ebase = mg*32 + (lane>>2);
#pragma unroll
    for (int mt = 0; mt < 2; mt++)
#pragma unroll
    for (int hf = 0; hf < 2; hf++) {
        int gr = rbase + ebase + mt*16 + hf*8;
        int node = gr >> 3, slot = gr & 7;
        size_t ob = (size_t)node*1024 + (size_t)slot*128;
#pragma unroll
        for (int nt = 0; nt < 4; nt++) {
            int n = nbase + nt*8;
            *(float2*)&g_xjp[ob + n] =
                make_float2(acc[mt*4+nt][hf*2+0], acc[mt*4+nt][hf*2+1]);
        }
    }
}

// ---------------- gate: 10000 rows x 128, K=64 ----------------
#define GATE_GRID 157
__global__ void __launch_bounds__(256) gate_mma(const float* __restrict__ bg)
{
    extern __shared__ uint32_t sm[];
    uint32_t* Xs = sm;
    uint32_t* Ws = sm + 2304;
    int rbase = blockIdx.x * 64;
    int t = threadIdx.x, lane = t & 31, w = t >> 5, mg = w & 1, ng = w >> 1;
    cp_chunk<1056,256>(Ws, g_Wgc, t);
    {
        int r = t >> 2, q = t & 3;
        int node = rbase + r;
        uint32_t* col = Xs + r*36 + q*8;
        if (node < NN) {
            const float4* yp = (const float4*)&g_yn[(size_t)node*576 + q*16];
#pragma unroll
            for (int i = 0; i < 4; i++) {
                float4 v = yp[i];
                *(uint2*)(col + i*2) = make_uint2(f2bf2(v.x, v.y), f2bf2(v.z, v.w));
            }
        } else {
#pragma unroll
            for (int i = 0; i < 4; i++) *(uint2*)(col + i*2) = make_uint2(0,0);
        }
    }
    CP_WAIT0();
    __syncthreads();
    float acc[8][4] = {};
    gemm_mma<36,264,4>(Ws, Xs, lane, mg, ng, acc);
    int nbase = ng*32 + (lane&3)*2;
    int ebase = mg*32 + (lane>>2);
#pragma unroll
    for (int mt = 0; mt < 2; mt++)
#pragma unroll
    for (int hf = 0; hf < 2; hf++) {
        int node = rbase + ebase + mt*16 + hf*8;
        if (node >= NN) continue;
        size_t ob = (size_t)node*128;
#pragma unroll
        for (int nt = 0; nt < 4; nt++) {
            int n = nbase + nt*8;
            float z0 = acc[mt*4+nt][hf*2+0] + bg[n];
            float z1 = acc[mt*4+nt][hf*2+1] + bg[n+1];
            float s0 = sigm(z0), s1 = sigm(z1);
            *(float2*)&g_gsil[ob + n] = make_float2(z0*s0, z1*s1);
            *(float2*)&g_gsig[ob + n] = make_float2(s0, s1);
        }
    }
}

// ---------------- radial MLP: 128 edges/block, 16-quarter bf16 pipeline ----------------
__global__ void __launch_bounds__(512,2) rad_kernel(
    const float* __restrict__ edist, const float* __restrict__ semb,
    const float* __restrict__ temb,  const float* __restrict__ b1,
    const float* __restrict__ b2,    const int* __restrict__ anum,
    const int* __restrict__ eidx)
{
    extern __shared__ uint32_t sm[];
    uint32_t* ef = sm;            // 128*68 = 8704
    uint32_t* Ws = sm + 8704;     // 4224 (2 x 2112)
    int* zsrc = (int*)(sm + 12928);
    int* ztgt = zsrc + 128;
    int e0 = blockIdx.x * 128, t = threadIdx.x;
    int lane = t & 31, w = t >> 5, mg = w & 3, ng = w >> 2;
    auto qsrc = [](int m) { return m < 4 ? g_W1c + m*2112 : g_W2c + (m-4)*2112; };
    cp_chunk<528,512>(Ws,        qsrc(0), t);
    cp_chunk<528,512>(Ws + 2112, qsrc(1), t);
    if (t < 128)      zsrc[t]     = anum[eidx[e0 + t]];
    else if (t < 256) ztgt[t-128] = anum[eidx[NE + e0 + t - 128]];
    __syncthreads();
    {
        int e = t >> 2, q = t & 3;
        const float4* xp;
        if (q < 2)      xp = (const float4*)&edist[(size_t)(e0+e)*64 + q*32];
        else if (q==2)  xp = (const float4*)&semb[(size_t)zsrc[e]*32];
        else            xp = (const float4*)&temb[(size_t)ztgt[e]*32];
        uint32_t* col = ef + e*68 + q*16;
#pragma unroll
        for (int i4 = 0; i4 < 8; i4++) {
            float4 v = xp[i4];
            *(uint2*)(col + i4*2) = make_uint2(f2bf2(v.x, v.y), f2bf2(v.z, v.w));
        }
    }
    int nbase = ng*32 + (lane&3)*2;
    int ebase = mg*32 + (lane>>2);
    int m = 0;
    {
        float acc[8][4] = {};
        for (int q = 0; q < 4; q++, m++) {
            if (m + 1 < 16) CP_WAIT1(); else CP_WAIT0();
            __syncthreads();
            gemm_mma<68,264,2>(Ws + (m&1)*2112, ef + q*16, lane, mg, ng, acc);
            __syncthreads();
            if (m + 2 < 16) cp_chunk<528,512>(Ws + (m&1)*2112, qsrc(m+2), t);
        }
#pragma unroll
        for (int nt = 0; nt < 4; nt++) {
            int n = nbase + nt*8;
            float2 bb = *(const float2*)&b1[n];
#pragma unroll
            for (int mt = 0; mt < 2; mt++)
#pragma unroll
            for (int hf = 0; hf < 2; hf++) {
                int el = ebase + mt*16 + hf*8;
                float z0 = acc[mt*4+nt][hf*2+0] + bb.x;
                float z1 = acc[mt*4+nt][hf*2+1] + bb.y;
                ef[el*68 + (n>>1)] = f2bf2(z0*sigm(z0), z1*sigm(z1));
            }
        }
    }
    for (int j = 0; j < 3; j++) {
        float acc[8][4] = {};
        for (int q = 0; q < 4; q++, m++) {
            if (m + 1 < 16) CP_WAIT1(); else CP_WAIT0();
            __syncthreads();
            gemm_mma<68,264,2>(Ws + (m&1)*2112, ef + q*16, lane, mg, ng, acc);
            __syncthreads();
            if (m + 2 < 16) cp_chunk<528,512>(Ws + (m&1)*2112, qsrc(m+2), t);
        }
#pragma unroll
        for (int nt = 0; nt < 4; nt++) {
            int n = nbase + nt*8;
            float2 bb = *(const float2*)&b2[j*128 + n];
#pragma unroll
            for (int mt = 0; mt < 2; mt++)
#pragma unroll
            for (int hf = 0; hf < 2; hf++) {
                int el = ebase + mt*16 + hf*8;
                *(float2*)&g_rad[(size_t)(e0+el)*384 + j*128 + n] =
                    make_float2(acc[mt*4+nt][hf*2+0] + bb.x, acc[mt*4+nt][hf*2+1] + bb.y);
            }
        }
    }
}

// ---------------- extra: 28-quarter bf16 pipeline ----------------
__global__ void __launch_bounds__(512,2) extra_kernel(
    const float* __restrict__ lng, const float* __restrict__ lnb,
    const float* __restrict__ adot, const int* __restrict__ eidx)
{
    extern __shared__ uint32_t sm[];
    uint32_t* Xs = sm;            // 8704
    uint32_t* Ws = sm + 8704;     // 4224
    int* src_s = (int*)(sm + 12928);
    int* tgt_s = src_s + 128;
    int e0 = blockIdx.x * 128, t = threadIdx.x;
    int lane = t & 31, w = t >> 5, mg = w & 3, ng = w >> 2;
    cp_chunk<528,512>(Ws,        g_Wm0c,        t);
    cp_chunk<528,512>(Ws + 2112, g_Wm0c + 2112, t);
    if (t < 128)      src_s[t]     = eidx[e0 + t];
    else if (t < 256) tgt_s[t-128] = eidx[NE + e0 + t - 128];
    __syncthreads();
    {
        int e = t >> 2, q = t & 3;
        const float4* rp = (const float4*)&g_rad[(size_t)(e0+e)*384 + q*32];
        const float4* xp = (q < 2)
            ? (const float4*)&g_xn[(size_t)src_s[e]*576 + q*32]
            : (const float4*)&g_xn[(size_t)tgt_s[e]*576 + (q-2)*32];
        uint32_t* col = Xs + e*68 + q*16;
#pragma unroll
        for (int i4 = 0; i4 < 8; i4++) {
            float4 xv = xp[i4], rv = rp[i4];
            *(uint2*)(col + i4*2) =
                make_uint2(f2bf2(xv.x*rv.x, xv.y*rv.y), f2bf2(xv.z*rv.z, xv.w*rv.w));
        }
    }
    int nbase = ng*32 + (lane&3)*2;
    int ebase = mg*32 + (lane>>2);
    int m = 0;
    for (int oc = 0; oc < 7; oc++) {
        float acc[8][4] = {};
        for (int q = 0; q < 4; q++, m++) {
            if (m + 1 < 28) CP_WAIT1(); else CP_WAIT0();
            __syncthreads();
            gemm_mma<68,264,2>(Ws + (m&1)*2112, Xs + q*16, lane, mg, ng, acc);
            __syncthreads();
            if (m + 2 < 28) cp_chunk<528,512>(Ws + (m&1)*2112, g_Wm0c + (m+2)*2112, t);
        }
        if (oc < 2) {
            int h = oc*4 + ng;
#pragma unroll
            for (int mt = 0; mt < 2; mt++)
#pragma unroll
            for (int hf = 0; hf < 2; hf++) {
                int el = ebase + mt*16 + hf*8;
                float sum = 0.f, ssq = 0.f;
#pragma unroll
                for (int nt = 0; nt < 4; nt++) {
                    float v0 = acc[mt*4+nt][hf*2+0], v1 = acc[mt*4+nt][hf*2+1];
                    sum += v0 + v1; ssq += v0*v0 + v1*v1;
                }
                sum += __shfl_xor_sync(0xffffffffu, sum, 1);
                sum += __shfl_xor_sync(0xffffffffu, sum, 2);
                ssq += __shfl_xor_sync(0xffffffffu, ssq, 1);
                ssq += __shfl_xor_sync(0xffffffffu, ssq, 2);
                float mean = sum * (1.f/32.f);
                float rs = rsqrtf(ssq * (1.f/32.f) - mean*mean + 1e-5f);
                float logit = 0.f;
#pragma unroll
                for (int nt = 0; nt < 4; nt++) {
                    int a = nt*8 + (lane&3)*2;
#pragma unroll
                    for (int jj = 0; jj < 2; jj++) {
                        float v = acc[mt*4+nt][hf*2+jj];
                        float an = (v - mean)*rs*lng[a+jj] + lnb[a+jj];
                        logit += (0.2f*an + 0.8f*an*sigm(an)) * adot[h*32 + a + jj];
                    }
                }
                logit += __shfl_xor_sync(0xffffffffu, logit, 1);
                logit += __shfl_xor_sync(0xffffffffu, logit, 2);
                if ((lane & 3) == 0) {
                    float ex = __expf(logit);
                    g_e[(size_t)(e0+el)*8 + h] = ex;
                    atomicAdd(&g_den[(size_t)tgt_s[el]*8 + h], ex);
                }
            }
        } else if (oc == 2) {
#pragma unroll
            for (int nt = 0; nt < 4; nt++) {
                int n = nbase + nt*8;
#pragma unroll
                for (int mt = 0; mt < 2; mt++)
#pragma unroll
                for (int hf = 0; hf < 2; hf++) {
                    int el = ebase + mt*16 + hf*8;
                    float z0 = acc[mt*4+nt][hf*2+0], z1 = acc[mt*4+nt][hf*2+1];
                    *(float2*)&g_val0[(size_t)(e0+el)*128 + n] =
                        make_float2(z0*sigm(z0), z1*sigm(z1));
                }
            }
        } else {
            int which = oc - 3;
            float* base = (which < 2) ? g_gdir : g_gten;
            int l = which & 1;
#pragma unroll
            for (int nt = 0; nt < 4; nt++) {
                int n = nbase + nt*8;
#pragma unroll
                for (int mt = 0; mt < 2; mt++)
#pragma unroll
                for (int hf = 0; hf < 2; hf++) {
                    int el = ebase + mt*16 + hf*8;
                    *(float2*)&base[(size_t)(e0+el)*256 + l*128 + n] =
                        make_float2(sigm(acc[mt*4+nt][hf*2+0]), sigm(acc[mt*4+nt][hf*2+1]));
                }
            }
        }
    }
}

// ---------------- fused conv1+conv2: resident bf16 weights, 2 blocks/SM ----------------
__global__ void __launch_bounds__(512,2) conv_kernel(
    const float* __restrict__ rl, const int* __restrict__ eidx)
{
    extern __shared__ uint32_t sm[];
    uint32_t* XV  = sm;            // 8704
    uint32_t* W1s = sm + 8704;     // 8448
    uint32_t* W2s = sm + 17152;    // 8448
    float* rl_s = (float*)(sm + 25600);   // 1024
    float* ee_s = (float*)(sm + 26624);   // 1024
    int* src_s = (int*)(sm + 27648);      // 128
    int* tgt_s = (int*)(sm + 27776);      // 128
    int e0 = blockIdx.x * 128, t = threadIdx.x;
    int lane = t & 31, w = t >> 5, mg = w & 3, ng = w >> 2;
    if (t < 128)      src_s[t]     = eidx[e0 + t];
    else if (t < 256) tgt_s[t-128] = eidx[NE + e0 + t - 128];
    for (int i = t; i < 1024; i += 512) {
        rl_s[i] = rl[(size_t)e0*8 + i];
        ee_s[i] = g_e[(size_t)e0*8 + i];
    }
    int nbase = ng*32 + (lane&3)*2;
    int ebase = mg*32 + (lane>>2);
    int se = t >> 2, sq = t & 3;

    for (int deg = 0; deg <= 2; deg++) {
        __syncthreads();
        cp_chunk<2112,512>(W2s, g_Wc2c + deg*8448, t);
        if (deg) cp_chunk<2112,512>(W1s, g_Wc1c + deg*8448, t);
        int kbeg = (deg == 0) ? 0 : ((deg == 1) ? 1 : 4);
        int kend = (deg == 0) ? 1 : ((deg == 1) ? 4 : 9);
        for (int k = kbeg; k < kend; k++) {
            if (deg == 0) {
                const float4* vp = (const float4*)&g_val0[(size_t)(e0+se)*128 + sq*32];
                uint32_t* col = XV + se*68 + sq*16;
#pragma unroll
                for (int i4 = 0; i4 < 8; i4++) {
                    float4 v = vp[i4];
                    *(uint2*)(col + i4*2) = make_uint2(f2bf2(v.x, v.y), f2bf2(v.z, v.w));
                }
            } else {
                const float4* rp = (const float4*)&g_rad[(size_t)(e0+se)*384 + deg*128 + sq*32];
                const float4* xp = (sq < 2)
                    ? (const float4*)&g_xn[(size_t)src_s[se]*576 + k*64 + sq*32]
                    : (const float4*)&g_xn[(size_t)tgt_s[se]*576 + k*64 + (sq-2)*32];
                uint32_t* col = XV + se*68 + sq*16;
#pragma unroll
                for (int i4 = 0; i4 < 8; i4++) {
                    float4 xv = xp[i4], rv = rp[i4];
                    *(uint2*)(col + i4*2) =
                        make_uint2(f2bf2(xv.x*rv.x, xv.y*rv.y), f2bf2(xv.z*rv.z, xv.w*rv.w));
                }
            }
            if (k == kbeg) CP_WAIT0();
            __syncthreads();
            if (deg) {
                float acc[8][4] = {};
                gemm_mma<68,264,8>(W1s, XV, lane, mg, ng, acc);
                int l = (k < 4) ? 0 : 1;
#pragma unroll
                for (int mt = 0; mt < 2; mt++)
#pragma unroll
                for (int hf = 0; hf < 2; hf++) {
                    int el = ebase + mt*16 + hf*8;
                    size_t ge = (size_t)(e0 + el);
                    float r = rl_s[el*8 + (k-1)];
                    size_t gb = ge*256 + l*128;
                    size_t xb = (size_t)src_s[el]*1024 + (size_t)(k-1)*128;
#pragma unroll
                    for (int nt = 0; nt < 4; nt++) {
                        int n = nbase + nt*8;
                        float2 gd = *(const float2*)&g_gdir[gb + n];
                        float2 gt = *(const float2*)&g_gten[gb + n];
                        float2 xj = *(const float2*)&g_xjp[xb + n];
                        acc[mt*4+nt][hf*2+0] += r*gd.x + xj.x*gt.x;
                        acc[mt*4+nt][hf*2+1] += r*gd.y + xj.y*gt.y;
                    }
                }
                __syncthreads();   // conv1 reads of XV done
#pragma unroll
                for (int mt = 0; mt < 2; mt++)
#pragma unroll
                for (int hf = 0; hf < 2; hf++) {
                    int el = ebase + mt*16 + hf*8;
#pragma unroll
                    for (int nt = 0; nt < 4; nt++) {
                        int n = nbase + nt*8;
                        XV[el*68 + (n>>1)] =
                            f2bf2(acc[mt*4+nt][hf*2+0], acc[mt*4+nt][hf*2+1]);
                    }
                }
                __syncthreads();
            }
            float acc[8][4] = {};
            gemm_mma<68,264,8>(W2s, XV, lane, mg, ng, acc);
#pragma unroll
            for (int mt = 0; mt < 2; mt++)
#pragma unroll
            for (int hf = 0; hf < 2; hf++) {
                int el = ebase + mt*16 + hf*8;
                size_t nb = (size_t)tgt_s[el]*1152 + (size_t)k*128;
#pragma unroll
                for (int nt = 0; nt < 4; nt++) {
                    int n = nbase + nt*8;
                    float s = ee_s[el*8 + (n >> 4)];
                    red2(&g_num[nb + n], acc[mt*4+nt][hf*2+0]*s, acc[mt*4+nt][hf*2+1]*s);
                }
            }
            __syncthreads();
        }
    }
}

// ---------------- node GEMMs ----------------
#define P_T0 79
#define P_T1 314
#define P_GRID 705
__device__ __forceinline__ void node_row(int b, int* deg, int* rbase,
                                         int* nslots, int* soff, int* nrows)
{
    if (b < P_T0)      { *deg=0; *rbase=b*128;          *nslots=1; *soff=0; *nrows=10000; }
    else if (b < P_T1) { *deg=1; *rbase=(b-P_T0)*128;   *nslots=3; *soff=1; *nrows=30000; }
    else               { *deg=2; *rbase=(b-P_T1)*128;   *nslots=5; *soff=4; *nrows=50000; }
}

__global__ void __launch_bounds__(256,2) proj_mma(
    const float* __restrict__ x, const float* __restrict__ bp)
{
    extern __shared__ uint32_t sm[];
    uint32_t* Xs = sm;            // 8704
    uint32_t* Ws = sm + 8704;     // 4352
    int deg, rbase, nslots, soff, nrows;
    node_row(blockIdx.x, &deg, &rbase, &nslots, &soff, &nrows);
    int t = threadIdx.x, lane = t & 31, w = t >> 5, mg = w & 3, ng = w >> 2;
    cp_chunk<1088,256>(Ws, g_Wpc + deg*4352, t);
    {
        int r = t >> 1, h2 = t & 1;
        int gr = rbase + r;
        uint32_t* col = Xs + r*68 + h2*32;
        if (gr < nrows) {
            int node = gr / nslots, slot = soff + gr % nslots;
            const float4* np = (const float4*)&g_num[(size_t)node*1152 + slot*128 + h2*64];
            float di[4];
#pragma unroll
            for (int q = 0; q < 4; q++) di[q] = 1.f / (g_den[node*8 + h2*4 + q] + 1e-30f);
#pragma unroll
            for (int i = 0; i < 16; i++) {
                float4 v = np[i]; float d = di[i>>2];
                *(uint2*)(col + i*2) = make_uint2(f2bf2(v.x*d, v.y*d), f2bf2(v.z*d, v.w*d));
            }
        } else {
#pragma unroll
            for (int i = 0; i < 16; i++) *(uint2*)(col + i*2) = make_uint2(0,0);
        }
    }
    CP_WAIT0();
    __syncthreads();
    float acc[8][4] = {};
    gemm_mma<68,136,8>(Ws, Xs, lane, mg, ng, acc);
    int nbase = ng*32 + (lane&3)*2;
    int ebase = mg*32 + (lane>>2);
#pragma unroll
    for (int mt = 0; mt < 2; mt++)
#pragma unroll
    for (int hf = 0; hf < 2; hf++) {
        int gr = rbase + ebase + mt*16 + hf*8;
        if (gr >= nrows) continue;
        int node = gr / nslots, slot = soff + gr % nslots;
        size_t ob = (size_t)node*576 + slot*64;
#pragma unroll
        for (int nt = 0; nt < 4; nt++) {
            int n = nbase + nt*8;
            float b0 = (slot == 0) ? bp[n] : 0.f, b1 = (slot == 0) ? bp[n+1] : 0.f;
            *(float2*)&g_x1[ob + n] = make_float2(
                x[ob + n]   + acc[mt*4+nt][hf*2+0] + b0,
                x[ob + n+1] + acc[mt*4+nt][hf*2+1] + b1);
        }
    }
}

__global__ void __launch_bounds__(256,2) ffn2_mma(
    const float* __restrict__ bf2, float* __restrict__ out)
{
    extern __shared__ uint32_t sm[];
    uint32_t* Xs = sm;
    uint32_t* Ws = sm + 8704;
    int deg, rbase, nslots, soff, nrows;
    node_row(blockIdx.x, &deg, &rbase, &nslots, &soff, &nrows);
    int t = threadIdx.x, lane = t & 31, w = t >> 5, mg = w & 3, ng = w >> 2;
    cp_chunk<1088,256>(Ws, g_Wf2c + deg*4352, t);
    {
        int r = t >> 1, h2 = t & 1;
        int gr = rbase + r;
        uint32_t* col = Xs + r*68 + h2*32;
        if (gr < nrows) {
            int node = gr / nslots, slot = soff + gr % nslots;
            const float4* hp = (slot == 0)
                ? (const float4*)&g_gsil[(size_t)node*128 + h2*64]
                : (const float4*)&g_h[(size_t)node*1024 + (size_t)(slot-1)*128 + h2*64];
#pragma unroll
            for (int i = 0; i < 16; i++) {
                float4 v = hp[i];
                *(uint2*)(col + i*2) = make_uint2(f2bf2(v.x, v.y), f2bf2(v.z, v.w));
            }
        } else {
#pragma unroll
            for (int i = 0; i < 16; i++) *(uint2*)(col + i*2) = make_uint2(0,0);
        }
    }
    CP_WAIT0();
    __syncthreads();
    float acc[8][4] = {};
    gemm_mma<68,136,8>(Ws, Xs, lane, mg, ng, acc);
    int nbase = ng*32 + (lane&3)*2;
    int ebase = mg*32 + (lane>>2);
#pragma unroll
    for (int mt = 0; mt < 2; mt++)
#pragma unroll
    for (int hf = 0; hf < 2; hf++) {
        int gr = rbase + ebase + mt*16 + hf*8;
        if (gr >= nrows) continue;
        int node = gr / nslots, slot = soff + gr % nslots;
        size_t ob = (size_t)node*576 + slot*64;
#pragma unroll
        for (int nt = 0; nt < 4; nt++) {
            int n = nbase + nt*8;
            float b0 = (slot == 0) ? bf2[n] : 0.f, b1 = (slot == 0) ? bf2[n+1] : 0.f;
            *(float2*)&out[ob + n] = make_float2(
                g_x1[ob + n]   + acc[mt*4+nt][hf*2+0] + b0,
                g_x1[ob + n+1] + acc[mt*4+nt][hf*2+1] + b1);
        }
    }
}

#define F_T1 469
#define F_GRID 1251
__global__ void __launch_bounds__(256) ffn1_mma()
{
    extern __shared__ uint32_t sm[];
    uint32_t* Xs = sm;            // 2304
    uint32_t* Ws = sm + 2304;     // 4224
    int b = blockIdx.x, deg, rbase, nslots, soff, nrows;
    if (b < F_T1) { deg=1; rbase=b*64;         nslots=3; soff=1; nrows=30000; }
    else          { deg=2; rbase=(b-F_T1)*64;  nslots=5; soff=4; nrows=50000; }
    int t = threadIdx.x, lane = t & 31, w = t >> 5, mg = w & 1, ng = w >> 1;
    cp_chunk<1056,256>(Ws, g_Wf1c + deg*4224, t);
    {
        int r = t >> 2, q = t & 3;
        int gr = rbase + r;
        uint32_t* col = Xs + r*36 + q*8;
        if (gr < nrows) {
            int node = gr / nslots, slot = soff + gr % nslots;
            const float4* yp = (const float4*)&g_yn[(size_t)node*576 + slot*64 + q*16];
#pragma unroll
            for (int i = 0; i < 4; i++) {
                float4 v = yp[i];
                *(uint2*)(col + i*2) = make_uint2(f2bf2(v.x, v.y), f2bf2(v.z, v.w));
            }
        } else {
#pragma unroll
            for (int i = 0; i < 4; i++) *(uint2*)(col + i*2) = make_uint2(0,0);
        }
    }
    CP_WAIT0();
    __syncthreads();
    float acc[8][4] = {};
    gemm_mma<36,264,4>(Ws, Xs, lane, mg, ng, acc);
    int nbase = ng*32 + (lane&3)*2;
    int ebase = mg*32 + (lane>>2);
#pragma unroll
    for (int mt = 0; mt < 2; mt++)
#pragma unroll
    for (int hf = 0; hf < 2; hf++) {
        int gr = rbase + ebase + mt*16 + hf*8;
        if (gr >= nrows) continue;
        int node = gr / nslots, slot = soff + gr % nslots;
        size_t hb = (size_t)node*1024 + (size_t)(slot-1)*128;
        size_t gsb = (size_t)node*128;
#pragma unroll
        for (int nt = 0; nt < 4; nt++) {
            int n = nbase + nt*8;
            float2 gs = *(const float2*)&g_gsig[gsb + n];
            *(float2*)&g_h[hb + n] = make_float2(
                acc[mt*4+nt][hf*2+0]*gs.x, acc[mt*4+nt][hf*2+1]*gs.y);
        }
    }
}

// ---------------- launch ----------------
extern "C" void kernel_launch(void* const* d_in, const int* in_sizes, int n_in,
                              void* d_out, int out_size)
{
    const float* x     = (const float*)d_in[0];
    const float* edist = (const float*)d_in[1];
    const float* rl    = (const float*)d_in[2];
    const float* semb  = (const float*)d_in[3];
    const float* temb  = (const float*)d_in[4];
    const float* W1    = (const float*)d_in[5];
    const float* b1    = (const float*)d_in[6];
    const float* W2    = (const float*)d_in[7];
    const float* b2    = (const float*)d_in[8];
    const float* Wc1   = (const float*)d_in[9];
    const float* Wm0   = (const float*)d_in[10];
    const float* lng   = (const float*)d_in[11];
    const float* lnb   = (const float*)d_in[12];
    const float* adot  = (const float*)d_in[13];
    const float* Wxj   = (const float*)d_in[14];
    const float* Wc2   = (const float*)d_in[15];
    const float* Wp    = (const float*)d_in[16];
    const float* bp    = (const float*)d_in[17];
    const float* Wg    = (const float*)d_in[18];
    const float* bg    = (const float*)d_in[19];
    const float* Wf1   = (const float*)d_in[20];
    const float* Wf2   = (const float*)d_in[22];
    const float* bf2   = (const float*)d_in[23];
    const int*   anum  = (const int*)d_in[24];
    const int*   eidx  = (const int*)d_in[25];
    float* out = (float*)d_out;

    float *p_xn, *p_x1, *p_yn;
    cudaGetSymbolAddress((void**)&p_xn, g_xn);
    cudaGetSymbolAddress((void**)&p_x1, g_x1);
    cudaGetSymbolAddress((void**)&p_yn, g_yn);

    static bool attr_set = false;
    if (!attr_set) {
        cudaFuncSetAttribute(rad_kernel,   cudaFuncAttributeMaxDynamicSharedMemorySize, 52736);
        cudaFuncSetAttribute(extra_kernel, cudaFuncAttributeMaxDynamicSharedMemorySize, 52736);
        cudaFuncSetAttribute(conv_kernel,  cudaFuncAttributeMaxDynamicSharedMemorySize, 111616);
        cudaFuncSetAttribute(proj_mma,     cudaFuncAttributeMaxDynamicSharedMemorySize, 52224);
        cudaFuncSetAttribute(ffn2_mma,     cudaFuncAttributeMaxDynamicSharedMemorySize, 52224);
        cudaFuncSetAttribute(ffn1_mma,     cudaFuncAttributeMaxDynamicSharedMemorySize, 26112);
        cudaFuncSetAttribute(xjp_mma,      cudaFuncAttributeMaxDynamicSharedMemorySize, 26112);
        cudaFuncSetAttribute(gate_mma,     cudaFuncAttributeMaxDynamicSharedMemorySize, 26112);
        attr_set = true;
    }

    wconv_kernel<<<(WCONV_N + 255)/256, 256>>>(W1, W2, Wm0, Wc1, Wc2, Wp, Wf1, Wf2, Wxj, Wg);
    zero_kernel<<<(NN*1152/4 + 255)/256, 256>>>();
    enorm_kernel<<<NN/4, 256>>>(x, p_xn);
    xjp_mma<<<XJ_GRID, 256, 26112>>>();
    rad_kernel<<<NE/128, 512, 52736>>>(edist, semb, temb, b1, b2, anum, eidx);
    extra_kernel<<<NE/128, 512, 52736>>>(lng, lnb, adot, eidx);
    conv_kernel<<<NE/128, 512, 111616>>>(rl, eidx);
    proj_mma<<<P_GRID, 256, 52224>>>(x, bp);
    enorm_kernel<<<NN/4, 256>>>(p_x1, p_yn);
    gate_mma<<<GATE_GRID, 256, 26112>>>(bg);
    ffn1_mma<<<F_GRID, 256, 26112>>>();
    ffn2_mma<<<P_GRID, 256, 52224>>>(bf2, out);
}

// round 14
// speedup vs baseline: 1.2722x; 1.0102x over previous
#include <cuda_runtime.h>
#include <cstdint>

#define NN 10000
#define NE 80000

__device__ float g_xn  [NN*576];
__device__ float g_rad [NE*384];
__device__ float g_val0[NE*128];
__device__ float g_gdir[NE*256];
__device__ float g_gten[NE*256];
__device__ float g_e   [NE*8];
__device__ float g_xjp [NN*1024];
__device__ float g_num [NN*1152];
__device__ float g_den [NN*8];
__device__ float g_x1  [NN*576];
__device__ float g_yn  [NN*576];
__device__ float g_h   [NN*1024];
__device__ float g_gsil[NN*128];
__device__ float g_gsig[NN*128];

// bf16-pair weights, fragment-interleaved SMEM-image layout
__device__ __align__(16) uint32_t g_W1c [8448];
__device__ __align__(16) uint32_t g_W2c [25344];
__device__ __align__(16) uint32_t g_Wm0c[59136];
__device__ __align__(16) uint32_t g_Wc1c[25344];
__device__ __align__(16) uint32_t g_Wc2c[25344];
__device__ __align__(16) uint32_t g_Wpc [13056];
__device__ __align__(16) uint32_t g_Wf1c[12672];
__device__ __align__(16) uint32_t g_Wf2c[13056];
__device__ __align__(16) uint32_t g_Wxjc[4224];
__device__ __align__(16) uint32_t g_Wgc [4224];

__device__ __forceinline__ float sigm(float z) { return 1.f / (1.f + __expf(-z)); }

__device__ __forceinline__ uint32_t f2bf2(float lo, float hi) {
    uint32_t r; asm("cvt.rn.bf16x2.f32 %0, %1, %2;" : "=r"(r) : "f"(hi), "f"(lo)); return r;
}
__device__ __forceinline__ void red2(float* p, float a, float b) {
    asm volatile("red.global.add.v2.f32 [%0], {%1,%2};" :: "l"(p), "f"(a), "f"(b) : "memory");
}
__device__ __forceinline__ void mma16(float* d, uint32_t a0,uint32_t a1,uint32_t a2,uint32_t a3,
                                      uint32_t b0,uint32_t b1) {
    asm volatile("mma.sync.aligned.m16n8k16.row.col.f32.bf16.bf16.f32 "
                 "{%0,%1,%2,%3},{%4,%5,%6,%7},{%8,%9},{%0,%1,%2,%3};"
                 : "+f"(d[0]),"+f"(d[1]),"+f"(d[2]),"+f"(d[3])
                 : "r"(a0),"r"(a1),"r"(a2),"r"(a3),"r"(b0),"r"(b1));
}

// ---- cp.async helpers ----
__device__ __forceinline__ void cp16(uint32_t saddr, const uint32_t* src) {
    asm volatile("cp.async.cg.shared.global [%0], [%1], 16;" :: "r"(saddr), "l"(src));
}
#define CP_COMMIT() asm volatile("cp.async.commit_group;" ::: "memory")
#define CP_WAIT0()  asm volatile("cp.async.wait_group 0;" ::: "memory")
#define CP_WAIT1()  asm volatile("cp.async.wait_group 1;" ::: "memory")

template<int N4, int NT>
__device__ __forceinline__ void cp_chunk(uint32_t* dst, const uint32_t* __restrict__ src, int t) {
    uint32_t d = (uint32_t)__cvta_generic_to_shared(dst);
    for (int i = t; i < N4; i += NT) cp16(d + i*16, src + i*4);
    CP_COMMIT();
}

__device__ __forceinline__ int bpairpos(int k2, int n, int QS) {
    return (k2>>3)*4*QS + (k2&3)*QS + 2*n + ((k2>>2)&1);
}

// Warp tile 32 rows x 32 cols, bf16 k16.
template<int XST, int QS, int NK>
__device__ __forceinline__ void gemm_mma(const uint32_t* __restrict__ Ws,
                                         const uint32_t* __restrict__ Xs,
                                         int lane, int mg, int ng, float acc[8][4])
{
    const uint32_t* xb = Xs + (mg*32 + (lane>>2))*XST + (lane&3);
    const uint32_t* wb = Ws + (lane&3)*QS + (ng*32 + (lane>>2))*2;
#pragma unroll
    for (int kk = 0; kk < NK; kk++) {
        const uint32_t* xp = xb + kk*8;
        uint32_t a00 = xp[0],      a01 = xp[8*XST],   a02 = xp[4],        a03 = xp[8*XST+4];
        uint32_t a10 = xp[16*XST], a11 = xp[24*XST],  a12 = xp[16*XST+4], a13 = xp[24*XST+4];
        const uint32_t* wp = wb + kk*4*QS;
        uint2 b[4];
#pragma unroll
        for (int nt = 0; nt < 4; nt++) b[nt] = *(const uint2*)(wp + nt*16);
#pragma unroll
        for (int nt = 0; nt < 4; nt++) {
            mma16(acc[nt],   a00,a01,a02,a03, b[nt].x, b[nt].y);
            mma16(acc[4+nt], a10,a11,a12,a13, b[nt].x, b[nt].y);
        }
    }
}

// ---------------- weight pre-conversion ----------------
__global__ void __launch_bounds__(256) wconv_kernel(
    const float* __restrict__ W1, const float* __restrict__ W2,
    const float* __restrict__ Wm0, const float* __restrict__ Wc1,
    const float* __restrict__ Wc2, const float* __restrict__ Wp,
    const float* __restrict__ Wf1, const float* __restrict__ Wf2,
    const float* __restrict__ Wxj, const float* __restrict__ Wg)
{
    int i = blockIdx.x*256 + threadIdx.x;
    if (i < 8192) { int k2=i>>7, n=i&127;
        g_W1c[bpairpos(k2,n,264)] = f2bf2(W1[2*k2*128+n], W1[(2*k2+1)*128+n]); return; } i -= 8192;
    if (i < 24576) { int j=i/8192, r=i&8191, k2=r>>7, n=r&127;
        g_W2c[j*8448 + bpairpos(k2,n,264)] =
            f2bf2(W2[2*k2*384 + j*128 + n], W2[(2*k2+1)*384 + j*128 + n]); return; } i -= 24576;
    if (i < 57344){ int j=i/8192, r=i&8191, k2=r>>7, n=r&127;
        g_Wm0c[j*8448 + bpairpos(k2,n,264)] =
            f2bf2(Wm0[2*k2*896 + j*128 + n], Wm0[(2*k2+1)*896 + j*128 + n]); return; } i -= 57344;
    if (i < 24576) { int d=i>>13, r=i&8191, k2=r>>7, n=r&127;
        g_Wc1c[d*8448 + bpairpos(k2,n,264)] =
            f2bf2(Wc1[d*16384 + 2*k2*128 + n], Wc1[d*16384 + (2*k2+1)*128 + n]); return; } i -= 24576;
    if (i < 24576) { int d=i>>13, r=i&8191, k2=r>>7, n=r&127;
        g_Wc2c[d*8448 + bpairpos(k2,n,264)] =
            f2bf2(Wc2[d*16384 + 2*k2*128 + n], Wc2[d*16384 + (2*k2+1)*128 + n]); return; } i -= 24576;
    if (i < 12288) { int d=i>>12, r=i&4095, k2=r>>6, n=r&63;
        g_Wpc[d*4352 + bpairpos(k2,n,136)] =
            f2bf2(Wp[d*8192 + 2*k2*64 + n], Wp[d*8192 + (2*k2+1)*64 + n]); return; } i -= 12288;
    if (i < 8192) { int d=(i>>12)+1, r=i&4095, k2=r>>7, n=r&127;
        g_Wf1c[d*4224 + bpairpos(k2,n,264)] =
            f2bf2(Wf1[d*8192 + 2*k2*128 + n], Wf1[d*8192 + (2*k2+1)*128 + n]); return; } i -= 8192;
    if (i < 12288) { int d=i>>12, r=i&4095, k2=r>>6, n=r&63;
        g_Wf2c[d*4352 + bpairpos(k2,n,136)] =
            f2bf2(Wf2[d*8192 + 2*k2*64 + n], Wf2[d*8192 + (2*k2+1)*64 + n]); return; } i -= 12288;
    if (i < 4096)  { int k2=i>>7, n=i&127;
        g_Wxjc[bpairpos(k2,n,264)] = f2bf2(Wxj[2*k2*128+n], Wxj[(2*k2+1)*128+n]); return; } i -= 4096;
    if (i < 4096)  { int k2=i>>7, n=i&127;
        g_Wgc[bpairpos(k2,n,264)] = f2bf2(Wg[2*k2*128+n], Wg[(2*k2+1)*128+n]); return; }
}
#define WCONV_N 180224

__global__ void zero_kernel() {
    size_t i = (size_t)blockIdx.x * blockDim.x + threadIdx.x;
    if (i < NN*1152/4) ((float4*)g_num)[i] = make_float4(0.f,0.f,0.f,0.f);
    if (i < NN*8)      g_den[i] = 0.f;
}

// ---------------- enorm ----------------
__global__ void __launch_bounds__(256) enorm_kernel(const float* __restrict__ src, float* __restrict__ dst) {
    int n = blockIdx.x*4 + (threadIdx.x >> 6);
    int c = threadIdx.x & 63;
    const float* p = src + (size_t)n*576 + c;
    float v[9];
#pragma unroll
    for (int k = 0; k < 9; k++) v[k] = p[k*64];
    float s0 = v[0]*v[0];
    float s1 = v[1]*v[1] + v[2]*v[2] + v[3]*v[3];
    float s2 = v[4]*v[4] + v[5]*v[5] + v[6]*v[6] + v[7]*v[7] + v[8]*v[8];
#pragma unroll
    for (int off = 16; off; off >>= 1) {
        s0 += __shfl_xor_sync(0xffffffffu, s0, off);
        s1 += __shfl_xor_sync(0xffffffffu, s1, off);
        s2 += __shfl_xor_sync(0xffffffffu, s2, off);
    }
    __shared__ float red[4][3][2];
    int g = threadIdx.x >> 6, hw = (c >> 5);
    if ((c & 31) == 0) { red[g][0][hw] = s0; red[g][1][hw] = s1; red[g][2][hw] = s2; }
    __syncthreads();
    float sc0 = rsqrtf((red[g][0][0]+red[g][0][1]) * (1.f/64.f)  + 1e-6f);
    float sc1 = rsqrtf((red[g][1][0]+red[g][1][1]) * (1.f/192.f) + 1e-6f);
    float sc2 = rsqrtf((red[g][2][0]+red[g][2][1]) * (1.f/320.f) + 1e-6f);
    float* q = dst + (size_t)n*576 + c;
    q[0] = v[0]*sc0;
#pragma unroll
    for (int k = 1; k < 4; k++) q[k*64] = v[k]*sc1;
#pragma unroll
    for (int k = 4; k < 9; k++) q[k*64] = v[k]*sc2;
}

// ---------------- xjp: 80000 rows x 128, K=64 ----------------
#define XJ_GRID 1250
__global__ void __launch_bounds__(256) xjp_mma()
{
    extern __shared__ uint32_t sm[];
    uint32_t* Xs = sm;            // 2304
    uint32_t* Ws = sm + 2304;     // 4224
    int rbase = blockIdx.x * 64;
    int t = threadIdx.x, lane = t & 31, w = t >> 5, mg = w & 1, ng = w >> 1;
    cp_chunk<1056,256>(Ws, g_Wxjc, t);
    {
        int r = t >> 2, q = t & 3;
        int gr = rbase + r;
        int node = gr >> 3, slot = 1 + (gr & 7);
        const float4* yp = (const float4*)&g_xn[(size_t)node*576 + slot*64 + q*16];
        uint32_t* col = Xs + r*36 + q*8;
#pragma unroll
        for (int i = 0; i < 4; i++) {
            float4 v = yp[i];
            *(uint2*)(col + i*2) = make_uint2(f2bf2(v.x, v.y), f2bf2(v.z, v.w));
        }
    }
    CP_WAIT0();
    __syncthreads();
    float acc[8][4] = {};
    gemm_mma<36,264,4>(Ws, Xs, lane, mg, ng, acc);
    int nbase = ng*32 + (lane&3)*2;
    int ebase = mg*32 + (lane>>2);
#pragma unroll
    for (int mt = 0; mt < 2; mt++)
#pragma unroll
    for (int hf = 0; hf < 2; hf++) {
        int gr = rbase + ebase + mt*16 + hf*8;
        int node = gr >> 3, slot = gr & 7;
        size_t ob = (size_t)node*1024 + (size_t)slot*128;
#pragma unroll
        for (int nt = 0; nt < 4; nt++) {
            int n = nbase + nt*8;
            *(float2*)&g_xjp[ob + n] =
                make_float2(acc[mt*4+nt][hf*2+0], acc[mt*4+nt][hf*2+1]);
        }
    }
}

// ---------------- gate: 10000 rows x 128, K=64 ----------------
#define GATE_GRID 157
__global__ void __launch_bounds__(256) gate_mma(const float* __restrict__ bg)
{
    extern __shared__ uint32_t sm[];
    uint32_t* Xs = sm;
    uint32_t* Ws = sm + 2304;
    int rbase = blockIdx.x * 64;
    int t = threadIdx.x, lane = t & 31, w = t >> 5, mg = w & 1, ng = w >> 1;
    cp_chunk<1056,256>(Ws, g_Wgc, t);
    {
        int r = t >> 2, q = t & 3;
        int node = rbase + r;
        uint32_t* col = Xs + r*36 + q*8;
        if (node < NN) {
            const float4* yp = (const float4*)&g_yn[(size_t)node*576 + q*16];
#pragma unroll
            for (int i = 0; i < 4; i++) {
                float4 v = yp[i];
                *(uint2*)(col + i*2) = make_uint2(f2bf2(v.x, v.y), f2bf2(v.z, v.w));
            }
        } else {
#pragma unroll
            for (int i = 0; i < 4; i++) *(uint2*)(col + i*2) = make_uint2(0,0);
        }
    }
    CP_WAIT0();
    __syncthreads();
    float acc[8][4] = {};
    gemm_mma<36,264,4>(Ws, Xs, lane, mg, ng, acc);
    int nbase = ng*32 + (lane&3)*2;
    int ebase = mg*32 + (lane>>2);
#pragma unroll
    for (int mt = 0; mt < 2; mt++)
#pragma unroll
    for (int hf = 0; hf < 2; hf++) {
        int node = rbase + ebase + mt*16 + hf*8;
        if (node >= NN) continue;
        size_t ob = (size_t)node*128;
#pragma unroll
        for (int nt = 0; nt < 4; nt++) {
            int n = nbase + nt*8;
            float z0 = acc[mt*4+nt][hf*2+0] + bg[n];
            float z1 = acc[mt*4+nt][hf*2+1] + bg[n+1];
            float s0 = sigm(z0), s1 = sigm(z1);
            *(float2*)&g_gsil[ob + n] = make_float2(z0*s0, z1*s1);
            *(float2*)&g_gsig[ob + n] = make_float2(s0, s1);
        }
    }
}

// ---------------- radial MLP: 128 edges/block, 8-half triple-buffered pipeline ----------------
__global__ void __launch_bounds__(512,2) rad_kernel(
    const float* __restrict__ edist, const float* __restrict__ semb,
    const float* __restrict__ temb,  const float* __restrict__ b1,
    const float* __restrict__ b2,    const int* __restrict__ anum,
    const int* __restrict__ eidx)
{
    extern __shared__ uint32_t sm[];
    uint32_t* ef = sm;            // 8704
    uint32_t* Ws = sm + 8704;     // 3 x 4224 = 12672
    int* zsrc = (int*)(sm + 21376);
    int* ztgt = zsrc + 128;
    int e0 = blockIdx.x * 128, t = threadIdx.x;
    int lane = t & 31, w = t >> 5, mg = w & 3, ng = w >> 2;
    auto hsrc = [](int m) { return m < 2 ? g_W1c + m*4224 : g_W2c + (m-2)*4224; };
    cp_chunk<1056,512>(Ws,        hsrc(0), t);
    cp_chunk<1056,512>(Ws + 4224, hsrc(1), t);
    if (t < 128)      zsrc[t]     = anum[eidx[e0 + t]];
    else if (t < 256) ztgt[t-128] = anum[eidx[NE + e0 + t - 128]];
    {
        int e = t >> 2, q = t & 3;
        const float4* xp;
        if (q < 2)      xp = (const float4*)&edist[(size_t)(e0+e)*64 + q*32];
        else if (q==2)  xp = (const float4*)&semb[(size_t)zsrc[e]*32];
        else            xp = (const float4*)&temb[(size_t)ztgt[e]*32];
        // zsrc/ztgt race: staged by same warps that wrote? need sync first
        // (handled below: we sync before first gemm; but xp uses zsrc -> do safe path)
        (void)xp;
    }
    __syncthreads();   // zsrc/ztgt visible
    {
        int e = t >> 2, q = t & 3;
        const float4* xp;
        if (q < 2)      xp = (const float4*)&edist[(size_t)(e0+e)*64 + q*32];
        else if (q==2)  xp = (const float4*)&semb[(size_t)zsrc[e]*32];
        else            xp = (const float4*)&temb[(size_t)ztgt[e]*32];
        uint32_t* col = ef + e*68 + q*16;
#pragma unroll
        for (int i4 = 0; i4 < 8; i4++) {
            float4 v = xp[i4];
            *(uint2*)(col + i4*2) = make_uint2(f2bf2(v.x, v.y), f2bf2(v.z, v.w));
        }
    }
    int nbase = ng*32 + (lane&3)*2;
    int ebase = mg*32 + (lane>>2);
    int m = 0, mb = 0;   // mb = m % 3
    {   // layer 1: stages 0,1
        float acc[8][4] = {};
        for (int s = 0; s < 2; s++, m++) {
            if (m + 1 < 8) CP_WAIT1(); else CP_WAIT0();
            __syncthreads();
            gemm_mma<68,264,4>(Ws + mb*4224, ef + s*32, lane, mg, ng, acc);
            if (m + 2 < 8) {
                int nb = mb + 2; if (nb >= 3) nb -= 3;
                cp_chunk<1056,512>(Ws + nb*4224, hsrc(m+2), t);
            }
            if (++mb == 3) mb = 0;
        }
        __syncthreads();   // all layer-1 reads of ef done before overwrite
#pragma unroll
        for (int nt = 0; nt < 4; nt++) {
            int n = nbase + nt*8;
            float2 bb = *(const float2*)&b1[n];
#pragma unroll
            for (int mt = 0; mt < 2; mt++)
#pragma unroll
            for (int hf = 0; hf < 2; hf++) {
                int el = ebase + mt*16 + hf*8;
                float z0 = acc[mt*4+nt][hf*2+0] + bb.x;
                float z1 = acc[mt*4+nt][hf*2+1] + bb.y;
                ef[el*68 + (n>>1)] = f2bf2(z0*sigm(z0), z1*sigm(z1));
            }
        }
    }
    for (int j = 0; j < 3; j++) {
        float acc[8][4] = {};
        for (int s = 0; s < 2; s++, m++) {
            if (m + 1 < 8) CP_WAIT1(); else CP_WAIT0();
            __syncthreads();
            gemm_mma<68,264,4>(Ws + mb*4224, ef + s*32, lane, mg, ng, acc);
            if (m + 2 < 8) {
                int nb = mb + 2; if (nb >= 3) nb -= 3;
                cp_chunk<1056,512>(Ws + nb*4224, hsrc(m+2), t);
            }
            if (++mb == 3) mb = 0;
        }
#pragma unroll
        for (int nt = 0; nt < 4; nt++) {
            int n = nbase + nt*8;
            float2 bb = *(const float2*)&b2[j*128 + n];
#pragma unroll
            for (int mt = 0; mt < 2; mt++)
#pragma unroll
            for (int hf = 0; hf < 2; hf++) {
                int el = ebase + mt*16 + hf*8;
                *(float2*)&g_rad[(size_t)(e0+el)*384 + j*128 + n] =
                    make_float2(acc[mt*4+nt][hf*2+0] + bb.x, acc[mt*4+nt][hf*2+1] + bb.y);
            }
        }
    }
}

// ---------------- extra: 14-half triple-buffered pipeline ----------------
__global__ void __launch_bounds__(512,2) extra_kernel(
    const float* __restrict__ lng, const float* __restrict__ lnb,
    const float* __restrict__ adot, const int* __restrict__ eidx)
{
    extern __shared__ uint32_t sm[];
    uint32_t* Xs = sm;            // 8704
    uint32_t* Ws = sm + 8704;     // 12672
    int* src_s = (int*)(sm + 21376);
    int* tgt_s = src_s + 128;
    int e0 = blockIdx.x * 128, t = threadIdx.x;
    int lane = t & 31, w = t >> 5, mg = w & 3, ng = w >> 2;
    cp_chunk<1056,512>(Ws,        g_Wm0c,        t);
    cp_chunk<1056,512>(Ws + 4224, g_Wm0c + 4224, t);
    if (t < 128)      src_s[t]     = eidx[e0 + t];
    else if (t < 256) tgt_s[t-128] = eidx[NE + e0 + t - 128];
    __syncthreads();
    {
        int e = t >> 2, q = t & 3;
        const float4* rp = (const float4*)&g_rad[(size_t)(e0+e)*384 + q*32];
        const float4* xp = (q < 2)
            ? (const float4*)&g_xn[(size_t)src_s[e]*576 + q*32]
            : (const float4*)&g_xn[(size_t)tgt_s[e]*576 + (q-2)*32];
        uint32_t* col = Xs + e*68 + q*16;
#pragma unroll
        for (int i4 = 0; i4 < 8; i4++) {
            float4 xv = xp[i4], rv = rp[i4];
            *(uint2*)(col + i4*2) =
                make_uint2(f2bf2(xv.x*rv.x, xv.y*rv.y), f2bf2(xv.z*rv.z, xv.w*rv.w));
        }
    }
    int nbase = ng*32 + (lane&3)*2;
    int ebase = mg*32 + (lane>>2);
    int m = 0, mb = 0;
    for (int oc = 0; oc < 7; oc++) {
        float acc[8][4] = {};
        for (int s = 0; s < 2; s++, m++) {
            if (m + 1 < 14) CP_WAIT1(); else CP_WAIT0();
            __syncthreads();
            gemm_mma<68,264,4>(Ws + mb*4224, Xs + s*32, lane, mg, ng, acc);
            if (m + 2 < 14) {
                int nb = mb + 2; if (nb >= 3) nb -= 3;
                cp_chunk<1056,512>(Ws + nb*4224, g_Wm0c + (m+2)*4224, t);
            }
            if (++mb == 3) mb = 0;
        }
        if (oc < 2) {
            int h = oc*4 + ng;
#pragma unroll
            for (int mt = 0; mt < 2; mt++)
#pragma unroll
            for (int hf = 0; hf < 2; hf++) {
                int el = ebase + mt*16 + hf*8;
                float sum = 0.f, ssq = 0.f;
#pragma unroll
                for (int nt = 0; nt < 4; nt++) {
                    float v0 = acc[mt*4+nt][hf*2+0], v1 = acc[mt*4+nt][hf*2+1];
                    sum += v0 + v1; ssq += v0*v0 + v1*v1;
                }
                sum += __shfl_xor_sync(0xffffffffu, sum, 1);
                sum += __shfl_xor_sync(0xffffffffu, sum, 2);
                ssq += __shfl_xor_sync(0xffffffffu, ssq, 1);
                ssq += __shfl_xor_sync(0xffffffffu, ssq, 2);
                float mean = sum * (1.f/32.f);
                float rs = rsqrtf(ssq * (1.f/32.f) - mean*mean + 1e-5f);
                float logit = 0.f;
#pragma unroll
                for (int nt = 0; nt < 4; nt++) {
                    int a = nt*8 + (lane&3)*2;
#pragma unroll
                    for (int jj = 0; jj < 2; jj++) {
                        float v = acc[mt*4+nt][hf*2+jj];
                        float an = (v - mean)*rs*lng[a+jj] + lnb[a+jj];
                        logit += (0.2f*an + 0.8f*an*sigm(an)) * adot[h*32 + a + jj];
                    }
                }
                logit += __shfl_xor_sync(0xffffffffu, logit, 1);
                logit += __shfl_xor_sync(0xffffffffu, logit, 2);
                if ((lane & 3) == 0) {
                    float ex = __expf(logit);
                    g_e[(size_t)(e0+el)*8 + h] = ex;
                    atomicAdd(&g_den[(size_t)tgt_s[el]*8 + h], ex);
                }
            }
        } else if (oc == 2) {
#pragma unroll
            for (int nt = 0; nt < 4; nt++) {
                int n = nbase + nt*8;
#pragma unroll
                for (int mt = 0; mt < 2; mt++)
#pragma unroll
                for (int hf = 0; hf < 2; hf++) {
                    int el = ebase + mt*16 + hf*8;
                    float z0 = acc[mt*4+nt][hf*2+0], z1 = acc[mt*4+nt][hf*2+1];
                    *(float2*)&g_val0[(size_t)(e0+el)*128 + n] =
                        make_float2(z0*sigm(z0), z1*sigm(z1));
                }
            }
        } else {
            int which = oc - 3;
            float* base = (which < 2) ? g_gdir : g_gten;
            int l = which & 1;
#pragma unroll
            for (int nt = 0; nt < 4; nt++) {
                int n = nbase + nt*8;
#pragma unroll
                for (int mt = 0; mt < 2; mt++)
#pragma unroll
                for (int hf = 0; hf < 2; hf++) {
                    int el = ebase + mt*16 + hf*8;
                    *(float2*)&base[(size_t)(e0+el)*256 + l*128 + n] =
                        make_float2(sigm(acc[mt*4+nt][hf*2+0]), sigm(acc[mt*4+nt][hf*2+1]));
                }
            }
        }
    }
}

// ---------------- fused conv1+conv2: resident bf16 weights, 2 blocks/SM ----------------
__global__ void __launch_bounds__(512,2) conv_kernel(
    const float* __restrict__ rl, const int* __restrict__ eidx)
{
    extern __shared__ uint32_t sm[];
    uint32_t* XV  = sm;            // 8704
    uint32_t* W1s = sm + 8704;     // 8448
    uint32_t* W2s = sm + 17152;    // 8448
    float* rl_s = (float*)(sm + 25600);
    float* ee_s = (float*)(sm + 26624);
    int* src_s = (int*)(sm + 27648);
    int* tgt_s = (int*)(sm + 27776);
    int e0 = blockIdx.x * 128, t = threadIdx.x;
    int lane = t & 31, w = t >> 5, mg = w & 3, ng = w >> 2;
    if (t < 128)      src_s[t]     = eidx[e0 + t];
    else if (t < 256) tgt_s[t-128] = eidx[NE + e0 + t - 128];
    for (int i = t; i < 1024; i += 512) {
        rl_s[i] = rl[(size_t)e0*8 + i];
        ee_s[i] = g_e[(size_t)e0*8 + i];
    }
    int nbase = ng*32 + (lane&3)*2;
    int ebase = mg*32 + (lane>>2);
    int se = t >> 2, sq = t & 3;

    for (int deg = 0; deg <= 2; deg++) {
        __syncthreads();
        cp_chunk<2112,512>(W2s, g_Wc2c + deg*8448, t);
        if (deg) cp_chunk<2112,512>(W1s, g_Wc1c + deg*8448, t);
        int kbeg = (deg == 0) ? 0 : ((deg == 1) ? 1 : 4);
        int kend = (deg == 0) ? 1 : ((deg == 1) ? 4 : 9);
        for (int k = kbeg; k < kend; k++) {
            if (deg == 0) {
                const float4* vp = (const float4*)&g_val0[(size_t)(e0+se)*128 + sq*32];
                uint32_t* col = XV + se*68 + sq*16;
#pragma unroll
                for (int i4 = 0; i4 < 8; i4++) {
                    float4 v = vp[i4];
                    *(uint2*)(col + i4*2) = make_uint2(f2bf2(v.x, v.y), f2bf2(v.z, v.w));
                }
            } else {
                const float4* rp = (const float4*)&g_rad[(size_t)(e0+se)*384 + deg*128 + sq*32];
                const float4* xp = (sq < 2)
                    ? (const float4*)&g_xn[(size_t)src_s[se]*576 + k*64 + sq*32]
                    : (const float4*)&g_xn[(size_t)tgt_s[se]*576 + k*64 + (sq-2)*32];
                uint32_t* col = XV + se*68 + sq*16;
#pragma unroll
                for (int i4 = 0; i4 < 8; i4++) {
                    float4 xv = xp[i4], rv = rp[i4];
                    *(uint2*)(col + i4*2) =
                        make_uint2(f2bf2(xv.x*rv.x, xv.y*rv.y), f2bf2(xv.z*rv.z, xv.w*rv.w));
                }
            }
            if (k == kbeg) CP_WAIT0();
            __syncthreads();
            if (deg) {
                float acc[8][4] = {};
                gemm_mma<68,264,8>(W1s, XV, lane, mg, ng, acc);
                int l = (k < 4) ? 0 : 1;
#pragma unroll
                for (int mt = 0; mt < 2; mt++)
#pragma unroll
                for (int hf = 0; hf < 2; hf++) {
                    int el = ebase + mt*16 + hf*8;
                    size_t ge = (size_t)(e0 + el);
                    float r = rl_s[el*8 + (k-1)];
                    size_t gb = ge*256 + l*128;
                    size_t xb = (size_t)src_s[el]*1024 + (size_t)(k-1)*128;
#pragma unroll
                    for (int nt = 0; nt < 4; nt++) {
                        int n = nbase + nt*8;
                        float2 gd = *(const float2*)&g_gdir[gb + n];
                        float2 gt = *(const float2*)&g_gten[gb + n];
                        float2 xj = *(const float2*)&g_xjp[xb + n];
                        acc[mt*4+nt][hf*2+0] += r*gd.x + xj.x*gt.x;
                        acc[mt*4+nt][hf*2+1] += r*gd.y + xj.y*gt.y;
                    }
                }
                __syncthreads();
#pragma unroll
                for (int mt = 0; mt < 2; mt++)
#pragma unroll
                for (int hf = 0; hf < 2; hf++) {
                    int el = ebase + mt*16 + hf*8;
#pragma unroll
                    for (int nt = 0; nt < 4; nt++) {
                        int n = nbase + nt*8;
                        XV[el*68 + (n>>1)] =
                            f2bf2(acc[mt*4+nt][hf*2+0], acc[mt*4+nt][hf*2+1]);
                    }
                }
                __syncthreads();
            }
            float acc[8][4] = {};
            gemm_mma<68,264,8>(W2s, XV, lane, mg, ng, acc);
#pragma unroll
            for (int mt = 0; mt < 2; mt++)
#pragma unroll
            for (int hf = 0; hf < 2; hf++) {
                int el = ebase + mt*16 + hf*8;
                size_t nb = (size_t)tgt_s[el]*1152 + (size_t)k*128;
#pragma unroll
                for (int nt = 0; nt < 4; nt++) {
                    int n = nbase + nt*8;
                    float s = ee_s[el*8 + (n >> 4)];
                    red2(&g_num[nb + n], acc[mt*4+nt][hf*2+0]*s, acc[mt*4+nt][hf*2+1]*s);
                }
            }
            __syncthreads();
        }
    }
}

// ---------------- node GEMMs ----------------
#define P_T0 79
#define P_T1 314
#define P_GRID 705
__device__ __forceinline__ void node_row(int b, int* deg, int* rbase,
                                         int* nslots, int* soff, int* nrows)
{
    if (b < P_T0)      { *deg=0; *rbase=b*128;          *nslots=1; *soff=0; *nrows=10000; }
    else if (b < P_T1) { *deg=1; *rbase=(b-P_T0)*128;   *nslots=3; *soff=1; *nrows=30000; }
    else               { *deg=2; *rbase=(b-P_T1)*128;   *nslots=5; *soff=4; *nrows=50000; }
}

__global__ void __launch_bounds__(256,2) proj_mma(
    const float* __restrict__ x, const float* __restrict__ bp)
{
    extern __shared__ uint32_t sm[];
    uint32_t* Xs = sm;            // 8704
    uint32_t* Ws = sm + 8704;     // 4352
    int deg, rbase, nslots, soff, nrows;
    node_row(blockIdx.x, &deg, &rbase, &nslots, &soff, &nrows);
    int t = threadIdx.x, lane = t & 31, w = t >> 5, mg = w & 3, ng = w >> 2;
    cp_chunk<1088,256>(Ws, g_Wpc + deg*4352, t);
    {
        int r = t >> 1, h2 = t & 1;
        int gr = rbase + r;
        uint32_t* col = Xs + r*68 + h2*32;
        if (gr < nrows) {
            int node = gr / nslots, slot = soff + gr % nslots;
            const float4* np = (const float4*)&g_num[(size_t)node*1152 + slot*128 + h2*64];
            float di[4];
#pragma unroll
            for (int q = 0; q < 4; q++) di[q] = 1.f / (g_den[node*8 + h2*4 + q] + 1e-30f);
#pragma unroll
            for (int i = 0; i < 16; i++) {
                float4 v = np[i]; float d = di[i>>2];
                *(uint2*)(col + i*2) = make_uint2(f2bf2(v.x*d, v.y*d), f2bf2(v.z*d, v.w*d));
            }
        } else {
#pragma unroll
            for (int i = 0; i < 16; i++) *(uint2*)(col + i*2) = make_uint2(0,0);
        }
    }
    CP_WAIT0();
    __syncthreads();
    float acc[8][4] = {};
    gemm_mma<68,136,8>(Ws, Xs, lane, mg, ng, acc);
    int nbase = ng*32 + (lane&3)*2;
    int ebase = mg*32 + (lane>>2);
#pragma unroll
    for (int mt = 0; mt < 2; mt++)
#pragma unroll
    for (int hf = 0; hf < 2; hf++) {
        int gr = rbase + ebase + mt*16 + hf*8;
        if (gr >= nrows) continue;
        int node = gr / nslots, slot = soff + gr % nslots;
        size_t ob = (size_t)node*576 + slot*64;
#pragma unroll
        for (int nt = 0; nt < 4; nt++) {
            int n = nbase + nt*8;
            float b0 = (slot == 0) ? bp[n] : 0.f, b1 = (slot == 0) ? bp[n+1] : 0.f;
            *(float2*)&g_x1[ob + n] = make_float2(
                x[ob + n]   + acc[mt*4+nt][hf*2+0] + b0,
                x[ob + n+1] + acc[mt*4+nt][hf*2+1] + b1);
        }
    }
}

__global__ void __launch_bounds__(256,2) ffn2_mma(
    const float* __restrict__ bf2, float* __restrict__ out)
{
    extern __shared__ uint32_t sm[];
    uint32_t* Xs = sm;
    uint32_t* Ws = sm + 8704;
    int deg, rbase, nslots, soff, nrows;
    node_row(blockIdx.x, &deg, &rbase, &nslots, &soff, &nrows);
    int t = threadIdx.x, lane = t & 31, w = t >> 5, mg = w & 3, ng = w >> 2;
    cp_chunk<1088,256>(Ws, g_Wf2c + deg*4352, t);
    {
        int r = t >> 1, h2 = t & 1;
        int gr = rbase + r;
        uint32_t* col = Xs + r*68 + h2*32;
        if (gr < nrows) {
            int node = gr / nslots, slot = soff + gr % nslots;
            const float4* hp = (slot == 0)
                ? (const float4*)&g_gsil[(size_t)node*128 + h2*64]
                : (const float4*)&g_h[(size_t)node*1024 + (size_t)(slot-1)*128 + h2*64];
#pragma unroll
            for (int i = 0; i < 16; i++) {
                float4 v = hp[i];
                *(uint2*)(col + i*2) = make_uint2(f2bf2(v.x, v.y), f2bf2(v.z, v.w));
            }
        } else {
#pragma unroll
            for (int i = 0; i < 16; i++) *(uint2*)(col + i*2) = make_uint2(0,0);
        }
    }
    CP_WAIT0();
    __syncthreads();
    float acc[8][4] = {};
    gemm_mma<68,136,8>(Ws, Xs, lane, mg, ng, acc);
    int nbase = ng*32 + (lane&3)*2;
    int ebase = mg*32 + (lane>>2);
#pragma unroll
    for (int mt = 0; mt < 2; mt++)
#pragma unroll
    for (int hf = 0; hf < 2; hf++) {
        int gr = rbase + ebase + mt*16 + hf*8;
        if (gr >= nrows) continue;
        int node = gr / nslots, slot = soff + gr % nslots;
        size_t ob = (size_t)node*576 + slot*64;
#pragma unroll
        for (int nt = 0; nt < 4; nt++) {
            int n = nbase + nt*8;
            float b0 = (slot == 0) ? bf2[n] : 0.f, b1 = (slot == 0) ? bf2[n+1] : 0.f;
            *(float2*)&out[ob + n] = make_float2(
                g_x1[ob + n]   + acc[mt*4+nt][hf*2+0] + b0,
                g_x1[ob + n+1] + acc[mt*4+nt][hf*2+1] + b1);
        }
    }
}

#define F_T1 469
#define F_GRID 1251
__global__ void __launch_bounds__(256) ffn1_mma()
{
    extern __shared__ uint32_t sm[];
    uint32_t* Xs = sm;            // 2304
    uint32_t* Ws = sm + 2304;     // 4224
    int b = blockIdx.x, deg, rbase, nslots, soff, nrows;
    if (b < F_T1) { deg=1; rbase=b*64;         nslots=3; soff=1; nrows=30000; }
    else          { deg=2; rbase=(b-F_T1)*64;  nslots=5; soff=4; nrows=50000; }
    int t = threadIdx.x, lane = t & 31, w = t >> 5, mg = w & 1, ng = w >> 1;
    cp_chunk<1056,256>(Ws, g_Wf1c + deg*4224, t);
    {
        int r = t >> 2, q = t & 3;
        int gr = rbase + r;
        uint32_t* col = Xs + r*36 + q*8;
        if (gr < nrows) {
            int node = gr / nslots, slot = soff + gr % nslots;
            const float4* yp = (const float4*)&g_yn[(size_t)node*576 + slot*64 + q*16];
#pragma unroll
            for (int i = 0; i < 4; i++) {
                float4 v = yp[i];
                *(uint2*)(col + i*2) = make_uint2(f2bf2(v.x, v.y), f2bf2(v.z, v.w));
            }
        } else {
#pragma unroll
            for (int i = 0; i < 4; i++) *(uint2*)(col + i*2) = make_uint2(0,0);
        }
    }
    CP_WAIT0();
    __syncthreads();
    float acc[8][4] = {};
    gemm_mma<36,264,4>(Ws, Xs, lane, mg, ng, acc);
    int nbase = ng*32 + (lane&3)*2;
    int ebase = mg*32 + (lane>>2);
#pragma unroll
    for (int mt = 0; mt < 2; mt++)
#pragma unroll
    for (int hf = 0; hf < 2; hf++) {
        int gr = rbase + ebase + mt*16 + hf*8;
        if (gr >= nrows) continue;
        int node = gr / nslots, slot = soff + gr % nslots;
        size_t hb = (size_t)node*1024 + (size_t)(slot-1)*128;
        size_t gsb = (size_t)node*128;
#pragma unroll
        for (int nt = 0; nt < 4; nt++) {
            int n = nbase + nt*8;
            float2 gs = *(const float2*)&g_gsig[gsb + n];
            *(float2*)&g_h[hb + n] = make_float2(
                acc[mt*4+nt][hf*2+0]*gs.x, acc[mt*4+nt][hf*2+1]*gs.y);
        }
    }
}

// ---------------- launch ----------------
extern "C" void kernel_launch(void* const* d_in, const int* in_sizes, int n_in,
                              void* d_out, int out_size)
{
    const float* x     = (const float*)d_in[0];
    const float* edist = (const float*)d_in[1];
    const float* rl    = (const float*)d_in[2];
    const float* semb  = (const float*)d_in[3];
    const float* temb  = (const float*)d_in[4];
    const float* W1    = (const float*)d_in[5];
    const float* b1    = (const float*)d_in[6];
    const float* W2    = (const float*)d_in[7];
    const float* b2    = (const float*)d_in[8];
    const float* Wc1   = (const float*)d_in[9];
    const float* Wm0   = (const float*)d_in[10];
    const float* lng   = (const float*)d_in[11];
    const float* lnb   = (const float*)d_in[12];
    const float* adot  = (const float*)d_in[13];
    const float* Wxj   = (const float*)d_in[14];
    const float* Wc2   = (const float*)d_in[15];
    const float* Wp    = (const float*)d_in[16];
    const float* bp    = (const float*)d_in[17];
    const float* Wg    = (const float*)d_in[18];
    const float* bg    = (const float*)d_in[19];
    const float* Wf1   = (const float*)d_in[20];
    const float* Wf2   = (const float*)d_in[22];
    const float* bf2   = (const float*)d_in[23];
    const int*   anum  = (const int*)d_in[24];
    const int*   eidx  = (const int*)d_in[25];
    float* out = (float*)d_out;

    float *p_xn, *p_x1, *p_yn;
    cudaGetSymbolAddress((void**)&p_xn, g_xn);
    cudaGetSymbolAddress((void**)&p_x1, g_x1);
    cudaGetSymbolAddress((void**)&p_yn, g_yn);

    static bool attr_set = false;
    if (!attr_set) {
        cudaFuncSetAttribute(rad_kernel,   cudaFuncAttributeMaxDynamicSharedMemorySize, 86528);
        cudaFuncSetAttribute(extra_kernel, cudaFuncAttributeMaxDynamicSharedMemorySize, 86528);
        cudaFuncSetAttribute(conv_kernel,  cudaFuncAttributeMaxDynamicSharedMemorySize, 111616);
        cudaFuncSetAttribute(proj_mma,     cudaFuncAttributeMaxDynamicSharedMemorySize, 52224);
        cudaFuncSetAttribute(ffn2_mma,     cudaFuncAttributeMaxDynamicSharedMemorySize, 52224);
        cudaFuncSetAttribute(ffn1_mma,     cudaFuncAttributeMaxDynamicSharedMemorySize, 26112);
        cudaFuncSetAttribute(xjp_mma,      cudaFuncAttributeMaxDynamicSharedMemorySize, 26112);
        cudaFuncSetAttribute(gate_mma,     cudaFuncAttributeMaxDynamicSharedMemorySize, 26112);
        attr_set = true;
    }

    wconv_kernel<<<(WCONV_N + 255)/256, 256>>>(W1, W2, Wm0, Wc1, Wc2, Wp, Wf1, Wf2, Wxj, Wg);
    zero_kernel<<<(NN*1152/4 + 255)/256, 256>>>();
    enorm_kernel<<<NN/4, 256>>>(x, p_xn);
    xjp_mma<<<XJ_GRID, 256, 26112>>>();
    rad_kernel<<<NE/128, 512, 86528>>>(edist, semb, temb, b1, b2, anum, eidx);
    extra_kernel<<<NE/128, 512, 86528>>>(lng, lnb, adot, eidx);
    conv_kernel<<<NE/128, 512, 111616>>>(rl, eidx);
    proj_mma<<<P_GRID, 256, 52224>>>(x, bp);
    enorm_kernel<<<NN/4, 256>>>(p_x1, p_yn);
    gate_mma<<<GATE_GRID, 256, 26112>>>(bg);
    ffn1_mma<<<F_GRID, 256, 26112>>>();
    ffn2_mma<<<P_GRID, 256, 52224>>>(bf2, out);
}

// round 15
// speedup vs baseline: 1.3120x; 1.0312x over previous
#include <cuda_runtime.h>
#include <cstdint>

#define NN 10000
#define NE 80000

__device__ float g_xn  [NN*576];
__device__ float g_rad [NE*384];
__device__ float g_val0[NE*128];
__device__ float g_gdir[NE*256];
__device__ float g_gten[NE*256];
__device__ float g_e   [NE*8];
__device__ float g_xjp [NN*1024];
__device__ float g_num [NN*1152];
__device__ float g_den [NN*8];
__device__ float g_x1  [NN*576];
__device__ float g_yn  [NN*576];
__device__ float g_h   [NN*1024];
__device__ float g_gsil[NN*128];
__device__ float g_gsig[NN*128];

// bf16-pair weights, row-major [n][k2] images (ldmatrix-ready), row stride padded
// 128-k chunks: stride 68 (64+4). 64-k chunks: stride 36 (32+4).
__device__ __align__(16) uint32_t g_W1c [9216];    // 2 halves  (64k x 128n, 4608 ea)
__device__ __align__(16) uint32_t g_W2c [27648];   // 6 halves
__device__ __align__(16) uint32_t g_Wm0c[64512];   // 14 halves
__device__ __align__(16) uint32_t g_Wc1c[26112];   // 3 chunks (128k x 128n, 8704 ea)
__device__ __align__(16) uint32_t g_Wc2c[26112];
__device__ __align__(16) uint32_t g_Wpc [13056];   // 3 chunks (128k x 64n, 4352 ea)
__device__ __align__(16) uint32_t g_Wf1c[13824];   // 3 chunks (64k x 128n, 4608 ea; deg0 unused)
__device__ __align__(16) uint32_t g_Wf2c[13056];
__device__ __align__(16) uint32_t g_Wxjc[4608];
__device__ __align__(16) uint32_t g_Wgc [4608];

__device__ __forceinline__ float sigm(float z) { return 1.f / (1.f + __expf(-z)); }

__device__ __forceinline__ uint32_t f2bf2(float lo, float hi) {
    uint32_t r; asm("cvt.rn.bf16x2.f32 %0, %1, %2;" : "=r"(r) : "f"(hi), "f"(lo)); return r;
}
__device__ __forceinline__ void red2(float* p, float a, float b) {
    asm volatile("red.global.add.v2.f32 [%0], {%1,%2};" :: "l"(p), "f"(a), "f"(b) : "memory");
}
__device__ __forceinline__ void mma16(float* d, uint32_t a0,uint32_t a1,uint32_t a2,uint32_t a3,
                                      uint32_t b0,uint32_t b1) {
    asm volatile("mma.sync.aligned.m16n8k16.row.col.f32.bf16.bf16.f32 "
                 "{%0,%1,%2,%3},{%4,%5,%6,%7},{%8,%9},{%0,%1,%2,%3};"
                 : "+f"(d[0]),"+f"(d[1]),"+f"(d[2]),"+f"(d[3])
                 : "r"(a0),"r"(a1),"r"(a2),"r"(a3),"r"(b0),"r"(b1));
}
__device__ __forceinline__ uint32_t s2u(const uint32_t* p) {
    return (uint32_t)__cvta_generic_to_shared(p);
}
#define LDSM4(r0,r1,r2,r3,addr) \
    asm volatile("ldmatrix.sync.aligned.m8n8.x4.shared.b16 {%0,%1,%2,%3}, [%4];" \
        : "=r"(r0),"=r"(r1),"=r"(r2),"=r"(r3) : "r"(addr))

// ---- cp.async helpers ----
__device__ __forceinline__ void cp16(uint32_t saddr, const uint32_t* src) {
    asm volatile("cp.async.cg.shared.global [%0], [%1], 16;" :: "r"(saddr), "l"(src));
}
#define CP_COMMIT() asm volatile("cp.async.commit_group;" ::: "memory")
#define CP_WAIT0()  asm volatile("cp.async.wait_group 0;" ::: "memory")
#define CP_WAIT1()  asm volatile("cp.async.wait_group 1;" ::: "memory")

template<int N4, int NT>
__device__ __forceinline__ void cp_chunk(uint32_t* dst, const uint32_t* __restrict__ src, int t) {
    uint32_t d = (uint32_t)__cvta_generic_to_shared(dst);
    for (int i = t; i < N4; i += NT) cp16(d + i*16, src + i*4);
    CP_COMMIT();
}

// Warp tile 32 rows x 32 cols, bf16 k16, ldmatrix fragment loads.
template<int XST, int WST, int NK>
__device__ __forceinline__ void gemm_mma(const uint32_t* __restrict__ Ws,
                                         const uint32_t* __restrict__ Xs,
                                         int lane, int mg, int ng, float acc[8][4])
{
    int aro = ((lane>>3)&1)*8 + (lane&7);
    int awo = (lane>>4)*4;
    uint32_t aa0 = s2u(Xs + (mg*32 + aro)*XST + awo);
    uint32_t aa1 = aa0 + 16*XST*4;
    int bro = (lane&7) + (lane>>4)*8;
    int bwo = ((lane>>3)&1)*4;
    uint32_t ba0 = s2u(Ws + (ng*32 + bro)*WST + bwo);
    uint32_t ba1 = ba0 + 16*WST*4;
#pragma unroll
    for (int kk = 0; kk < NK; kk++) {
        uint32_t a0,a1,a2,a3, c0,c1,c2,c3, p0,p1,p2,p3, q0,q1,q2,q3;
        LDSM4(a0,a1,a2,a3, aa0 + kk*32);
        LDSM4(c0,c1,c2,c3, aa1 + kk*32);
        LDSM4(p0,p1,p2,p3, ba0 + kk*32);
        LDSM4(q0,q1,q2,q3, ba1 + kk*32);
        mma16(acc[0], a0,a1,a2,a3, p0,p1);
        mma16(acc[1], a0,a1,a2,a3, p2,p3);
        mma16(acc[2], a0,a1,a2,a3, q0,q1);
        mma16(acc[3], a0,a1,a2,a3, q2,q3);
        mma16(acc[4], c0,c1,c2,c3, p0,p1);
        mma16(acc[5], c0,c1,c2,c3, p2,p3);
        mma16(acc[6], c0,c1,c2,c3, q0,q1);
        mma16(acc[7], c0,c1,c2,c3, q2,q3);
    }
}

// ---------------- weight pre-conversion (row-major [n][k2] images) ----------------
__global__ void __launch_bounds__(256) wconv_kernel(
    const float* __restrict__ W1, const float* __restrict__ W2,
    const float* __restrict__ Wm0, const float* __restrict__ Wc1,
    const float* __restrict__ Wc2, const float* __restrict__ Wp,
    const float* __restrict__ Wf1, const float* __restrict__ Wf2,
    const float* __restrict__ Wxj, const float* __restrict__ Wg)
{
    int i = blockIdx.x*256 + threadIdx.x;
    if (i < 8192) { int k2=i>>7, n=i&127;
        g_W1c[(k2>>5)*4608 + n*36 + (k2&31)] =
            f2bf2(W1[2*k2*128+n], W1[(2*k2+1)*128+n]); return; } i -= 8192;
    if (i < 24576) { int j=i/8192, r=i&8191, k2=r>>7, n=r&127;
        g_W2c[(j*2 + (k2>>5))*4608 + n*36 + (k2&31)] =
            f2bf2(W2[2*k2*384 + j*128 + n], W2[(2*k2+1)*384 + j*128 + n]); return; } i -= 24576;
    if (i < 57344){ int j=i/8192, r=i&8191, k2=r>>7, n=r&127;
        g_Wm0c[(j*2 + (k2>>5))*4608 + n*36 + (k2&31)] =
            f2bf2(Wm0[2*k2*896 + j*128 + n], Wm0[(2*k2+1)*896 + j*128 + n]); return; } i -= 57344;
    if (i < 24576) { int d=i>>13, r=i&8191, k2=r>>7, n=r&127;
        g_Wc1c[d*8704 + n*68 + k2] =
            f2bf2(Wc1[d*16384 + 2*k2*128 + n], Wc1[d*16384 + (2*k2+1)*128 + n]); return; } i -= 24576;
    if (i < 24576) { int d=i>>13, r=i&8191, k2=r>>7, n=r&127;
        g_Wc2c[d*8704 + n*68 + k2] =
            f2bf2(Wc2[d*16384 + 2*k2*128 + n], Wc2[d*16384 + (2*k2+1)*128 + n]); return; } i -= 24576;
    if (i < 12288) { int d=i>>12, r=i&4095, k2=r>>6, n=r&63;
        g_Wpc[d*4352 + n*68 + k2] =
            f2bf2(Wp[d*8192 + 2*k2*64 + n], Wp[d*8192 + (2*k2+1)*64 + n]); return; } i -= 12288;
    if (i < 8192) { int d=(i>>12)+1, r=i&4095, k2=r>>7, n=r&127;
        g_Wf1c[d*4608 + n*36 + k2] =
            f2bf2(Wf1[d*8192 + 2*k2*128 + n], Wf1[d*8192 + (2*k2+1)*128 + n]); return; } i -= 8192;
    if (i < 12288) { int d=i>>12, r=i&4095, k2=r>>6, n=r&63;
        g_Wf2c[d*4352 + n*68 + k2] =
            f2bf2(Wf2[d*8192 + 2*k2*64 + n], Wf2[d*8192 + (2*k2+1)*64 + n]); return; } i -= 12288;
    if (i < 4096)  { int k2=i>>7, n=i&127;
        g_Wxjc[n*36 + k2] = f2bf2(Wxj[2*k2*128+n], Wxj[(2*k2+1)*128+n]); return; } i -= 4096;
    if (i < 4096)  { int k2=i>>7, n=i&127;
        g_Wgc[n*36 + k2] = f2bf2(Wg[2*k2*128+n], Wg[(2*k2+1)*128+n]); return; }
}
#define WCONV_N 180224

__global__ void zero_kernel() {
    size_t i = (size_t)blockIdx.x * blockDim.x + threadIdx.x;
    if (i < NN*1152/4) ((float4*)g_num)[i] = make_float4(0.f,0.f,0.f,0.f);
    if (i < NN*8)      g_den[i] = 0.f;
}

// ---------------- enorm ----------------
__global__ void __launch_bounds__(256) enorm_kernel(const float* __restrict__ src, float* __restrict__ dst) {
    int n = blockIdx.x*4 + (threadIdx.x >> 6);
    int c = threadIdx.x & 63;
    const float* p = src + (size_t)n*576 + c;
    float v[9];
#pragma unroll
    for (int k = 0; k < 9; k++) v[k] = p[k*64];
    float s0 = v[0]*v[0];
    float s1 = v[1]*v[1] + v[2]*v[2] + v[3]*v[3];
    float s2 = v[4]*v[4] + v[5]*v[5] + v[6]*v[6] + v[7]*v[7] + v[8]*v[8];
#pragma unroll
    for (int off = 16; off; off >>= 1) {
        s0 += __shfl_xor_sync(0xffffffffu, s0, off);
        s1 += __shfl_xor_sync(0xffffffffu, s1, off);
        s2 += __shfl_xor_sync(0xffffffffu, s2, off);
    }
    __shared__ float red[4][3][2];
    int g = threadIdx.x >> 6, hw = (c >> 5);
    if ((c & 31) == 0) { red[g][0][hw] = s0; red[g][1][hw] = s1; red[g][2][hw] = s2; }
    __syncthreads();
    float sc0 = rsqrtf((red[g][0][0]+red[g][0][1]) * (1.f/64.f)  + 1e-6f);
    float sc1 = rsqrtf((red[g][1][0]+red[g][1][1]) * (1.f/192.f) + 1e-6f);
    float sc2 = rsqrtf((red[g][2][0]+red[g][2][1]) * (1.f/320.f) + 1e-6f);
    float* q = dst + (size_t)n*576 + c;
    q[0] = v[0]*sc0;
#pragma unroll
    for (int k = 1; k < 4; k++) q[k*64] = v[k]*sc1;
#pragma unroll
    for (int k = 4; k < 9; k++) q[k*64] = v[k]*sc2;
}

// ---------------- xjp: 80000 rows x 128, K=64 ----------------
#define XJ_GRID 1250
__global__ void __launch_bounds__(256) xjp_mma()
{
    extern __shared__ uint32_t sm[];
    uint32_t* Xs = sm;            // 2304
    uint32_t* Ws = sm + 2304;     // 4608
    int rbase = blockIdx.x * 64;
    int t = threadIdx.x, lane = t & 31, w = t >> 5, mg = w & 1, ng = w >> 1;
    cp_chunk<1152,256>(Ws, g_Wxjc, t);
    {
        int r = t >> 2, q = t & 3;
        int gr = rbase + r;
        int node = gr >> 3, slot = 1 + (gr & 7);
        const float4* yp = (const float4*)&g_xn[(size_t)node*576 + slot*64 + q*16];
        uint32_t* col = Xs + r*36 + q*8;
#pragma unroll
        for (int i = 0; i < 4; i++) {
            float4 v = yp[i];
            *(uint2*)(col + i*2) = make_uint2(f2bf2(v.x, v.y), f2bf2(v.z, v.w));
        }
    }
    CP_WAIT0();
    __syncthreads();
    float acc[8][4] = {};
    gemm_mma<36,36,4>(Ws, Xs, lane, mg, ng, acc);
    int nbase = ng*32 + (lane&3)*2;
    int ebase = mg*32 + (lane>>2);
#pragma unroll
    for (int mt = 0; mt < 2; mt++)
#pragma unroll
    for (int hf = 0; hf < 2; hf++) {
        int gr = rbase + ebase + mt*16 + hf*8;
        int node = gr >> 3, slot = gr & 7;
        size_t ob = (size_t)node*1024 + (size_t)slot*128;
#pragma unroll
        for (int nt = 0; nt < 4; nt++) {
            int n = nbase + nt*8;
            *(float2*)&g_xjp[ob + n] =
                make_float2(acc[mt*4+nt][hf*2+0], acc[mt*4+nt][hf*2+1]);
        }
    }
}

// ---------------- gate: 10000 rows x 128, K=64 ----------------
#define GATE_GRID 157
__global__ void __launch_bounds__(256) gate_mma(const float* __restrict__ bg)
{
    extern __shared__ uint32_t sm[];
    uint32_t* Xs = sm;
    uint32_t* Ws = sm + 2304;
    int rbase = blockIdx.x * 64;
    int t = threadIdx.x, lane = t & 31, w = t >> 5, mg = w & 1, ng = w >> 1;
    cp_chunk<1152,256>(Ws, g_Wgc, t);
    {
        int r = t >> 2, q = t & 3;
        int node = rbase + r;
        uint32_t* col = Xs + r*36 + q*8;
        if (node < NN) {
            const float4* yp = (const float4*)&g_yn[(size_t)node*576 + q*16];
#pragma unroll
            for (int i = 0; i < 4; i++) {
                float4 v = yp[i];
                *(uint2*)(col + i*2) = make_uint2(f2bf2(v.x, v.y), f2bf2(v.z, v.w));
            }
        } else {
#pragma unroll
            for (int i = 0; i < 4; i++) *(uint2*)(col + i*2) = make_uint2(0,0);
        }
    }
    CP_WAIT0();
    __syncthreads();
    float acc[8][4] = {};
    gemm_mma<36,36,4>(Ws, Xs, lane, mg, ng, acc);
    int nbase = ng*32 + (lane&3)*2;
    int ebase = mg*32 + (lane>>2);
#pragma unroll
    for (int mt = 0; mt < 2; mt++)
#pragma unroll
    for (int hf = 0; hf < 2; hf++) {
        int node = rbase + ebase + mt*16 + hf*8;
        if (node >= NN) continue;
        size_t ob = (size_t)node*128;
#pragma unroll
        for (int nt = 0; nt < 4; nt++) {
            int n = nbase + nt*8;
            float z0 = acc[mt*4+nt][hf*2+0] + bg[n];
            float z1 = acc[mt*4+nt][hf*2+1] + bg[n+1];
            float s0 = sigm(z0), s1 = sigm(z1);
            *(float2*)&g_gsil[ob + n] = make_float2(z0*s0, z1*s1);
            *(float2*)&g_gsig[ob + n] = make_float2(s0, s1);
        }
    }
}

// ---------------- radial MLP: 128 edges/block, 8-half triple-buffered pipeline ----------------
__global__ void __launch_bounds__(512,2) rad_kernel(
    const float* __restrict__ edist, const float* __restrict__ semb,
    const float* __restrict__ temb,  const float* __restrict__ b1,
    const float* __restrict__ b2,    const int* __restrict__ anum,
    const int* __restrict__ eidx)
{
    extern __shared__ uint32_t sm[];
    uint32_t* ef = sm;            // 8704
    uint32_t* Ws = sm + 8704;     // 3 x 4608 = 13824
    int* zsrc = (int*)(sm + 22528);
    int* ztgt = zsrc + 128;
    int e0 = blockIdx.x * 128, t = threadIdx.x;
    int lane = t & 31, w = t >> 5, mg = w & 3, ng = w >> 2;
    auto hsrc = [](int m) { return m < 2 ? g_W1c + m*4608 : g_W2c + (m-2)*4608; };
    cp_chunk<1152,512>(Ws,        hsrc(0), t);
    cp_chunk<1152,512>(Ws + 4608, hsrc(1), t);
    if (t < 128)      zsrc[t]     = anum[eidx[e0 + t]];
    else if (t < 256) ztgt[t-128] = anum[eidx[NE + e0 + t - 128]];
    __syncthreads();   // zsrc/ztgt visible
    {
        int e = t >> 2, q = t & 3;
        const float4* xp;
        if (q < 2)      xp = (const float4*)&edist[(size_t)(e0+e)*64 + q*32];
        else if (q==2)  xp = (const float4*)&semb[(size_t)zsrc[e]*32];
        else            xp = (const float4*)&temb[(size_t)ztgt[e]*32];
        uint32_t* col = ef + e*68 + q*16;
#pragma unroll
        for (int i4 = 0; i4 < 8; i4++) {
            float4 v = xp[i4];
            *(uint2*)(col + i4*2) = make_uint2(f2bf2(v.x, v.y), f2bf2(v.z, v.w));
        }
    }
    int nbase = ng*32 + (lane&3)*2;
    int ebase = mg*32 + (lane>>2);
    int m = 0, mb = 0;
    {   // layer 1: halves 0,1
        float acc[8][4] = {};
        for (int s = 0; s < 2; s++, m++) {
            if (m + 1 < 8) CP_WAIT1(); else CP_WAIT0();
            __syncthreads();
            gemm_mma<68,36,4>(Ws + mb*4608, ef + s*32, lane, mg, ng, acc);
            if (m + 2 < 8) {
                int nb = mb + 2; if (nb >= 3) nb -= 3;
                cp_chunk<1152,512>(Ws + nb*4608, hsrc(m+2), t);
            }
            if (++mb == 3) mb = 0;
        }
        __syncthreads();   // all layer-1 reads of ef done before overwrite
#pragma unroll
        for (int nt = 0; nt < 4; nt++) {
            int n = nbase + nt*8;
            float2 bb = *(const float2*)&b1[n];
#pragma unroll
            for (int mt = 0; mt < 2; mt++)
#pragma unroll
            for (int hf = 0; hf < 2; hf++) {
                int el = ebase + mt*16 + hf*8;
                float z0 = acc[mt*4+nt][hf*2+0] + bb.x;
                float z1 = acc[mt*4+nt][hf*2+1] + bb.y;
                ef[el*68 + (n>>1)] = f2bf2(z0*sigm(z0), z1*sigm(z1));
            }
        }
    }
    for (int j = 0; j < 3; j++) {
        float acc[8][4] = {};
        for (int s = 0; s < 2; s++, m++) {
            if (m + 1 < 8) CP_WAIT1(); else CP_WAIT0();
            __syncthreads();
            gemm_mma<68,36,4>(Ws + mb*4608, ef + s*32, lane, mg, ng, acc);
            if (m + 2 < 8) {
                int nb = mb + 2; if (nb >= 3) nb -= 3;
                cp_chunk<1152,512>(Ws + nb*4608, hsrc(m+2), t);
            }
            if (++mb == 3) mb = 0;
        }
#pragma unroll
        for (int nt = 0; nt < 4; nt++) {
            int n = nbase + nt*8;
            float2 bb = *(const float2*)&b2[j*128 + n];
#pragma unroll
            for (int mt = 0; mt < 2; mt++)
#pragma unroll
            for (int hf = 0; hf < 2; hf++) {
                int el = ebase + mt*16 + hf*8;
                *(float2*)&g_rad[(size_t)(e0+el)*384 + j*128 + n] =
                    make_float2(acc[mt*4+nt][hf*2+0] + bb.x, acc[mt*4+nt][hf*2+1] + bb.y);
            }
        }
    }
}

// ---------------- extra: 14-half triple-buffered pipeline ----------------
__global__ void __launch_bounds__(512,2) extra_kernel(
    const float* __restrict__ lng, const float* __restrict__ lnb,
    const float* __restrict__ adot, const int* __restrict__ eidx)
{
    extern __shared__ uint32_t sm[];
    uint32_t* Xs = sm;            // 8704
    uint32_t* Ws = sm + 8704;     // 13824
    int* src_s = (int*)(sm + 22528);
    int* tgt_s = src_s + 128;
    int e0 = blockIdx.x * 128, t = threadIdx.x;
    int lane = t & 31, w = t >> 5, mg = w & 3, ng = w >> 2;
    cp_chunk<1152,512>(Ws,        g_Wm0c,        t);
    cp_chunk<1152,512>(Ws + 4608, g_Wm0c + 4608, t);
    if (t < 128)      src_s[t]     = eidx[e0 + t];
    else if (t < 256) tgt_s[t-128] = eidx[NE + e0 + t - 128];
    __syncthreads();
    {
        int e = t >> 2, q = t & 3;
        const float4* rp = (const float4*)&g_rad[(size_t)(e0+e)*384 + q*32];
        const float4* xp = (q < 2)
            ? (const float4*)&g_xn[(size_t)src_s[e]*576 + q*32]
            : (const float4*)&g_xn[(size_t)tgt_s[e]*576 + (q-2)*32];
        uint32_t* col = Xs + e*68 + q*16;
#pragma unroll
        for (int i4 = 0; i4 < 8; i4++) {
            float4 xv = xp[i4], rv = rp[i4];
            *(uint2*)(col + i4*2) =
                make_uint2(f2bf2(xv.x*rv.x, xv.y*rv.y), f2bf2(xv.z*rv.z, xv.w*rv.w));
        }
    }
    int nbase = ng*32 + (lane&3)*2;
    int ebase = mg*32 + (lane>>2);
    int m = 0, mb = 0;
    for (int oc = 0; oc < 7; oc++) {
        float acc[8][4] = {};
        for (int s = 0; s < 2; s++, m++) {
            if (m + 1 < 14) CP_WAIT1(); else CP_WAIT0();
            __syncthreads();
            gemm_mma<68,36,4>(Ws + mb*4608, Xs + s*32, lane, mg, ng, acc);
            if (m + 2 < 14) {
                int nb = mb + 2; if (nb >= 3) nb -= 3;
                cp_chunk<1152,512>(Ws + nb*4608, g_Wm0c + (m+2)*4608, t);
            }
            if (++mb == 3) mb = 0;
        }
        if (oc < 2) {
            int h = oc*4 + ng;
#pragma unroll
            for (int mt = 0; mt < 2; mt++)
#pragma unroll
            for (int hf = 0; hf < 2; hf++) {
                int el = ebase + mt*16 + hf*8;
                float sum = 0.f, ssq = 0.f;
#pragma unroll
                for (int nt = 0; nt < 4; nt++) {
                    float v0 = acc[mt*4+nt][hf*2+0], v1 = acc[mt*4+nt][hf*2+1];
                    sum += v0 + v1; ssq += v0*v0 + v1*v1;
                }
                sum += __shfl_xor_sync(0xffffffffu, sum, 1);
                sum += __shfl_xor_sync(0xffffffffu, sum, 2);
                ssq += __shfl_xor_sync(0xffffffffu, ssq, 1);
                ssq += __shfl_xor_sync(0xffffffffu, ssq, 2);
                float mean = sum * (1.f/32.f);
                float rs = rsqrtf(ssq * (1.f/32.f) - mean*mean + 1e-5f);
                float logit = 0.f;
#pragma unroll
                for (int nt = 0; nt < 4; nt++) {
                    int a = nt*8 + (lane&3)*2;
#pragma unroll
                    for (int jj = 0; jj < 2; jj++) {
                        float v = acc[mt*4+nt][hf*2+jj];
                        float an = (v - mean)*rs*lng[a+jj] + lnb[a+jj];
                        logit += (0.2f*an + 0.8f*an*sigm(an)) * adot[h*32 + a + jj];
                    }
                }
                logit += __shfl_xor_sync(0xffffffffu, logit, 1);
                logit += __shfl_xor_sync(0xffffffffu, logit, 2);
                if ((lane & 3) == 0) {
                    float ex = __expf(logit);
                    g_e[(size_t)(e0+el)*8 + h] = ex;
                    atomicAdd(&g_den[(size_t)tgt_s[el]*8 + h], ex);
                }
            }
        } else if (oc == 2) {
#pragma unroll
            for (int nt = 0; nt < 4; nt++) {
                int n = nbase + nt*8;
#pragma unroll
                for (int mt = 0; mt < 2; mt++)
#pragma unroll
                for (int hf = 0; hf < 2; hf++) {
                    int el = ebase + mt*16 + hf*8;
                    float z0 = acc[mt*4+nt][hf*2+0], z1 = acc[mt*4+nt][hf*2+1];
                    *(float2*)&g_val0[(size_t)(e0+el)*128 + n] =
                        make_float2(z0*sigm(z0), z1*sigm(z1));
                }
            }
        } else {
            int which = oc - 3;
            float* base = (which < 2) ? g_gdir : g_gten;
            int l = which & 1;
#pragma unroll
            for (int nt = 0; nt < 4; nt++) {
                int n = nbase + nt*8;
#pragma unroll
                for (int mt = 0; mt < 2; mt++)
#pragma unroll
                for (int hf = 0; hf < 2; hf++) {
                    int el = ebase + mt*16 + hf*8;
                    *(float2*)&base[(size_t)(e0+el)*256 + l*128 + n] =
                        make_float2(sigm(acc[mt*4+nt][hf*2+0]), sigm(acc[mt*4+nt][hf*2+1]));
                }
            }
        }
    }
}

// ---------------- fused conv1+conv2: resident bf16 weights, 2 blocks/SM ----------------
__global__ void __launch_bounds__(512,2) conv_kernel(
    const float* __restrict__ rl, const int* __restrict__ eidx)
{
    extern __shared__ uint32_t sm[];
    uint32_t* XV  = sm;            // 8704
    uint32_t* W1s = sm + 8704;     // 8704
    uint32_t* W2s = sm + 17408;    // 8704
    float* rl_s = (float*)(sm + 26112);   // 1024
    float* ee_s = (float*)(sm + 27136);   // 1024
    int* src_s = (int*)(sm + 28160);      // 128
    int* tgt_s = (int*)(sm + 28288);      // 128
    int e0 = blockIdx.x * 128, t = threadIdx.x;
    int lane = t & 31, w = t >> 5, mg = w & 3, ng = w >> 2;
    if (t < 128)      src_s[t]     = eidx[e0 + t];
    else if (t < 256) tgt_s[t-128] = eidx[NE + e0 + t - 128];
    for (int i = t; i < 1024; i += 512) {
        rl_s[i] = rl[(size_t)e0*8 + i];
        ee_s[i] = g_e[(size_t)e0*8 + i];
    }
    int nbase = ng*32 + (lane&3)*2;
    int ebase = mg*32 + (lane>>2);
    int se = t >> 2, sq = t & 3;

    for (int deg = 0; deg <= 2; deg++) {
        __syncthreads();
        cp_chunk<2176,512>(W2s, g_Wc2c + deg*8704, t);
        if (deg) cp_chunk<2176,512>(W1s, g_Wc1c + deg*8704, t);
        int kbeg = (deg == 0) ? 0 : ((deg == 1) ? 1 : 4);
        int kend = (deg == 0) ? 1 : ((deg == 1) ? 4 : 9);
        for (int k = kbeg; k < kend; k++) {
            if (deg == 0) {
                const float4* vp = (const float4*)&g_val0[(size_t)(e0+se)*128 + sq*32];
                uint32_t* col = XV + se*68 + sq*16;
#pragma unroll
                for (int i4 = 0; i4 < 8; i4++) {
                    float4 v = vp[i4];
                    *(uint2*)(col + i4*2) = make_uint2(f2bf2(v.x, v.y), f2bf2(v.z, v.w));
                }
            } else {
                const float4* rp = (const float4*)&g_rad[(size_t)(e0+se)*384 + deg*128 + sq*32];
                const float4* xp = (sq < 2)
                    ? (const float4*)&g_xn[(size_t)src_s[se]*576 + k*64 + sq*32]
                    : (const float4*)&g_xn[(size_t)tgt_s[se]*576 + k*64 + (sq-2)*32];
                uint32_t* col = XV + se*68 + sq*16;
#pragma unroll
                for (int i4 = 0; i4 < 8; i4++) {
                    float4 xv = xp[i4], rv = rp[i4];
                    *(uint2*)(col + i4*2) =
                        make_uint2(f2bf2(xv.x*rv.x, xv.y*rv.y), f2bf2(xv.z*rv.z, xv.w*rv.w));
                }
            }
            if (k == kbeg) CP_WAIT0();
            __syncthreads();
            if (deg) {
                float acc[8][4] = {};
                gemm_mma<68,68,8>(W1s, XV, lane, mg, ng, acc);
                int l = (k < 4) ? 0 : 1;
#pragma unroll
                for (int mt = 0; mt < 2; mt++)
#pragma unroll
                for (int hf = 0; hf < 2; hf++) {
                    int el = ebase + mt*16 + hf*8;
                    size_t ge = (size_t)(e0 + el);
                    float r = rl_s[el*8 + (k-1)];
                    size_t gb = ge*256 + l*128;
                    size_t xb = (size_t)src_s[el]*1024 + (size_t)(k-1)*128;
#pragma unroll
                    for (int nt = 0; nt < 4; nt++) {
                        int n = nbase + nt*8;
                        float2 gd = *(const float2*)&g_gdir[gb + n];
                        float2 gt = *(const float2*)&g_gten[gb + n];
                        float2 xj = *(const float2*)&g_xjp[xb + n];
                        acc[mt*4+nt][hf*2+0] += r*gd.x + xj.x*gt.x;
                        acc[mt*4+nt][hf*2+1] += r*gd.y + xj.y*gt.y;
                    }
                }
                __syncthreads();
#pragma unroll
                for (int mt = 0; mt < 2; mt++)
#pragma unroll
                for (int hf = 0; hf < 2; hf++) {
                    int el = ebase + mt*16 + hf*8;
#pragma unroll
                    for (int nt = 0; nt < 4; nt++) {
                        int n = nbase + nt*8;
                        XV[el*68 + (n>>1)] =
                            f2bf2(acc[mt*4+nt][hf*2+0], acc[mt*4+nt][hf*2+1]);
                    }
                }
                __syncthreads();
            }
            float acc[8][4] = {};
            gemm_mma<68,68,8>(W2s, XV, lane, mg, ng, acc);
#pragma unroll
            for (int mt = 0; mt < 2; mt++)
#pragma unroll
            for (int hf = 0; hf < 2; hf++) {
                int el = ebase + mt*16 + hf*8;
                size_t nb = (size_t)tgt_s[el]*1152 + (size_t)k*128;
#pragma unroll
                for (int nt = 0; nt < 4; nt++) {
                    int n = nbase + nt*8;
                    float s = ee_s[el*8 + (n >> 4)];
                    red2(&g_num[nb + n], acc[mt*4+nt][hf*2+0]*s, acc[mt*4+nt][hf*2+1]*s);
                }
            }
            __syncthreads();
        }
    }
}

// ---------------- node GEMMs ----------------
#define P_T0 79
#define P_T1 314
#define P_GRID 705
__device__ __forceinline__ void node_row(int b, int* deg, int* rbase,
                                         int* nslots, int* soff, int* nrows)
{
    if (b < P_T0)      { *deg=0; *rbase=b*128;          *nslots=1; *soff=0; *nrows=10000; }
    else if (b < P_T1) { *deg=1; *rbase=(b-P_T0)*128;   *nslots=3; *soff=1; *nrows=30000; }
    else               { *deg=2; *rbase=(b-P_T1)*128;   *nslots=5; *soff=4; *nrows=50000; }
}

__global__ void __launch_bounds__(256,2) proj_mma(
    const float* __restrict__ x, const float* __restrict__ bp)
{
    extern __shared__ uint32_t sm[];
    uint32_t* Xs = sm;            // 8704
    uint32_t* Ws = sm + 8704;     // 4352
    int deg, rbase, nslots, soff, nrows;
    node_row(blockIdx.x, &deg, &rbase, &nslots, &soff, &nrows);
    int t = threadIdx.x, lane = t & 31, w = t >> 5, mg = w & 3, ng = w >> 2;
    cp_chunk<1088,256>(Ws, g_Wpc + deg*4352, t);
    {
        int r = t >> 1, h2 = t & 1;
        int gr = rbase + r;
        uint32_t* col = Xs + r*68 + h2*32;
        if (gr < nrows) {
            int node = gr / nslots, slot = soff + gr % nslots;
            const float4* np = (const float4*)&g_num[(size_t)node*1152 + slot*128 + h2*64];
            float di[4];
#pragma unroll
            for (int q = 0; q < 4; q++) di[q] = 1.f / (g_den[node*8 + h2*4 + q] + 1e-30f);
#pragma unroll
            for (int i = 0; i < 16; i++) {
                float4 v = np[i]; float d = di[i>>2];
                *(uint2*)(col + i*2) = make_uint2(f2bf2(v.x*d, v.y*d), f2bf2(v.z*d, v.w*d));
            }
        } else {
#pragma unroll
            for (int i = 0; i < 16; i++) *(uint2*)(col + i*2) = make_uint2(0,0);
        }
    }
    CP_WAIT0();
    __syncthreads();
    float acc[8][4] = {};
    gemm_mma<68,68,8>(Ws, Xs, lane, mg, ng, acc);
    int nbase = ng*32 + (lane&3)*2;
    int ebase = mg*32 + (lane>>2);
#pragma unroll
    for (int mt = 0; mt < 2; mt++)
#pragma unroll
    for (int hf = 0; hf < 2; hf++) {
        int gr = rbase + ebase + mt*16 + hf*8;
        if (gr >= nrows) continue;
        int node = gr / nslots, slot = soff + gr % nslots;
        size_t ob = (size_t)node*576 + slot*64;
#pragma unroll
        for (int nt = 0; nt < 4; nt++) {
            int n = nbase + nt*8;
            float b0 = (slot == 0) ? bp[n] : 0.f, b1 = (slot == 0) ? bp[n+1] : 0.f;
            *(float2*)&g_x1[ob + n] = make_float2(
                x[ob + n]   + acc[mt*4+nt][hf*2+0] + b0,
                x[ob + n+1] + acc[mt*4+nt][hf*2+1] + b1);
        }
    }
}

__global__ void __launch_bounds__(256,2) ffn2_mma(
    const float* __restrict__ bf2, float* __restrict__ out)
{
    extern __shared__ uint32_t sm[];
    uint32_t* Xs = sm;
    uint32_t* Ws = sm + 8704;
    int deg, rbase, nslots, soff, nrows;
    node_row(blockIdx.x, &deg, &rbase, &nslots, &soff, &nrows);
    int t = threadIdx.x, lane = t & 31, w = t >> 5, mg = w & 3, ng = w >> 2;
    cp_chunk<1088,256>(Ws, g_Wf2c + deg*4352, t);
    {
        int r = t >> 1, h2 = t & 1;
        int gr = rbase + r;
        uint32_t* col = Xs + r*68 + h2*32;
        if (gr < nrows) {
            int node = gr / nslots, slot = soff + gr % nslots;
            const float4* hp = (slot == 0)
                ? (const float4*)&g_gsil[(size_t)node*128 + h2*64]
                : (const float4*)&g_h[(size_t)node*1024 + (size_t)(slot-1)*128 + h2*64];
#pragma unroll
            for (int i = 0; i < 16; i++) {
                float4 v = hp[i];
                *(uint2*)(col + i*2) = make_uint2(f2bf2(v.x, v.y), f2bf2(v.z, v.w));
            }
        } else {
#pragma unroll
            for (int i = 0; i < 16; i++) *(uint2*)(col + i*2) = make_uint2(0,0);
        }
    }
    CP_WAIT0();
    __syncthreads();
    float acc[8][4] = {};
    gemm_mma<68,68,8>(Ws, Xs, lane, mg, ng, acc);
    int nbase = ng*32 + (lane&3)*2;
    int ebase = mg*32 + (lane>>2);
#pragma unroll
    for (int mt = 0; mt < 2; mt++)
#pragma unroll
    for (int hf = 0; hf < 2; hf++) {
        int gr = rbase + ebase + mt*16 + hf*8;
        if (gr >= nrows) continue;
        int node = gr / nslots, slot = soff + gr % nslots;
        size_t ob = (size_t)node*576 + slot*64;
#pragma unroll
        for (int nt = 0; nt < 4; nt++) {
            int n = nbase + nt*8;
            float b0 = (slot == 0) ? bf2[n] : 0.f, b1 = (slot == 0) ? bf2[n+1] : 0.f;
            *(float2*)&out[ob + n] = make_float2(
                g_x1[ob + n]   + acc[mt*4+nt][hf*2+0] + b0,
                g_x1[ob + n+1] + acc[mt*4+nt][hf*2+1] + b1);
        }
    }
}

#define F_T1 469
#define F_GRID 1251
__global__ void __launch_bounds__(256) ffn1_mma()
{
    extern __shared__ uint32_t sm[];
    uint32_t* Xs = sm;            // 2304
    uint32_t* Ws = sm + 2304;     // 4608
    int b = blockIdx.x, deg, rbase, nslots, soff, nrows;
    if (b < F_T1) { deg=1; rbase=b*64;         nslots=3; soff=1; nrows=30000; }
    else          { deg=2; rbase=(b-F_T1)*64;  nslots=5; soff=4; nrows=50000; }
    int t = threadIdx.x, lane = t & 31, w = t >> 5, mg = w & 1, ng = w >> 1;
    cp_chunk<1152,256>(Ws, g_Wf1c + deg*4608, t);
    {
        int r = t >> 2, q = t & 3;
        int gr = rbase + r;
        uint32_t* col = Xs + r*36 + q*8;
        if (gr < nrows) {
            int node = gr / nslots, slot = soff + gr % nslots;
            const float4* yp = (const float4*)&g_yn[(size_t)node*576 + slot*64 + q*16];
#pragma unroll
            for (int i = 0; i < 4; i++) {
                float4 v = yp[i];
                *(uint2*)(col + i*2) = make_uint2(f2bf2(v.x, v.y), f2bf2(v.z, v.w));
            }
        } else {
#pragma unroll
            for (int i = 0; i < 4; i++) *(uint2*)(col + i*2) = make_uint2(0,0);
        }
    }
    CP_WAIT0();
    __syncthreads();
    float acc[8][4] = {};
    gemm_mma<36,36,4>(Ws, Xs, lane, mg, ng, acc);
    int nbase = ng*32 + (lane&3)*2;
    int ebase = mg*32 + (lane>>2);
#pragma unroll
    for (int mt = 0; mt < 2; mt++)
#pragma unroll
    for (int hf = 0; hf < 2; hf++) {
        int gr = rbase + ebase + mt*16 + hf*8;
        if (gr >= nrows) continue;
        int node = gr / nslots, slot = soff + gr % nslots;
        size_t hb = (size_t)node*1024 + (size_t)(slot-1)*128;
        size_t gsb = (size_t)node*128;
#pragma unroll
        for (int nt = 0; nt < 4; nt++) {
            int n = nbase + nt*8;
            float2 gs = *(const float2*)&g_gsig[gsb + n];
            *(float2*)&g_h[hb + n] = make_float2(
                acc[mt*4+nt][hf*2+0]*gs.x, acc[mt*4+nt][hf*2+1]*gs.y);
        }
    }
}

// ---------------- launch ----------------
extern "C" void kernel_launch(void* const* d_in, const int* in_sizes, int n_in,
                              void* d_out, int out_size)
{
    const float* x     = (const float*)d_in[0];
    const float* edist = (const float*)d_in[1];
    const float* rl    = (const float*)d_in[2];
    const float* semb  = (const float*)d_in[3];
    const float* temb  = (const float*)d_in[4];
    const float* W1    = (const float*)d_in[5];
    const float* b1    = (const float*)d_in[6];
    const float* W2    = (const float*)d_in[7];
    const float* b2    = (const float*)d_in[8];
    const float* Wc1   = (const float*)d_in[9];
    const float* Wm0   = (const float*)d_in[10];
    const float* lng   = (const float*)d_in[11];
    const float* lnb   = (const float*)d_in[12];
    const float* adot  = (const float*)d_in[13];
    const float* Wxj   = (const float*)d_in[14];
    const float* Wc2   = (const float*)d_in[15];
    const float* Wp    = (const float*)d_in[16];
    const float* bp    = (const float*)d_in[17];
    const float* Wg    = (const float*)d_in[18];
    const float* bg    = (const float*)d_in[19];
    const float* Wf1   = (const float*)d_in[20];
    const float* Wf2   = (const float*)d_in[22];
    const float* bf2   = (const float*)d_in[23];
    const int*   anum  = (const int*)d_in[24];
    const int*   eidx  = (const int*)d_in[25];
    float* out = (float*)d_out;

    float *p_xn, *p_x1, *p_yn;
    cudaGetSymbolAddress((void**)&p_xn, g_xn);
    cudaGetSymbolAddress((void**)&p_x1, g_x1);
    cudaGetSymbolAddress((void**)&p_yn, g_yn);

    static bool attr_set = false;
    if (!attr_set) {
        cudaFuncSetAttribute(rad_kernel,   cudaFuncAttributeMaxDynamicSharedMemorySize, 91136);
        cudaFuncSetAttribute(extra_kernel, cudaFuncAttributeMaxDynamicSharedMemorySize, 91136);
        cudaFuncSetAttribute(conv_kernel,  cudaFuncAttributeMaxDynamicSharedMemorySize, 113664);
        cudaFuncSetAttribute(proj_mma,     cudaFuncAttributeMaxDynamicSharedMemorySize, 52224);
        cudaFuncSetAttribute(ffn2_mma,     cudaFuncAttributeMaxDynamicSharedMemorySize, 52224);
        cudaFuncSetAttribute(ffn1_mma,     cudaFuncAttributeMaxDynamicSharedMemorySize, 27648);
        cudaFuncSetAttribute(xjp_mma,      cudaFuncAttributeMaxDynamicSharedMemorySize, 27648);
        cudaFuncSetAttribute(gate_mma,     cudaFuncAttributeMaxDynamicSharedMemorySize, 27648);
        attr_set = true;
    }

    wconv_kernel<<<(WCONV_N + 255)/256, 256>>>(W1, W2, Wm0, Wc1, Wc2, Wp, Wf1, Wf2, Wxj, Wg);
    zero_kernel<<<(NN*1152/4 + 255)/256, 256>>>();
    enorm_kernel<<<NN/4, 256>>>(x, p_xn);
    xjp_mma<<<XJ_GRID, 256, 27648>>>();
    rad_kernel<<<NE/128, 512, 91136>>>(edist, semb, temb, b1, b2, anum, eidx);
    extra_kernel<<<NE/128, 512, 91136>>>(lng, lnb, adot, eidx);
    conv_kernel<<<NE/128, 512, 113664>>>(rl, eidx);
    proj_mma<<<P_GRID, 256, 52224>>>(x, bp);
    enorm_kernel<<<NN/4, 256>>>(p_x1, p_yn);
    gate_mma<<<GATE_GRID, 256, 27648>>>(bg);
    ffn1_mma<<<F_GRID, 256, 27648>>>();
    ffn2_mma<<<P_GRID, 256, 52224>>>(bf2, out);
}

// round 16
// speedup vs baseline: 1.4597x; 1.1126x over previous
#include <cuda_runtime.h>
#include <cstdint>

#define NN 10000
#define NE 80000

__device__ float g_xn  [NN*576];
__device__ float g_rad [NE*384];
__device__ uint32_t g_val0b[NE*64];    // bf16x2 pairs
__device__ uint32_t g_gdirb[NE*128];   // bf16x2 pairs (l,n/2)
__device__ uint32_t g_gtenb[NE*128];
__device__ float g_e   [NE*8];
__device__ uint32_t g_xjpb[NN*512];    // bf16x2 pairs
__device__ float g_num [NN*1152];
__device__ float g_den [NN*8];
__device__ float g_x1  [NN*576];
__device__ float g_yn  [NN*576];
__device__ float g_h   [NN*1024];
__device__ float g_gsil[NN*128];
__device__ float g_gsig[NN*128];

// bf16-pair weights, row-major [n][k2] images (ldmatrix-ready)
__device__ __align__(16) uint32_t g_W1c [9216];
__device__ __align__(16) uint32_t g_W2c [27648];
__device__ __align__(16) uint32_t g_Wm0c[64512];
__device__ __align__(16) uint32_t g_Wc1c[26112];
__device__ __align__(16) uint32_t g_Wc2c[26112];
__device__ __align__(16) uint32_t g_Wpc [13056];
__device__ __align__(16) uint32_t g_Wf1c[13824];
__device__ __align__(16) uint32_t g_Wf2c[13056];
__device__ __align__(16) uint32_t g_Wxjc[4608];
__device__ __align__(16) uint32_t g_Wgc [4608];

__device__ __forceinline__ float sigm(float z) { return 1.f / (1.f + __expf(-z)); }

__device__ __forceinline__ uint32_t f2bf2(float lo, float hi) {
    uint32_t r; asm("cvt.rn.bf16x2.f32 %0, %1, %2;" : "=r"(r) : "f"(hi), "f"(lo)); return r;
}
__device__ __forceinline__ float2 ubf2(uint32_t w) {
    return make_float2(__uint_as_float(w << 16), __uint_as_float(w & 0xffff0000u));
}
__device__ __forceinline__ void red2(float* p, float a, float b) {
    asm volatile("red.global.add.v2.f32 [%0], {%1,%2};" :: "l"(p), "f"(a), "f"(b) : "memory");
}
__device__ __forceinline__ void mma16(float* d, uint32_t a0,uint32_t a1,uint32_t a2,uint32_t a3,
                                      uint32_t b0,uint32_t b1) {
    asm volatile("mma.sync.aligned.m16n8k16.row.col.f32.bf16.bf16.f32 "
                 "{%0,%1,%2,%3},{%4,%5,%6,%7},{%8,%9},{%0,%1,%2,%3};"
                 : "+f"(d[0]),"+f"(d[1]),"+f"(d[2]),"+f"(d[3])
                 : "r"(a0),"r"(a1),"r"(a2),"r"(a3),"r"(b0),"r"(b1));
}
__device__ __forceinline__ uint32_t s2u(const uint32_t* p) {
    return (uint32_t)__cvta_generic_to_shared(p);
}
#define LDSM4(r0,r1,r2,r3,addr) \
    asm volatile("ldmatrix.sync.aligned.m8n8.x4.shared.b16 {%0,%1,%2,%3}, [%4];" \
        : "=r"(r0),"=r"(r1),"=r"(r2),"=r"(r3) : "r"(addr))

__device__ __forceinline__ void cp16(uint32_t saddr, const uint32_t* src) {
    asm volatile("cp.async.cg.shared.global [%0], [%1], 16;" :: "r"(saddr), "l"(src));
}
#define CP_COMMIT() asm volatile("cp.async.commit_group;" ::: "memory")
#define CP_WAIT0()  asm volatile("cp.async.wait_group 0;" ::: "memory")
#define CP_WAIT1()  asm volatile("cp.async.wait_group 1;" ::: "memory")

template<int N4, int NT>
__device__ __forceinline__ void cp_chunk(uint32_t* dst, const uint32_t* __restrict__ src, int t) {
    uint32_t d = (uint32_t)__cvta_generic_to_shared(dst);
    for (int i = t; i < N4; i += NT) cp16(d + i*16, src + i*4);
    CP_COMMIT();
}

// Warp tile 32 rows x 32 cols, bf16 k16, ldmatrix fragment loads.
template<int XST, int WST, int NK>
__device__ __forceinline__ void gemm_mma(const uint32_t* __restrict__ Ws,
                                         const uint32_t* __restrict__ Xs,
                                         int lane, int mg, int ng, float acc[8][4])
{
    int aro = ((lane>>3)&1)*8 + (lane&7);
    int awo = (lane>>4)*4;
    uint32_t aa0 = s2u(Xs + (mg*32 + aro)*XST + awo);
    uint32_t aa1 = aa0 + 16*XST*4;
    int bro = (lane&7) + (lane>>4)*8;
    int bwo = ((lane>>3)&1)*4;
    uint32_t ba0 = s2u(Ws + (ng*32 + bro)*WST + bwo);
    uint32_t ba1 = ba0 + 16*WST*4;
#pragma unroll
    for (int kk = 0; kk < NK; kk++) {
        uint32_t a0,a1,a2,a3, c0,c1,c2,c3, p0,p1,p2,p3, q0,q1,q2,q3;
        LDSM4(a0,a1,a2,a3, aa0 + kk*32);
        LDSM4(c0,c1,c2,c3, aa1 + kk*32);
        LDSM4(p0,p1,p2,p3, ba0 + kk*32);
        LDSM4(q0,q1,q2,q3, ba1 + kk*32);
        mma16(acc[0], a0,a1,a2,a3, p0,p1);
        mma16(acc[1], a0,a1,a2,a3, p2,p3);
        mma16(acc[2], a0,a1,a2,a3, q0,q1);
        mma16(acc[3], a0,a1,a2,a3, q2,q3);
        mma16(acc[4], c0,c1,c2,c3, p0,p1);
        mma16(acc[5], c0,c1,c2,c3, p2,p3);
        mma16(acc[6], c0,c1,c2,c3, q0,q1);
        mma16(acc[7], c0,c1,c2,c3, q2,q3);
    }
}

// ---------------- weight pre-conversion ----------------
__global__ void __launch_bounds__(256) wconv_kernel(
    const float* __restrict__ W1, const float* __restrict__ W2,
    const float* __restrict__ Wm0, const float* __restrict__ Wc1,
    const float* __restrict__ Wc2, const float* __restrict__ Wp,
    const float* __restrict__ Wf1, const float* __restrict__ Wf2,
    const float* __restrict__ Wxj, const float* __restrict__ Wg)
{
    int i = blockIdx.x*256 + threadIdx.x;
    if (i < 8192) { int k2=i>>7, n=i&127;
        g_W1c[(k2>>5)*4608 + n*36 + (k2&31)] =
            f2bf2(W1[2*k2*128+n], W1[(2*k2+1)*128+n]); return; } i -= 8192;
    if (i < 24576) { int j=i/8192, r=i&8191, k2=r>>7, n=r&127;
        g_W2c[(j*2 + (k2>>5))*4608 + n*36 + (k2&31)] =
            f2bf2(W2[2*k2*384 + j*128 + n], W2[(2*k2+1)*384 + j*128 + n]); return; } i -= 24576;
    if (i < 57344){ int j=i/8192, r=i&8191, k2=r>>7, n=r&127;
        g_Wm0c[(j*2 + (k2>>5))*4608 + n*36 + (k2&31)] =
            f2bf2(Wm0[2*k2*896 + j*128 + n], Wm0[(2*k2+1)*896 + j*128 + n]); return; } i -= 57344;
    if (i < 24576) { int d=i>>13, r=i&8191, k2=r>>7, n=r&127;
        g_Wc1c[d*8704 + n*68 + k2] =
            f2bf2(Wc1[d*16384 + 2*k2*128 + n], Wc1[d*16384 + (2*k2+1)*128 + n]); return; } i -= 24576;
    if (i < 24576) { int d=i>>13, r=i&8191, k2=r>>7, n=r&127;
        g_Wc2c[d*8704 + n*68 + k2] =
            f2bf2(Wc2[d*16384 + 2*k2*128 + n], Wc2[d*16384 + (2*k2+1)*128 + n]); return; } i -= 24576;
    if (i < 12288) { int d=i>>12, r=i&4095, k2=r>>6, n=r&63;
        g_Wpc[d*4352 + n*68 + k2] =
            f2bf2(Wp[d*8192 + 2*k2*64 + n], Wp[d*8192 + (2*k2+1)*64 + n]); return; } i -= 12288;
    if (i < 8192) { int d=(i>>12)+1, r=i&4095, k2=r>>7, n=r&127;
        g_Wf1c[d*4608 + n*36 + k2] =
            f2bf2(Wf1[d*8192 + 2*k2*128 + n], Wf1[d*8192 + (2*k2+1)*128 + n]); return; } i -= 8192;
    if (i < 12288) { int d=i>>12, r=i&4095, k2=r>>6, n=r&63;
        g_Wf2c[d*4352 + n*68 + k2] =
            f2bf2(Wf2[d*8192 + 2*k2*64 + n], Wf2[d*8192 + (2*k2+1)*64 + n]); return; } i -= 12288;
    if (i < 4096)  { int k2=i>>7, n=i&127;
        g_Wxjc[n*36 + k2] = f2bf2(Wxj[2*k2*128+n], Wxj[(2*k2+1)*128+n]); return; } i -= 4096;
    if (i < 4096)  { int k2=i>>7, n=i&127;
        g_Wgc[n*36 + k2] = f2bf2(Wg[2*k2*128+n], Wg[(2*k2+1)*128+n]); return; }
}
#define WCONV_N 180224

__global__ void zero_kernel() {
    size_t i = (size_t)blockIdx.x * blockDim.x + threadIdx.x;
    if (i < NN*1152/4) ((float4*)g_num)[i] = make_float4(0.f,0.f,0.f,0.f);
    if (i < NN*8)      g_den[i] = 0.f;
}

// ---------------- enorm ----------------
__global__ void __launch_bounds__(256) enorm_kernel(const float* __restrict__ src, float* __restrict__ dst) {
    int n = blockIdx.x*4 + (threadIdx.x >> 6);
    int c = threadIdx.x & 63;
    const float* p = src + (size_t)n*576 + c;
    float v[9];
#pragma unroll
    for (int k = 0; k < 9; k++) v[k] = p[k*64];
    float s0 = v[0]*v[0];
    float s1 = v[1]*v[1] + v[2]*v[2] + v[3]*v[3];
    float s2 = v[4]*v[4] + v[5]*v[5] + v[6]*v[6] + v[7]*v[7] + v[8]*v[8];
#pragma unroll
    for (int off = 16; off; off >>= 1) {
        s0 += __shfl_xor_sync(0xffffffffu, s0, off);
        s1 += __shfl_xor_sync(0xffffffffu, s1, off);
        s2 += __shfl_xor_sync(0xffffffffu, s2, off);
    }
    __shared__ float red[4][3][2];
    int g = threadIdx.x >> 6, hw = (c >> 5);
    if ((c & 31) == 0) { red[g][0][hw] = s0; red[g][1][hw] = s1; red[g][2][hw] = s2; }
    __syncthreads();
    float sc0 = rsqrtf((red[g][0][0]+red[g][0][1]) * (1.f/64.f)  + 1e-6f);
    float sc1 = rsqrtf((red[g][1][0]+red[g][1][1]) * (1.f/192.f) + 1e-6f);
    float sc2 = rsqrtf((red[g][2][0]+red[g][2][1]) * (1.f/320.f) + 1e-6f);
    float* q = dst + (size_t)n*576 + c;
    q[0] = v[0]*sc0;
#pragma unroll
    for (int k = 1; k < 4; k++) q[k*64] = v[k]*sc1;
#pragma unroll
    for (int k = 4; k < 9; k++) q[k*64] = v[k]*sc2;
}

// ---------------- xjp: 80000 rows x 128, K=64 ----------------
#define XJ_GRID 1250
__global__ void __launch_bounds__(256) xjp_mma()
{
    extern __shared__ uint32_t sm[];
    uint32_t* Xs = sm;            // 2304
    uint32_t* Ws = sm + 2304;     // 4608
    int rbase = blockIdx.x * 64;
    int t = threadIdx.x, lane = t & 31, w = t >> 5, mg = w & 1, ng = w >> 1;
    cp_chunk<1152,256>(Ws, g_Wxjc, t);
    {
        int r = t >> 2, q = t & 3;
        int gr = rbase + r;
        int node = gr >> 3, slot = 1 + (gr & 7);
        const float4* yp = (const float4*)&g_xn[(size_t)node*576 + slot*64 + q*16];
        uint32_t* col = Xs + r*36 + q*8;
#pragma unroll
        for (int i = 0; i < 4; i++) {
            float4 v = yp[i];
            *(uint2*)(col + i*2) = make_uint2(f2bf2(v.x, v.y), f2bf2(v.z, v.w));
        }
    }
    CP_WAIT0();
    __syncthreads();
    float acc[8][4] = {};
    gemm_mma<36,36,4>(Ws, Xs, lane, mg, ng, acc);
    int nbase = ng*32 + (lane&3)*2;
    int ebase = mg*32 + (lane>>2);
#pragma unroll
    for (int mt = 0; mt < 2; mt++)
#pragma unroll
    for (int hf = 0; hf < 2; hf++) {
        int gr = rbase + ebase + mt*16 + hf*8;
        int node = gr >> 3, slot = gr & 7;
        size_t ob = (size_t)node*512 + (size_t)slot*64;
#pragma unroll
        for (int nt = 0; nt < 4; nt++) {
            int n = nbase + nt*8;
            g_xjpb[ob + (n>>1)] = f2bf2(acc[mt*4+nt][hf*2+0], acc[mt*4+nt][hf*2+1]);
        }
    }
}

// ---------------- gate: 10000 rows x 128, K=64 ----------------
#define GATE_GRID 157
__global__ void __launch_bounds__(256) gate_mma(const float* __restrict__ bg)
{
    extern __shared__ uint32_t sm[];
    uint32_t* Xs = sm;
    uint32_t* Ws = sm + 2304;
    int rbase = blockIdx.x * 64;
    int t = threadIdx.x, lane = t & 31, w = t >> 5, mg = w & 1, ng = w >> 1;
    cp_chunk<1152,256>(Ws, g_Wgc, t);
    {
        int r = t >> 2, q = t & 3;
        int node = rbase + r;
        uint32_t* col = Xs + r*36 + q*8;
        if (node < NN) {
            const float4* yp = (const float4*)&g_yn[(size_t)node*576 + q*16];
#pragma unroll
            for (int i = 0; i < 4; i++) {
                float4 v = yp[i];
                *(uint2*)(col + i*2) = make_uint2(f2bf2(v.x, v.y), f2bf2(v.z, v.w));
            }
        } else {
#pragma unroll
            for (int i = 0; i < 4; i++) *(uint2*)(col + i*2) = make_uint2(0,0);
        }
    }
    CP_WAIT0();
    __syncthreads();
    float acc[8][4] = {};
    gemm_mma<36,36,4>(Ws, Xs, lane, mg, ng, acc);
    int nbase = ng*32 + (lane&3)*2;
    int ebase = mg*32 + (lane>>2);
#pragma unroll
    for (int mt = 0; mt < 2; mt++)
#pragma unroll
    for (int hf = 0; hf < 2; hf++) {
        int node = rbase + ebase + mt*16 + hf*8;
        if (node >= NN) continue;
        size_t ob = (size_t)node*128;
#pragma unroll
        for (int nt = 0; nt < 4; nt++) {
            int n = nbase + nt*8;
            float z0 = acc[mt*4+nt][hf*2+0] + bg[n];
            float z1 = acc[mt*4+nt][hf*2+1] + bg[n+1];
            float s0 = sigm(z0), s1 = sigm(z1);
            *(float2*)&g_gsil[ob + n] = make_float2(z0*s0, z1*s1);
            *(float2*)&g_gsig[ob + n] = make_float2(s0, s1);
        }
    }
}

// ---------------- radial MLP: 128 edges/block, 8-half triple-buffered pipeline ----------------
__global__ void __launch_bounds__(512,2) rad_kernel(
    const float* __restrict__ edist, const float* __restrict__ semb,
    const float* __restrict__ temb,  const float* __restrict__ b1,
    const float* __restrict__ b2,    const int* __restrict__ anum,
    const int* __restrict__ eidx)
{
    extern __shared__ uint32_t sm[];
    uint32_t* ef = sm;            // 8704
    uint32_t* Ws = sm + 8704;     // 13824
    int* zsrc = (int*)(sm + 22528);
    int* ztgt = zsrc + 128;
    int e0 = blockIdx.x * 128, t = threadIdx.x;
    int lane = t & 31, w = t >> 5, mg = w & 3, ng = w >> 2;
    auto hsrc = [](int m) { return m < 2 ? g_W1c + m*4608 : g_W2c + (m-2)*4608; };
    cp_chunk<1152,512>(Ws,        hsrc(0), t);
    cp_chunk<1152,512>(Ws + 4608, hsrc(1), t);
    if (t < 128)      zsrc[t]     = anum[eidx[e0 + t]];
    else if (t < 256) ztgt[t-128] = anum[eidx[NE + e0 + t - 128]];
    __syncthreads();
    {
        int e = t >> 2, q = t & 3;
        const float4* xp;
        if (q < 2)      xp = (const float4*)&edist[(size_t)(e0+e)*64 + q*32];
        else if (q==2)  xp = (const float4*)&semb[(size_t)zsrc[e]*32];
        else            xp = (const float4*)&temb[(size_t)ztgt[e]*32];
        uint32_t* col = ef + e*68 + q*16;
#pragma unroll
        for (int i4 = 0; i4 < 8; i4++) {
            float4 v = xp[i4];
            *(uint2*)(col + i4*2) = make_uint2(f2bf2(v.x, v.y), f2bf2(v.z, v.w));
        }
    }
    int nbase = ng*32 + (lane&3)*2;
    int ebase = mg*32 + (lane>>2);
    int m = 0, mb = 0;
    {
        float acc[8][4] = {};
        for (int s = 0; s < 2; s++, m++) {
            if (m + 1 < 8) CP_WAIT1(); else CP_WAIT0();
            __syncthreads();
            gemm_mma<68,36,4>(Ws + mb*4608, ef + s*32, lane, mg, ng, acc);
            if (m + 2 < 8) {
                int nb = mb + 2; if (nb >= 3) nb -= 3;
                cp_chunk<1152,512>(Ws + nb*4608, hsrc(m+2), t);
            }
            if (++mb == 3) mb = 0;
        }
        __syncthreads();
#pragma unroll
        for (int nt = 0; nt < 4; nt++) {
            int n = nbase + nt*8;
            float2 bb = *(const float2*)&b1[n];
#pragma unroll
            for (int mt = 0; mt < 2; mt++)
#pragma unroll
            for (int hf = 0; hf < 2; hf++) {
                int el = ebase + mt*16 + hf*8;
                float z0 = acc[mt*4+nt][hf*2+0] + bb.x;
                float z1 = acc[mt*4+nt][hf*2+1] + bb.y;
                ef[el*68 + (n>>1)] = f2bf2(z0*sigm(z0), z1*sigm(z1));
            }
        }
    }
    for (int j = 0; j < 3; j++) {
        float acc[8][4] = {};
        for (int s = 0; s < 2; s++, m++) {
            if (m + 1 < 8) CP_WAIT1(); else CP_WAIT0();
            __syncthreads();
            gemm_mma<68,36,4>(Ws + mb*4608, ef + s*32, lane, mg, ng, acc);
            if (m + 2 < 8) {
                int nb = mb + 2; if (nb >= 3) nb -= 3;
                cp_chunk<1152,512>(Ws + nb*4608, hsrc(m+2), t);
            }
            if (++mb == 3) mb = 0;
        }
#pragma unroll
        for (int nt = 0; nt < 4; nt++) {
            int n = nbase + nt*8;
            float2 bb = *(const float2*)&b2[j*128 + n];
#pragma unroll
            for (int mt = 0; mt < 2; mt++)
#pragma unroll
            for (int hf = 0; hf < 2; hf++) {
                int el = ebase + mt*16 + hf*8;
                *(float2*)&g_rad[(size_t)(e0+el)*384 + j*128 + n] =
                    make_float2(acc[mt*4+nt][hf*2+0] + bb.x, acc[mt*4+nt][hf*2+1] + bb.y);
            }
        }
    }
}

// ---------------- extra: 14-half triple-buffered pipeline ----------------
__global__ void __launch_bounds__(512,2) extra_kernel(
    const float* __restrict__ lng, const float* __restrict__ lnb,
    const float* __restrict__ adot, const int* __restrict__ eidx)
{
    extern __shared__ uint32_t sm[];
    uint32_t* Xs = sm;            // 8704
    uint32_t* Ws = sm + 8704;     // 13824
    int* src_s = (int*)(sm + 22528);
    int* tgt_s = src_s + 128;
    int e0 = blockIdx.x * 128, t = threadIdx.x;
    int lane = t & 31, w = t >> 5, mg = w & 3, ng = w >> 2;
    cp_chunk<1152,512>(Ws,        g_Wm0c,        t);
    cp_chunk<1152,512>(Ws + 4608, g_Wm0c + 4608, t);
    if (t < 128)      src_s[t]     = eidx[e0 + t];
    else if (t < 256) tgt_s[t-128] = eidx[NE + e0 + t - 128];
    __syncthreads();
    {
        int e = t >> 2, q = t & 3;
        const float4* rp = (const float4*)&g_rad[(size_t)(e0+e)*384 + q*32];
        const float4* xp = (q < 2)
            ? (const float4*)&g_xn[(size_t)src_s[e]*576 + q*32]
            : (const float4*)&g_xn[(size_t)tgt_s[e]*576 + (q-2)*32];
        uint32_t* col = Xs + e*68 + q*16;
#pragma unroll
        for (int i4 = 0; i4 < 8; i4++) {
            float4 xv = xp[i4], rv = rp[i4];
            *(uint2*)(col + i4*2) =
                make_uint2(f2bf2(xv.x*rv.x, xv.y*rv.y), f2bf2(xv.z*rv.z, xv.w*rv.w));
        }
    }
    int nbase = ng*32 + (lane&3)*2;
    int ebase = mg*32 + (lane>>2);
    int m = 0, mb = 0;
    for (int oc = 0; oc < 7; oc++) {
        float acc[8][4] = {};
        for (int s = 0; s < 2; s++, m++) {
            if (m + 1 < 14) CP_WAIT1(); else CP_WAIT0();
            __syncthreads();
            gemm_mma<68,36,4>(Ws + mb*4608, Xs + s*32, lane, mg, ng, acc);
            if (m + 2 < 14) {
                int nb = mb + 2; if (nb >= 3) nb -= 3;
                cp_chunk<1152,512>(Ws + nb*4608, g_Wm0c + (m+2)*4608, t);
            }
            if (++mb == 3) mb = 0;
        }
        if (oc < 2) {
            int h = oc*4 + ng;
#pragma unroll
            for (int mt = 0; mt < 2; mt++)
#pragma unroll
            for (int hf = 0; hf < 2; hf++) {
                int el = ebase + mt*16 + hf*8;
                float sum = 0.f, ssq = 0.f;
#pragma unroll
                for (int nt = 0; nt < 4; nt++) {
                    float v0 = acc[mt*4+nt][hf*2+0], v1 = acc[mt*4+nt][hf*2+1];
                    sum += v0 + v1; ssq += v0*v0 + v1*v1;
                }
                sum += __shfl_xor_sync(0xffffffffu, sum, 1);
                sum += __shfl_xor_sync(0xffffffffu, sum, 2);
                ssq += __shfl_xor_sync(0xffffffffu, ssq, 1);
                ssq += __shfl_xor_sync(0xffffffffu, ssq, 2);
                float mean = sum * (1.f/32.f);
                float rs = rsqrtf(ssq * (1.f/32.f) - mean*mean + 1e-5f);
                float logit = 0.f;
#pragma unroll
                for (int nt = 0; nt < 4; nt++) {
                    int a = nt*8 + (lane&3)*2;
#pragma unroll
                    for (int jj = 0; jj < 2; jj++) {
                        float v = acc[mt*4+nt][hf*2+jj];
                        float an = (v - mean)*rs*lng[a+jj] + lnb[a+jj];
                        logit += (0.2f*an + 0.8f*an*sigm(an)) * adot[h*32 + a + jj];
                    }
                }
                logit += __shfl_xor_sync(0xffffffffu, logit, 1);
                logit += __shfl_xor_sync(0xffffffffu, logit, 2);
                if ((lane & 3) == 0) {
                    float ex = __expf(logit);
                    g_e[(size_t)(e0+el)*8 + h] = ex;
                    atomicAdd(&g_den[(size_t)tgt_s[el]*8 + h], ex);
                }
            }
        } else if (oc == 2) {
#pragma unroll
            for (int nt = 0; nt < 4; nt++) {
                int n = nbase + nt*8;
#pragma unroll
                for (int mt = 0; mt < 2; mt++)
#pragma unroll
                for (int hf = 0; hf < 2; hf++) {
                    int el = ebase + mt*16 + hf*8;
                    float z0 = acc[mt*4+nt][hf*2+0], z1 = acc[mt*4+nt][hf*2+1];
                    g_val0b[(size_t)(e0+el)*64 + (n>>1)] =
                        f2bf2(z0*sigm(z0), z1*sigm(z1));
                }
            }
        } else {
            int which = oc - 3;
            uint32_t* base = (which < 2) ? g_gdirb : g_gtenb;
            int l = which & 1;
#pragma unroll
            for (int nt = 0; nt < 4; nt++) {
                int n = nbase + nt*8;
#pragma unroll
                for (int mt = 0; mt < 2; mt++)
#pragma unroll
                for (int hf = 0; hf < 2; hf++) {
                    int el = ebase + mt*16 + hf*8;
                    base[(size_t)(e0+el)*128 + l*64 + (n>>1)] =
                        f2bf2(sigm(acc[mt*4+nt][hf*2+0]), sigm(acc[mt*4+nt][hf*2+1]));
                }
            }
        }
    }
}

// ---------------- fused conv1+conv2: resident bf16 weights, 2 blocks/SM ----------------
__global__ void __launch_bounds__(512,2) conv_kernel(
    const float* __restrict__ rl, const int* __restrict__ eidx)
{
    extern __shared__ uint32_t sm[];
    uint32_t* XV  = sm;            // 8704
    uint32_t* W1s = sm + 8704;     // 8704
    uint32_t* W2s = sm + 17408;    // 8704
    float* rl_s = (float*)(sm + 26112);
    float* ee_s = (float*)(sm + 27136);
    int* src_s = (int*)(sm + 28160);
    int* tgt_s = (int*)(sm + 28288);
    int e0 = blockIdx.x * 128, t = threadIdx.x;
    int lane = t & 31, w = t >> 5, mg = w & 3, ng = w >> 2;
    if (t < 128)      src_s[t]     = eidx[e0 + t];
    else if (t < 256) tgt_s[t-128] = eidx[NE + e0 + t - 128];
    for (int i = t; i < 1024; i += 512) {
        rl_s[i] = rl[(size_t)e0*8 + i];
        ee_s[i] = g_e[(size_t)e0*8 + i];
    }
    int nbase = ng*32 + (lane&3)*2;
    int ebase = mg*32 + (lane>>2);
    int se = t >> 2, sq = t & 3;

    for (int deg = 0; deg <= 2; deg++) {
        __syncthreads();
        cp_chunk<2176,512>(W2s, g_Wc2c + deg*8704, t);
        if (deg) cp_chunk<2176,512>(W1s, g_Wc1c + deg*8704, t);
        int kbeg = (deg == 0) ? 0 : ((deg == 1) ? 1 : 4);
        int kend = (deg == 0) ? 1 : ((deg == 1) ? 4 : 9);
        for (int k = kbeg; k < kend; k++) {
            if (deg == 0) {
                const uint4* vp = (const uint4*)&g_val0b[(size_t)(e0+se)*64 + sq*16];
                uint32_t* col = XV + se*68 + sq*16;
#pragma unroll
                for (int i4 = 0; i4 < 4; i4++) *(uint4*)(col + i4*4) = vp[i4];
            } else {
                const float4* rp = (const float4*)&g_rad[(size_t)(e0+se)*384 + deg*128 + sq*32];
                const float4* xp = (sq < 2)
                    ? (const float4*)&g_xn[(size_t)src_s[se]*576 + k*64 + sq*32]
                    : (const float4*)&g_xn[(size_t)tgt_s[se]*576 + k*64 + (sq-2)*32];
                uint32_t* col = XV + se*68 + sq*16;
#pragma unroll
                for (int i4 = 0; i4 < 8; i4++) {
                    float4 xv = xp[i4], rv = rp[i4];
                    *(uint2*)(col + i4*2) =
                        make_uint2(f2bf2(xv.x*rv.x, xv.y*rv.y), f2bf2(xv.z*rv.z, xv.w*rv.w));
                }
            }
            if (k == kbeg) CP_WAIT0();
            __syncthreads();
            if (deg) {
                float acc[8][4] = {};
                gemm_mma<68,68,8>(W1s, XV, lane, mg, ng, acc);
                int l = (k < 4) ? 0 : 1;
#pragma unroll
                for (int mt = 0; mt < 2; mt++)
#pragma unroll
                for (int hf = 0; hf < 2; hf++) {
                    int el = ebase + mt*16 + hf*8;
                    size_t ge = (size_t)(e0 + el);
                    float r = rl_s[el*8 + (k-1)];
                    size_t gb = ge*128 + l*64;
                    size_t xb = (size_t)src_s[el]*512 + (size_t)(k-1)*64;
#pragma unroll
                    for (int nt = 0; nt < 4; nt++) {
                        int n = nbase + nt*8;
                        float2 gd = ubf2(g_gdirb[gb + (n>>1)]);
                        float2 gt = ubf2(g_gtenb[gb + (n>>1)]);
                        float2 xj = ubf2(g_xjpb[xb + (n>>1)]);
                        acc[mt*4+nt][hf*2+0] += r*gd.x + xj.x*gt.x;
                        acc[mt*4+nt][hf*2+1] += r*gd.y + xj.y*gt.y;
                    }
                }
                __syncthreads();
#pragma unroll
                for (int mt = 0; mt < 2; mt++)
#pragma unroll
                for (int hf = 0; hf < 2; hf++) {
                    int el = ebase + mt*16 + hf*8;
#pragma unroll
                    for (int nt = 0; nt < 4; nt++) {
                        int n = nbase + nt*8;
                        XV[el*68 + (n>>1)] =
                            f2bf2(acc[mt*4+nt][hf*2+0], acc[mt*4+nt][hf*2+1]);
                    }
                }
                __syncthreads();
            }
            float acc[8][4] = {};
            gemm_mma<68,68,8>(W2s, XV, lane, mg, ng, acc);
#pragma unroll
            for (int mt = 0; mt < 2; mt++)
#pragma unroll
            for (int hf = 0; hf < 2; hf++) {
                int el = ebase + mt*16 + hf*8;
                size_t nb = (size_t)tgt_s[el]*1152 + (size_t)k*128;
#pragma unroll
                for (int nt = 0; nt < 4; nt++) {
                    int n = nbase + nt*8;
                    float s = ee_s[el*8 + (n >> 4)];
                    red2(&g_num[nb + n], acc[mt*4+nt][hf*2+0]*s, acc[mt*4+nt][hf*2+1]*s);
                }
            }
            __syncthreads();
        }
    }
}

// ---------------- node GEMMs ----------------
#define P_T0 79
#define P_T1 314
#define P_GRID 705
__device__ __forceinline__ void node_row(int b, int* deg, int* rbase,
                                         int* nslots, int* soff, int* nrows)
{
    if (b < P_T0)      { *deg=0; *rbase=b*128;          *nslots=1; *soff=0; *nrows=10000; }
    else if (b < P_T1) { *deg=1; *rbase=(b-P_T0)*128;   *nslots=3; *soff=1; *nrows=30000; }
    else               { *deg=2; *rbase=(b-P_T1)*128;   *nslots=5; *soff=4; *nrows=50000; }
}

__global__ void __launch_bounds__(256,2) proj_mma(
    const float* __restrict__ x, const float* __restrict__ bp)
{
    extern __shared__ uint32_t sm[];
    uint32_t* Xs = sm;            // 8704
    uint32_t* Ws = sm + 8704;     // 4352
    int deg, rbase, nslots, soff, nrows;
    node_row(blockIdx.x, &deg, &rbase, &nslots, &soff, &nrows);
    int t = threadIdx.x, lane = t & 31, w = t >> 5, mg = w & 3, ng = w >> 2;
    cp_chunk<1088,256>(Ws, g_Wpc + deg*4352, t);
    {
        int r = t >> 1, h2 = t & 1;
        int gr = rbase + r;
        uint32_t* col = Xs + r*68 + h2*32;
        if (gr < nrows) {
            int node = gr / nslots, slot = soff + gr % nslots;
            const float4* np = (const float4*)&g_num[(size_t)node*1152 + slot*128 + h2*64];
            float di[4];
#pragma unroll
            for (int q = 0; q < 4; q++) di[q] = 1.f / (g_den[node*8 + h2*4 + q] + 1e-30f);
#pragma unroll
            for (int i = 0; i < 16; i++) {
                float4 v = np[i]; float d = di[i>>2];
                *(uint2*)(col + i*2) = make_uint2(f2bf2(v.x*d, v.y*d), f2bf2(v.z*d, v.w*d));
            }
        } else {
#pragma unroll
            for (int i = 0; i < 16; i++) *(uint2*)(col + i*2) = make_uint2(0,0);
        }
    }
    CP_WAIT0();
    __syncthreads();
    float acc[8][4] = {};
    gemm_mma<68,68,8>(Ws, Xs, lane, mg, ng, acc);
    int nbase = ng*32 + (lane&3)*2;
    int ebase = mg*32 + (lane>>2);
#pragma unroll
    for (int mt = 0; mt < 2; mt++)
#pragma unroll
    for (int hf = 0; hf < 2; hf++) {
        int gr = rbase + ebase + mt*16 + hf*8;
        if (gr >= nrows) continue;
        int node = gr / nslots, slot = soff + gr % nslots;
        size_t ob = (size_t)node*576 + slot*64;
#pragma unroll
        for (int nt = 0; nt < 4; nt++) {
            int n = nbase + nt*8;
            float b0 = (slot == 0) ? bp[n] : 0.f, b1 = (slot == 0) ? bp[n+1] : 0.f;
            *(float2*)&g_x1[ob + n] = make_float2(
                x[ob + n]   + acc[mt*4+nt][hf*2+0] + b0,
                x[ob + n+1] + acc[mt*4+nt][hf*2+1] + b1);
        }
    }
}

__global__ void __launch_bounds__(256,2) ffn2_mma(
    const float* __restrict__ bf2, float* __restrict__ out)
{
    extern __shared__ uint32_t sm[];
    uint32_t* Xs = sm;
    uint32_t* Ws = sm + 8704;
    int deg, rbase, nslots, soff, nrows;
    node_row(blockIdx.x, &deg, &rbase, &nslots, &soff, &nrows);
    int t = threadIdx.x, lane = t & 31, w = t >> 5, mg = w & 3, ng = w >> 2;
    cp_chunk<1088,256>(Ws, g_Wf2c + deg*4352, t);
    {
        int r = t >> 1, h2 = t & 1;
        int gr = rbase + r;
        uint32_t* col = Xs + r*68 + h2*32;
        if (gr < nrows) {
            int node = gr / nslots, slot = soff + gr % nslots;
            const float4* hp = (slot == 0)
                ? (const float4*)&g_gsil[(size_t)node*128 + h2*64]
                : (const float4*)&g_h[(size_t)node*1024 + (size_t)(slot-1)*128 + h2*64];
#pragma unroll
            for (int i = 0; i < 16; i++) {
                float4 v = hp[i];
                *(uint2*)(col + i*2) = make_uint2(f2bf2(v.x, v.y), f2bf2(v.z, v.w));
            }
        } else {
#pragma unroll
            for (int i = 0; i < 16; i++) *(uint2*)(col + i*2) = make_uint2(0,0);
        }
    }
    CP_WAIT0();
    __syncthreads();
    float acc[8][4] = {};
    gemm_mma<68,68,8>(Ws, Xs, lane, mg, ng, acc);
    int nbase = ng*32 + (lane&3)*2;
    int ebase = mg*32 + (lane>>2);
#pragma unroll
    for (int mt = 0; mt < 2; mt++)
#pragma unroll
    for (int hf = 0; hf < 2; hf++) {
        int gr = rbase + ebase + mt*16 + hf*8;
        if (gr >= nrows) continue;
        int node = gr / nslots, slot = soff + gr % nslots;
        size_t ob = (size_t)node*576 + slot*64;
#pragma unroll
        for (int nt = 0; nt < 4; nt++) {
            int n = nbase + nt*8;
            float b0 = (slot == 0) ? bf2[n] : 0.f, b1 = (slot == 0) ? bf2[n+1] : 0.f;
            *(float2*)&out[ob + n] = make_float2(
                g_x1[ob + n]   + acc[mt*4+nt][hf*2+0] + b0,
                g_x1[ob + n+1] + acc[mt*4+nt][hf*2+1] + b1);
        }
    }
}

#define F_T1 469
#define F_GRID 1251
__global__ void __launch_bounds__(256) ffn1_mma()
{
    extern __shared__ uint32_t sm[];
    uint32_t* Xs = sm;            // 2304
    uint32_t* Ws = sm + 2304;     // 4608
    int b = blockIdx.x, deg, rbase, nslots, soff, nrows;
    if (b < F_T1) { deg=1; rbase=b*64;         nslots=3; soff=1; nrows=30000; }
    else          { deg=2; rbase=(b-F_T1)*64;  nslots=5; soff=4; nrows=50000; }
    int t = threadIdx.x, lane = t & 31, w = t >> 5, mg = w & 1, ng = w >> 1;
    cp_chunk<1152,256>(Ws, g_Wf1c + deg*4608, t);
    {
        int r = t >> 2, q = t & 3;
        int gr = rbase + r;
        uint32_t* col = Xs + r*36 + q*8;
        if (gr < nrows) {
            int node = gr / nslots, slot = soff + gr % nslots;
            const float4* yp = (const float4*)&g_yn[(size_t)node*576 + slot*64 + q*16];
#pragma unroll
            for (int i = 0; i < 4; i++) {
                float4 v = yp[i];
                *(uint2*)(col + i*2) = make_uint2(f2bf2(v.x, v.y), f2bf2(v.z, v.w));
            }
        } else {
#pragma unroll
            for (int i = 0; i < 4; i++) *(uint2*)(col + i*2) = make_uint2(0,0);
        }
    }
    CP_WAIT0();
    __syncthreads();
    float acc[8][4] = {};
    gemm_mma<36,36,4>(Ws, Xs, lane, mg, ng, acc);
    int nbase = ng*32 + (lane&3)*2;
    int ebase = mg*32 + (lane>>2);
#pragma unroll
    for (int mt = 0; mt < 2; mt++)
#pragma unroll
    for (int hf = 0; hf < 2; hf++) {
        int gr = rbase + ebase + mt*16 + hf*8;
        if (gr >= nrows) continue;
        int node = gr / nslots, slot = soff + gr % nslots;
        size_t hb = (size_t)node*1024 + (size_t)(slot-1)*128;
        size_t gsb = (size_t)node*128;
#pragma unroll
        for (int nt = 0; nt < 4; nt++) {
            int n = nbase + nt*8;
            float2 gs = *(const float2*)&g_gsig[gsb + n];
            *(float2*)&g_h[hb + n] = make_float2(
                acc[mt*4+nt][hf*2+0]*gs.x, acc[mt*4+nt][hf*2+1]*gs.y);
        }
    }
}

// ---------------- launch ----------------
extern "C" void kernel_launch(void* const* d_in, const int* in_sizes, int n_in,
                              void* d_out, int out_size)
{
    const float* x     = (const float*)d_in[0];
    const float* edist = (const float*)d_in[1];
    const float* rl    = (const float*)d_in[2];
    const float* semb  = (const float*)d_in[3];
    const float* temb  = (const float*)d_in[4];
    const float* W1    = (const float*)d_in[5];
    const float* b1    = (const float*)d_in[6];
    const float* W2    = (const float*)d_in[7];
    const float* b2    = (const float*)d_in[8];
    const float* Wc1   = (const float*)d_in[9];
    const float* Wm0   = (const float*)d_in[10];
    const float* lng   = (const float*)d_in[11];
    const float* lnb   = (const float*)d_in[12];
    const float* adot  = (const float*)d_in[13];
    const float* Wxj   = (const float*)d_in[14];
    const float* Wc2   = (const float*)d_in[15];
    const float* Wp    = (const float*)d_in[16];
    const float* bp    = (const float*)d_in[17];
    const float* Wg    = (const float*)d_in[18];
    const float* bg    = (const float*)d_in[19];
    const float* Wf1   = (const float*)d_in[20];
    const float* Wf2   = (const float*)d_in[22];
    const float* bf2   = (const float*)d_in[23];
    const int*   anum  = (const int*)d_in[24];
    const int*   eidx  = (const int*)d_in[25];
    float* out = (float*)d_out;

    float *p_xn, *p_x1, *p_yn;
    cudaGetSymbolAddress((void**)&p_xn, g_xn);
    cudaGetSymbolAddress((void**)&p_x1, g_x1);
    cudaGetSymbolAddress((void**)&p_yn, g_yn);

    static bool attr_set = false;
    if (!attr_set) {
        cudaFuncSetAttribute(rad_kernel,   cudaFuncAttributeMaxDynamicSharedMemorySize, 91136);
        cudaFuncSetAttribute(extra_kernel, cudaFuncAttributeMaxDynamicSharedMemorySize, 91136);
        cudaFuncSetAttribute(conv_kernel,  cudaFuncAttributeMaxDynamicSharedMemorySize, 113664);
        cudaFuncSetAttribute(proj_mma,     cudaFuncAttributeMaxDynamicSharedMemorySize, 52224);
        cudaFuncSetAttribute(ffn2_mma,     cudaFuncAttributeMaxDynamicSharedMemorySize, 52224);
        cudaFuncSetAttribute(ffn1_mma,     cudaFuncAttributeMaxDynamicSharedMemorySize, 27648);
        cudaFuncSetAttribute(xjp_mma,      cudaFuncAttributeMaxDynamicSharedMemorySize, 27648);
        cudaFuncSetAttribute(gate_mma,     cudaFuncAttributeMaxDynamicSharedMemorySize, 27648);
        attr_set = true;
    }

    wconv_kernel<<<(WCONV_N + 255)/256, 256>>>(W1, W2, Wm0, Wc1, Wc2, Wp, Wf1, Wf2, Wxj, Wg);
    zero_kernel<<<(NN*1152/4 + 255)/256, 256>>>();
    enorm_kernel<<<NN/4, 256>>>(x, p_xn);
    xjp_mma<<<XJ_GRID, 256, 27648>>>();
    rad_kernel<<<NE/128, 512, 91136>>>(edist, semb, temb, b1, b2, anum, eidx);
    extra_kernel<<<NE/128, 512, 91136>>>(lng, lnb, adot, eidx);
    conv_kernel<<<NE/128, 512, 113664>>>(rl, eidx);
    proj_mma<<<P_GRID, 256, 52224>>>(x, bp);
    enorm_kernel<<<NN/4, 256>>>(p_x1, p_yn);
    gate_mma<<<GATE_GRID, 256, 27648>>>(bg);
    ffn1_mma<<<F_GRID, 256, 27648>>>();
    ffn2_mma<<<P_GRID, 256, 52224>>>(bf2, out);
}

// round 17
// speedup vs baseline: 1.4601x; 1.0003x over previous
#include <cuda_runtime.h>
#include <cstdint>

#define NN 10000
#define NE 80000

__device__ float g_xn  [NN*576];
__device__ float g_rad [NE*384];
__device__ uint32_t g_val0b[NE*64];    // bf16x2 pairs
__device__ uint32_t g_gdirb[NE*128];   // bf16x2 pairs (l,n/2)
__device__ uint32_t g_gtenb[NE*128];
__device__ float g_e   [NE*8];
__device__ uint32_t g_xjpb[NN*512];    // bf16x2 pairs
__device__ float g_num [NN*1152];
__device__ float g_den [NN*8];
__device__ float g_x1  [NN*576];
__device__ float g_yn  [NN*576];
__device__ float g_h   [NN*1024];
__device__ float g_gsil[NN*128];
__device__ float g_gsig[NN*128];

// bf16-pair weights, row-major [n][k2] images (ldmatrix-ready)
__device__ __align__(16) uint32_t g_W1c [9216];
__device__ __align__(16) uint32_t g_W2c [27648];
__device__ __align__(16) uint32_t g_Wm0c[64512];
__device__ __align__(16) uint32_t g_Wc1c[26112];
__device__ __align__(16) uint32_t g_Wc2c[26112];
__device__ __align__(16) uint32_t g_Wpc [13056];
__device__ __align__(16) uint32_t g_Wf1c[13824];
__device__ __align__(16) uint32_t g_Wf2c[13056];
__device__ __align__(16) uint32_t g_Wxjc[4608];
__device__ __align__(16) uint32_t g_Wgc [4608];

__device__ __forceinline__ float sigm(float z) { return 1.f / (1.f + __expf(-z)); }

__device__ __forceinline__ uint32_t f2bf2(float lo, float hi) {
    uint32_t r; asm("cvt.rn.bf16x2.f32 %0, %1, %2;" : "=r"(r) : "f"(hi), "f"(lo)); return r;
}
__device__ __forceinline__ float2 ubf2(uint32_t w) {
    return make_float2(__uint_as_float(w << 16), __uint_as_float(w & 0xffff0000u));
}
__device__ __forceinline__ void red2(float* p, float a, float b) {
    asm volatile("red.global.add.v2.f32 [%0], {%1,%2};" :: "l"(p), "f"(a), "f"(b) : "memory");
}
__device__ __forceinline__ void red4(float* p, float a, float b, float c, float d) {
    asm volatile("red.global.add.v4.f32 [%0], {%1,%2,%3,%4};"
                 :: "l"(p), "f"(a), "f"(b), "f"(c), "f"(d) : "memory");
}
__device__ __forceinline__ void mma16(float* d, uint32_t a0,uint32_t a1,uint32_t a2,uint32_t a3,
                                      uint32_t b0,uint32_t b1) {
    asm volatile("mma.sync.aligned.m16n8k16.row.col.f32.bf16.bf16.f32 "
                 "{%0,%1,%2,%3},{%4,%5,%6,%7},{%8,%9},{%0,%1,%2,%3};"
                 : "+f"(d[0]),"+f"(d[1]),"+f"(d[2]),"+f"(d[3])
                 : "r"(a0),"r"(a1),"r"(a2),"r"(a3),"r"(b0),"r"(b1));
}
__device__ __forceinline__ uint32_t s2u(const uint32_t* p) {
    return (uint32_t)__cvta_generic_to_shared(p);
}
#define LDSM4(r0,r1,r2,r3,addr) \
    asm volatile("ldmatrix.sync.aligned.m8n8.x4.shared.b16 {%0,%1,%2,%3}, [%4];" \
        : "=r"(r0),"=r"(r1),"=r"(r2),"=r"(r3) : "r"(addr))

__device__ __forceinline__ void cp16(uint32_t saddr, const uint32_t* src) {
    asm volatile("cp.async.cg.shared.global [%0], [%1], 16;" :: "r"(saddr), "l"(src));
}
#define CP_COMMIT() asm volatile("cp.async.commit_group;" ::: "memory")
#define CP_WAIT0()  asm volatile("cp.async.wait_group 0;" ::: "memory")
#define CP_WAIT1()  asm volatile("cp.async.wait_group 1;" ::: "memory")

template<int N4, int NT>
__device__ __forceinline__ void cp_chunk(uint32_t* dst, const uint32_t* __restrict__ src, int t) {
    uint32_t d = (uint32_t)__cvta_generic_to_shared(dst);
    for (int i = t; i < N4; i += NT) cp16(d + i*16, src + i*4);
    CP_COMMIT();
}

// Warp tile 32 rows x 32 cols, bf16 k16, ldmatrix fragment loads.
template<int XST, int WST, int NK>
__device__ __forceinline__ void gemm_mma(const uint32_t* __restrict__ Ws,
                                         const uint32_t* __restrict__ Xs,
                                         int lane, int mg, int ng, float acc[8][4])
{
    int aro = ((lane>>3)&1)*8 + (lane&7);
    int awo = (lane>>4)*4;
    uint32_t aa0 = s2u(Xs + (mg*32 + aro)*XST + awo);
    uint32_t aa1 = aa0 + 16*XST*4;
    int bro = (lane&7) + (lane>>4)*8;
    int bwo = ((lane>>3)&1)*4;
    uint32_t ba0 = s2u(Ws + (ng*32 + bro)*WST + bwo);
    uint32_t ba1 = ba0 + 16*WST*4;
#pragma unroll
    for (int kk = 0; kk < NK; kk++) {
        uint32_t a0,a1,a2,a3, c0,c1,c2,c3, p0,p1,p2,p3, q0,q1,q2,q3;
        LDSM4(a0,a1,a2,a3, aa0 + kk*32);
        LDSM4(c0,c1,c2,c3, aa1 + kk*32);
        LDSM4(p0,p1,p2,p3, ba0 + kk*32);
        LDSM4(q0,q1,q2,q3, ba1 + kk*32);
        mma16(acc[0], a0,a1,a2,a3, p0,p1);
        mma16(acc[1], a0,a1,a2,a3, p2,p3);
        mma16(acc[2], a0,a1,a2,a3, q0,q1);
        mma16(acc[3], a0,a1,a2,a3, q2,q3);
        mma16(acc[4], c0,c1,c2,c3, p0,p1);
        mma16(acc[5], c0,c1,c2,c3, p2,p3);
        mma16(acc[6], c0,c1,c2,c3, q0,q1);
        mma16(acc[7], c0,c1,c2,c3, q2,q3);
    }
}

// ---------------- weight pre-conversion ----------------
__global__ void __launch_bounds__(256) wconv_kernel(
    const float* __restrict__ W1, const float* __restrict__ W2,
    const float* __restrict__ Wm0, const float* __restrict__ Wc1,
    const float* __restrict__ Wc2, const float* __restrict__ Wp,
    const float* __restrict__ Wf1, const float* __restrict__ Wf2,
    const float* __restrict__ Wxj, const float* __restrict__ Wg)
{
    int i = blockIdx.x*256 + threadIdx.x;
    if (i < 8192) { int k2=i>>7, n=i&127;
        g_W1c[(k2>>5)*4608 + n*36 + (k2&31)] =
            f2bf2(W1[2*k2*128+n], W1[(2*k2+1)*128+n]); return; } i -= 8192;
    if (i < 24576) { int j=i/8192, r=i&8191, k2=r>>7, n=r&127;
        g_W2c[(j*2 + (k2>>5))*4608 + n*36 + (k2&31)] =
            f2bf2(W2[2*k2*384 + j*128 + n], W2[(2*k2+1)*384 + j*128 + n]); return; } i -= 24576;
    if (i < 57344){ int j=i/8192, r=i&8191, k2=r>>7, n=r&127;
        g_Wm0c[(j*2 + (k2>>5))*4608 + n*36 + (k2&31)] =
            f2bf2(Wm0[2*k2*896 + j*128 + n], Wm0[(2*k2+1)*896 + j*128 + n]); return; } i -= 57344;
    if (i < 24576) { int d=i>>13, r=i&8191, k2=r>>7, n=r&127;
        g_Wc1c[d*8704 + n*68 + k2] =
            f2bf2(Wc1[d*16384 + 2*k2*128 + n], Wc1[d*16384 + (2*k2+1)*128 + n]); return; } i -= 24576;
    if (i < 24576) { int d=i>>13, r=i&8191, k2=r>>7, n=r&127;
        g_Wc2c[d*8704 + n*68 + k2] =
            f2bf2(Wc2[d*16384 + 2*k2*128 + n], Wc2[d*16384 + (2*k2+1)*128 + n]); return; } i -= 24576;
    if (i < 12288) { int d=i>>12, r=i&4095, k2=r>>6, n=r&63;
        g_Wpc[d*4352 + n*68 + k2] =
            f2bf2(Wp[d*8192 + 2*k2*64 + n], Wp[d*8192 + (2*k2+1)*64 + n]); return; } i -= 12288;
    if (i < 8192) { int d=(i>>12)+1, r=i&4095, k2=r>>7, n=r&127;
        g_Wf1c[d*4608 + n*36 + k2] =
            f2bf2(Wf1[d*8192 + 2*k2*128 + n], Wf1[d*8192 + (2*k2+1)*128 + n]); return; } i -= 8192;
    if (i < 12288) { int d=i>>12, r=i&4095, k2=r>>6, n=r&63;
        g_Wf2c[d*4352 + n*68 + k2] =
            f2bf2(Wf2[d*8192 + 2*k2*64 + n], Wf2[d*8192 + (2*k2+1)*64 + n]); return; } i -= 12288;
    if (i < 4096)  { int k2=i>>7, n=i&127;
        g_Wxjc[n*36 + k2] = f2bf2(Wxj[2*k2*128+n], Wxj[(2*k2+1)*128+n]); return; } i -= 4096;
    if (i < 4096)  { int k2=i>>7, n=i&127;
        g_Wgc[n*36 + k2] = f2bf2(Wg[2*k2*128+n], Wg[(2*k2+1)*128+n]); return; }
}
#define WCONV_N 180224

__global__ void zero_kernel() {
    size_t i = (size_t)blockIdx.x * blockDim.x + threadIdx.x;
    if (i < NN*1152/4) ((float4*)g_num)[i] = make_float4(0.f,0.f,0.f,0.f);
    if (i < NN*8)      g_den[i] = 0.f;
}

// ---------------- enorm ----------------
__global__ void __launch_bounds__(256) enorm_kernel(const float* __restrict__ src, float* __restrict__ dst) {
    int n = blockIdx.x*4 + (threadIdx.x >> 6);
    int c = threadIdx.x & 63;
    const float* p = src + (size_t)n*576 + c;
    float v[9];
#pragma unroll
    for (int k = 0; k < 9; k++) v[k] = p[k*64];
    float s0 = v[0]*v[0];
    float s1 = v[1]*v[1] + v[2]*v[2] + v[3]*v[3];
    float s2 = v[4]*v[4] + v[5]*v[5] + v[6]*v[6] + v[7]*v[7] + v[8]*v[8];
#pragma unroll
    for (int off = 16; off; off >>= 1) {
        s0 += __shfl_xor_sync(0xffffffffu, s0, off);
        s1 += __shfl_xor_sync(0xffffffffu, s1, off);
        s2 += __shfl_xor_sync(0xffffffffu, s2, off);
    }
    __shared__ float red[4][3][2];
    int g = threadIdx.x >> 6, hw = (c >> 5);
    if ((c & 31) == 0) { red[g][0][hw] = s0; red[g][1][hw] = s1; red[g][2][hw] = s2; }
    __syncthreads();
    float sc0 = rsqrtf((red[g][0][0]+red[g][0][1]) * (1.f/64.f)  + 1e-6f);
    float sc1 = rsqrtf((red[g][1][0]+red[g][1][1]) * (1.f/192.f) + 1e-6f);
    float sc2 = rsqrtf((red[g][2][0]+red[g][2][1]) * (1.f/320.f) + 1e-6f);
    float* q = dst + (size_t)n*576 + c;
    q[0] = v[0]*sc0;
#pragma unroll
    for (int k = 1; k < 4; k++) q[k*64] = v[k]*sc1;
#pragma unroll
    for (int k = 4; k < 9; k++) q[k*64] = v[k]*sc2;
}

// ---------------- xjp: 80000 rows x 128, K=64 ----------------
#define XJ_GRID 1250
__global__ void __launch_bounds__(256) xjp_mma()
{
    extern __shared__ uint32_t sm[];
    uint32_t* Xs = sm;            // 2304
    uint32_t* Ws = sm + 2304;     // 4608
    int rbase = blockIdx.x * 64;
    int t = threadIdx.x, lane = t & 31, w = t >> 5, mg = w & 1, ng = w >> 1;
    cp_chunk<1152,256>(Ws, g_Wxjc, t);
    {
        int r = t >> 2, q = t & 3;
        int gr = rbase + r;
        int node = gr >> 3, slot = 1 + (gr & 7);
        const float4* yp = (const float4*)&g_xn[(size_t)node*576 + slot*64 + q*16];
        uint32_t* col = Xs + r*36 + q*8;
#pragma unroll
        for (int i = 0; i < 4; i++) {
            float4 v = yp[i];
            *(uint2*)(col + i*2) = make_uint2(f2bf2(v.x, v.y), f2bf2(v.z, v.w));
        }
    }
    CP_WAIT0();
    __syncthreads();
    float acc[8][4] = {};
    gemm_mma<36,36,4>(Ws, Xs, lane, mg, ng, acc);
    int nbase = ng*32 + (lane&3)*2;
    int ebase = mg*32 + (lane>>2);
#pragma unroll
    for (int mt = 0; mt < 2; mt++)
#pragma unroll
    for (int hf = 0; hf < 2; hf++) {
        int gr = rbase + ebase + mt*16 + hf*8;
        int node = gr >> 3, slot = gr & 7;
        size_t ob = (size_t)node*512 + (size_t)slot*64;
#pragma unroll
        for (int nt = 0; nt < 4; nt++) {
            int n = nbase + nt*8;
            g_xjpb[ob + (n>>1)] = f2bf2(acc[mt*4+nt][hf*2+0], acc[mt*4+nt][hf*2+1]);
        }
    }
}

// ---------------- gate: 10000 rows x 128, K=64 ----------------
#define GATE_GRID 157
__global__ void __launch_bounds__(256) gate_mma(const float* __restrict__ bg)
{
    extern __shared__ uint32_t sm[];
    uint32_t* Xs = sm;
    uint32_t* Ws = sm + 2304;
    int rbase = blockIdx.x * 64;
    int t = threadIdx.x, lane = t & 31, w = t >> 5, mg = w & 1, ng = w >> 1;
    cp_chunk<1152,256>(Ws, g_Wgc, t);
    {
        int r = t >> 2, q = t & 3;
        int node = rbase + r;
        uint32_t* col = Xs + r*36 + q*8;
        if (node < NN) {
            const float4* yp = (const float4*)&g_yn[(size_t)node*576 + q*16];
#pragma unroll
            for (int i = 0; i < 4; i++) {
                float4 v = yp[i];
                *(uint2*)(col + i*2) = make_uint2(f2bf2(v.x, v.y), f2bf2(v.z, v.w));
            }
        } else {
#pragma unroll
            for (int i = 0; i < 4; i++) *(uint2*)(col + i*2) = make_uint2(0,0);
        }
    }
    CP_WAIT0();
    __syncthreads();
    float acc[8][4] = {};
    gemm_mma<36,36,4>(Ws, Xs, lane, mg, ng, acc);
    int nbase = ng*32 + (lane&3)*2;
    int ebase = mg*32 + (lane>>2);
#pragma unroll
    for (int mt = 0; mt < 2; mt++)
#pragma unroll
    for (int hf = 0; hf < 2; hf++) {
        int node = rbase + ebase + mt*16 + hf*8;
        if (node >= NN) continue;
        size_t ob = (size_t)node*128;
#pragma unroll
        for (int nt = 0; nt < 4; nt++) {
            int n = nbase + nt*8;
            float z0 = acc[mt*4+nt][hf*2+0] + bg[n];
            float z1 = acc[mt*4+nt][hf*2+1] + bg[n+1];
            float s0 = sigm(z0), s1 = sigm(z1);
            *(float2*)&g_gsil[ob + n] = make_float2(z0*s0, z1*s1);
            *(float2*)&g_gsig[ob + n] = make_float2(s0, s1);
        }
    }
}

// ---------------- radial MLP: 128 edges/block, 8-half triple-buffered pipeline ----------------
__global__ void __launch_bounds__(512,2) rad_kernel(
    const float* __restrict__ edist, const float* __restrict__ semb,
    const float* __restrict__ temb,  const float* __restrict__ b1,
    const float* __restrict__ b2,    const int* __restrict__ anum,
    const int* __restrict__ eidx)
{
    extern __shared__ uint32_t sm[];
    uint32_t* ef = sm;            // 8704
    uint32_t* Ws = sm + 8704;     // 13824
    int* zsrc = (int*)(sm + 22528);
    int* ztgt = zsrc + 128;
    int e0 = blockIdx.x * 128, t = threadIdx.x;
    int lane = t & 31, w = t >> 5, mg = w & 3, ng = w >> 2;
    auto hsrc = [](int m) { return m < 2 ? g_W1c + m*4608 : g_W2c + (m-2)*4608; };
    cp_chunk<1152,512>(Ws,        hsrc(0), t);
    cp_chunk<1152,512>(Ws + 4608, hsrc(1), t);
    if (t < 128)      zsrc[t]     = anum[eidx[e0 + t]];
    else if (t < 256) ztgt[t-128] = anum[eidx[NE + e0 + t - 128]];
    __syncthreads();
    {
        int e = t >> 2, q = t & 3;
        const float4* xp;
        if (q < 2)      xp = (const float4*)&edist[(size_t)(e0+e)*64 + q*32];
        else if (q==2)  xp = (const float4*)&semb[(size_t)zsrc[e]*32];
        else            xp = (const float4*)&temb[(size_t)ztgt[e]*32];
        uint32_t* col = ef + e*68 + q*16;
#pragma unroll
        for (int i4 = 0; i4 < 8; i4++) {
            float4 v = xp[i4];
            *(uint2*)(col + i4*2) = make_uint2(f2bf2(v.x, v.y), f2bf2(v.z, v.w));
        }
    }
    int nbase = ng*32 + (lane&3)*2;
    int ebase = mg*32 + (lane>>2);
    int m = 0, mb = 0;
    {
        float acc[8][4] = {};
        for (int s = 0; s < 2; s++, m++) {
            if (m + 1 < 8) CP_WAIT1(); else CP_WAIT0();
            __syncthreads();
            gemm_mma<68,36,4>(Ws + mb*4608, ef + s*32, lane, mg, ng, acc);
            if (m + 2 < 8) {
                int nb = mb + 2; if (nb >= 3) nb -= 3;
                cp_chunk<1152,512>(Ws + nb*4608, hsrc(m+2), t);
            }
            if (++mb == 3) mb = 0;
        }
        __syncthreads();
#pragma unroll
        for (int nt = 0; nt < 4; nt++) {
            int n = nbase + nt*8;
            float2 bb = *(const float2*)&b1[n];
#pragma unroll
            for (int mt = 0; mt < 2; mt++)
#pragma unroll
            for (int hf = 0; hf < 2; hf++) {
                int el = ebase + mt*16 + hf*8;
                float z0 = acc[mt*4+nt][hf*2+0] + bb.x;
                float z1 = acc[mt*4+nt][hf*2+1] + bb.y;
                ef[el*68 + (n>>1)] = f2bf2(z0*sigm(z0), z1*sigm(z1));
            }
        }
    }
    for (int j = 0; j < 3; j++) {
        float acc[8][4] = {};
        for (int s = 0; s < 2; s++, m++) {
            if (m + 1 < 8) CP_WAIT1(); else CP_WAIT0();
            __syncthreads();
            gemm_mma<68,36,4>(Ws + mb*4608, ef + s*32, lane, mg, ng, acc);
            if (m + 2 < 8) {
                int nb = mb + 2; if (nb >= 3) nb -= 3;
                cp_chunk<1152,512>(Ws + nb*4608, hsrc(m+2), t);
            }
            if (++mb == 3) mb = 0;
        }
#pragma unroll
        for (int nt = 0; nt < 4; nt++) {
            int n = nbase + nt*8;
            float2 bb = *(const float2*)&b2[j*128 + n];
#pragma unroll
            for (int mt = 0; mt < 2; mt++)
#pragma unroll
            for (int hf = 0; hf < 2; hf++) {
                int el = ebase + mt*16 + hf*8;
                *(float2*)&g_rad[(size_t)(e0+el)*384 + j*128 + n] =
                    make_float2(acc[mt*4+nt][hf*2+0] + bb.x, acc[mt*4+nt][hf*2+1] + bb.y);
            }
        }
    }
}

// ---------------- extra: 14-half triple-buffered pipeline ----------------
__global__ void __launch_bounds__(512,2) extra_kernel(
    const float* __restrict__ lng, const float* __restrict__ lnb,
    const float* __restrict__ adot, const int* __restrict__ eidx)
{
    extern __shared__ uint32_t sm[];
    uint32_t* Xs = sm;            // 8704
    uint32_t* Ws = sm + 8704;     // 13824
    int* src_s = (int*)(sm + 22528);
    int* tgt_s = src_s + 128;
    int e0 = blockIdx.x * 128, t = threadIdx.x;
    int lane = t & 31, w = t >> 5, mg = w & 3, ng = w >> 2;
    cp_chunk<1152,512>(Ws,        g_Wm0c,        t);
    cp_chunk<1152,512>(Ws + 4608, g_Wm0c + 4608, t);
    if (t < 128)      src_s[t]     = eidx[e0 + t];
    else if (t < 256) tgt_s[t-128] = eidx[NE + e0 + t - 128];
    __syncthreads();
    {
        int e = t >> 2, q = t & 3;
        const float4* rp = (const float4*)&g_rad[(size_t)(e0+e)*384 + q*32];
        const float4* xp = (q < 2)
            ? (const float4*)&g_xn[(size_t)src_s[e]*576 + q*32]
            : (const float4*)&g_xn[(size_t)tgt_s[e]*576 + (q-2)*32];
        uint32_t* col = Xs + e*68 + q*16;
#pragma unroll
        for (int i4 = 0; i4 < 8; i4++) {
            float4 xv = xp[i4], rv = rp[i4];
            *(uint2*)(col + i4*2) =
                make_uint2(f2bf2(xv.x*rv.x, xv.y*rv.y), f2bf2(xv.z*rv.z, xv.w*rv.w));
        }
    }
    int nbase = ng*32 + (lane&3)*2;
    int ebase = mg*32 + (lane>>2);
    int m = 0, mb = 0;
    for (int oc = 0; oc < 7; oc++) {
        float acc[8][4] = {};
        for (int s = 0; s < 2; s++, m++) {
            if (m + 1 < 14) CP_WAIT1(); else CP_WAIT0();
            __syncthreads();
            gemm_mma<68,36,4>(Ws + mb*4608, Xs + s*32, lane, mg, ng, acc);
            if (m + 2 < 14) {
                int nb = mb + 2; if (nb >= 3) nb -= 3;
                cp_chunk<1152,512>(Ws + nb*4608, g_Wm0c + (m+2)*4608, t);
            }
            if (++mb == 3) mb = 0;
        }
        if (oc < 2) {
            int h = oc*4 + ng;
#pragma unroll
            for (int mt = 0; mt < 2; mt++)
#pragma unroll
            for (int hf = 0; hf < 2; hf++) {
                int el = ebase + mt*16 + hf*8;
                float sum = 0.f, ssq = 0.f;
#pragma unroll
                for (int nt = 0; nt < 4; nt++) {
                    float v0 = acc[mt*4+nt][hf*2+0], v1 = acc[mt*4+nt][hf*2+1];
                    sum += v0 + v1; ssq += v0*v0 + v1*v1;
                }
                sum += __shfl_xor_sync(0xffffffffu, sum, 1);
                sum += __shfl_xor_sync(0xffffffffu, sum, 2);
                ssq += __shfl_xor_sync(0xffffffffu, ssq, 1);
                ssq += __shfl_xor_sync(0xffffffffu, ssq, 2);
                float mean = sum * (1.f/32.f);
                float rs = rsqrtf(ssq * (1.f/32.f) - mean*mean + 1e-5f);
                float logit = 0.f;
#pragma unroll
                for (int nt = 0; nt < 4; nt++) {
                    int a = nt*8 + (lane&3)*2;
#pragma unroll
                    for (int jj = 0; jj < 2; jj++) {
                        float v = acc[mt*4+nt][hf*2+jj];
                        float an = (v - mean)*rs*lng[a+jj] + lnb[a+jj];
                        logit += (0.2f*an + 0.8f*an*sigm(an)) * adot[h*32 + a + jj];
                    }
                }
                logit += __shfl_xor_sync(0xffffffffu, logit, 1);
                logit += __shfl_xor_sync(0xffffffffu, logit, 2);
                if ((lane & 3) == 0) {
                    float ex = __expf(logit);
                    g_e[(size_t)(e0+el)*8 + h] = ex;
                    atomicAdd(&g_den[(size_t)tgt_s[el]*8 + h], ex);
                }
            }
        } else if (oc == 2) {
#pragma unroll
            for (int nt = 0; nt < 4; nt++) {
                int n = nbase + nt*8;
#pragma unroll
                for (int mt = 0; mt < 2; mt++)
#pragma unroll
                for (int hf = 0; hf < 2; hf++) {
                    int el = ebase + mt*16 + hf*8;
                    float z0 = acc[mt*4+nt][hf*2+0], z1 = acc[mt*4+nt][hf*2+1];
                    g_val0b[(size_t)(e0+el)*64 + (n>>1)] =
                        f2bf2(z0*sigm(z0), z1*sigm(z1));
                }
            }
        } else {
            int which = oc - 3;
            uint32_t* base = (which < 2) ? g_gdirb : g_gtenb;
            int l = which & 1;
#pragma unroll
            for (int nt = 0; nt < 4; nt++) {
                int n = nbase + nt*8;
#pragma unroll
                for (int mt = 0; mt < 2; mt++)
#pragma unroll
                for (int hf = 0; hf < 2; hf++) {
                    int el = ebase + mt*16 + hf*8;
                    base[(size_t)(e0+el)*128 + l*64 + (n>>1)] =
                        f2bf2(sigm(acc[mt*4+nt][hf*2+0]), sigm(acc[mt*4+nt][hf*2+1]));
                }
            }
        }
    }
}

// ---------------- fused conv1+conv2: resident bf16 weights, 2 blocks/SM ----------------
__global__ void __launch_bounds__(512,2) conv_kernel(
    const float* __restrict__ rl, const int* __restrict__ eidx)
{
    extern __shared__ uint32_t sm[];
    uint32_t* XV  = sm;            // 8704
    uint32_t* W1s = sm + 8704;     // 8704
    uint32_t* W2s = sm + 17408;    // 8704
    float* rl_s = (float*)(sm + 26112);
    float* ee_s = (float*)(sm + 27136);
    int* src_s = (int*)(sm + 28160);
    int* tgt_s = (int*)(sm + 28288);
    int e0 = blockIdx.x * 128, t = threadIdx.x;
    int lane = t & 31, w = t >> 5, mg = w & 3, ng = w >> 2;
    if (t < 128)      src_s[t]     = eidx[e0 + t];
    else if (t < 256) tgt_s[t-128] = eidx[NE + e0 + t - 128];
    for (int i = t; i < 1024; i += 512) {
        rl_s[i] = rl[(size_t)e0*8 + i];
        ee_s[i] = g_e[(size_t)e0*8 + i];
    }
    int nbase = ng*32 + (lane&3)*2;
    int ebase = mg*32 + (lane>>2);
    int se = t >> 2, sq = t & 3;

    for (int deg = 0; deg <= 2; deg++) {
        __syncthreads();
        cp_chunk<2176,512>(W2s, g_Wc2c + deg*8704, t);
        if (deg) cp_chunk<2176,512>(W1s, g_Wc1c + deg*8704, t);
        int kbeg = (deg == 0) ? 0 : ((deg == 1) ? 1 : 4);
        int kend = (deg == 0) ? 1 : ((deg == 1) ? 4 : 9);
        for (int k = kbeg; k < kend; k++) {
            if (deg == 0) {
                const uint4* vp = (const uint4*)&g_val0b[(size_t)(e0+se)*64 + sq*16];
                uint32_t* col = XV + se*68 + sq*16;
#pragma unroll
                for (int i4 = 0; i4 < 4; i4++) *(uint4*)(col + i4*4) = vp[i4];
            } else {
                const float4* rp = (const float4*)&g_rad[(size_t)(e0+se)*384 + deg*128 + sq*32];
                const float4* xp = (sq < 2)
                    ? (const float4*)&g_xn[(size_t)src_s[se]*576 + k*64 + sq*32]
                    : (const float4*)&g_xn[(size_t)tgt_s[se]*576 + k*64 + (sq-2)*32];
                uint32_t* col = XV + se*68 + sq*16;
#pragma unroll
                for (int i4 = 0; i4 < 8; i4++) {
                    float4 xv = xp[i4], rv = rp[i4];
                    *(uint2*)(col + i4*2) =
                        make_uint2(f2bf2(xv.x*rv.x, xv.y*rv.y), f2bf2(xv.z*rv.z, xv.w*rv.w));
                }
            }
            if (k == kbeg) CP_WAIT0();
            __syncthreads();
            if (deg) {
                float acc[8][4] = {};
                gemm_mma<68,68,8>(W1s, XV, lane, mg, ng, acc);
                int l = (k < 4) ? 0 : 1;
#pragma unroll
                for (int mt = 0; mt < 2; mt++)
#pragma unroll
                for (int hf = 0; hf < 2; hf++) {
                    int el = ebase + mt*16 + hf*8;
                    size_t ge = (size_t)(e0 + el);
                    float r = rl_s[el*8 + (k-1)];
                    size_t gb = ge*128 + l*64;
                    size_t xb = (size_t)src_s[el]*512 + (size_t)(k-1)*64;
#pragma unroll
                    for (int nt = 0; nt < 4; nt++) {
                        int n = nbase + nt*8;
                        float2 gd = ubf2(g_gdirb[gb + (n>>1)]);
                        float2 gt = ubf2(g_gtenb[gb + (n>>1)]);
                        float2 xj = ubf2(g_xjpb[xb + (n>>1)]);
                        acc[mt*4+nt][hf*2+0] += r*gd.x + xj.x*gt.x;
                        acc[mt*4+nt][hf*2+1] += r*gd.y + xj.y*gt.y;
                    }
                }
                __syncthreads();
#pragma unroll
                for (int mt = 0; mt < 2; mt++)
#pragma unroll
                for (int hf = 0; hf < 2; hf++) {
                    int el = ebase + mt*16 + hf*8;
#pragma unroll
                    for (int nt = 0; nt < 4; nt++) {
                        int n = nbase + nt*8;
                        XV[el*68 + (n>>1)] =
                            f2bf2(acc[mt*4+nt][hf*2+0], acc[mt*4+nt][hf*2+1]);
                    }
                }
                __syncthreads();
            }
            float acc[8][4] = {};
            gemm_mma<68,68,8>(W2s, XV, lane, mg, ng, acc);
            // lane-paired red4 scatter: even lane covers n..n+3 (own pair + neighbor's)
#pragma unroll
            for (int mt = 0; mt < 2; mt++)
#pragma unroll
            for (int hf = 0; hf < 2; hf++) {
                int el = ebase + mt*16 + hf*8;
                size_t nb = (size_t)tgt_s[el]*1152 + (size_t)k*128;
#pragma unroll
                for (int nt = 0; nt < 4; nt++) {
                    int n = nbase + nt*8;
                    float s = ee_s[el*8 + (n >> 4)];
                    float v0 = acc[mt*4+nt][hf*2+0]*s;
                    float v1 = acc[mt*4+nt][hf*2+1]*s;
                    float v2 = __shfl_down_sync(0xffffffffu, v0, 1);
                    float v3 = __shfl_down_sync(0xffffffffu, v1, 1);
                    if (!(lane & 1)) red4(&g_num[nb + n], v0, v1, v2, v3);
                }
            }
            __syncthreads();
        }
    }
}

// ---------------- node GEMMs ----------------
#define P_T0 79
#define P_T1 314
#define P_GRID 705
__device__ __forceinline__ void node_row(int b, int* deg, int* rbase,
                                         int* nslots, int* soff, int* nrows)
{
    if (b < P_T0)      { *deg=0; *rbase=b*128;          *nslots=1; *soff=0; *nrows=10000; }
    else if (b < P_T1) { *deg=1; *rbase=(b-P_T0)*128;   *nslots=3; *soff=1; *nrows=30000; }
    else               { *deg=2; *rbase=(b-P_T1)*128;   *nslots=5; *soff=4; *nrows=50000; }
}

__global__ void __launch_bounds__(256,2) proj_mma(
    const float* __restrict__ x, const float* __restrict__ bp)
{
    extern __shared__ uint32_t sm[];
    uint32_t* Xs = sm;            // 8704
    uint32_t* Ws = sm + 8704;     // 4352
    int deg, rbase, nslots, soff, nrows;
    node_row(blockIdx.x, &deg, &rbase, &nslots, &soff, &nrows);
    int t = threadIdx.x, lane = t & 31, w = t >> 5, mg = w & 3, ng = w >> 2;
    cp_chunk<1088,256>(Ws, g_Wpc + deg*4352, t);
    {
        int r = t >> 1, h2 = t & 1;
        int gr = rbase + r;
        uint32_t* col = Xs + r*68 + h2*32;
        if (gr < nrows) {
            int node = gr / nslots, slot = soff + gr % nslots;
            const float4* np = (const float4*)&g_num[(size_t)node*1152 + slot*128 + h2*64];
            float di[4];
#pragma unroll
            for (int q = 0; q < 4; q++) di[q] = 1.f / (g_den[node*8 + h2*4 + q] + 1e-30f);
#pragma unroll
            for (int i = 0; i < 16; i++) {
                float4 v = np[i]; float d = di[i>>2];
                *(uint2*)(col + i*2) = make_uint2(f2bf2(v.x*d, v.y*d), f2bf2(v.z*d, v.w*d));
            }
        } else {
#pragma unroll
            for (int i = 0; i < 16; i++) *(uint2*)(col + i*2) = make_uint2(0,0);
        }
    }
    CP_WAIT0();
    __syncthreads();
    float acc[8][4] = {};
    gemm_mma<68,68,8>(Ws, Xs, lane, mg, ng, acc);
    int nbase = ng*32 + (lane&3)*2;
    int ebase = mg*32 + (lane>>2);
#pragma unroll
    for (int mt = 0; mt < 2; mt++)
#pragma unroll
    for (int hf = 0; hf < 2; hf++) {
        int gr = rbase + ebase + mt*16 + hf*8;
        if (gr >= nrows) continue;
        int node = gr / nslots, slot = soff + gr % nslots;
        size_t ob = (size_t)node*576 + slot*64;
#pragma unroll
        for (int nt = 0; nt < 4; nt++) {
            int n = nbase + nt*8;
            float b0 = (slot == 0) ? bp[n] : 0.f, b1 = (slot == 0) ? bp[n+1] : 0.f;
            *(float2*)&g_x1[ob + n] = make_float2(
                x[ob + n]   + acc[mt*4+nt][hf*2+0] + b0,
                x[ob + n+1] + acc[mt*4+nt][hf*2+1] + b1);
        }
    }
}

__global__ void __launch_bounds__(256,2) ffn2_mma(
    const float* __restrict__ bf2, float* __restrict__ out)
{
    extern __shared__ uint32_t sm[];
    uint32_t* Xs = sm;
    uint32_t* Ws = sm + 8704;
    int deg, rbase, nslots, soff, nrows;
    node_row(blockIdx.x, &deg, &rbase, &nslots, &soff, &nrows);
    int t = threadIdx.x, lane = t & 31, w = t >> 5, mg = w & 3, ng = w >> 2;
    cp_chunk<1088,256>(Ws, g_Wf2c + deg*4352, t);
    {
        int r = t >> 1, h2 = t & 1;
        int gr = rbase + r;
        uint32_t* col = Xs + r*68 + h2*32;
        if (gr < nrows) {
            int node = gr / nslots, slot = soff + gr % nslots;
            const float4* hp = (slot == 0)
                ? (const float4*)&g_gsil[(size_t)node*128 + h2*64]
                : (const float4*)&g_h[(size_t)node*1024 + (size_t)(slot-1)*128 + h2*64];
#pragma unroll
            for (int i = 0; i < 16; i++) {
                float4 v = hp[i];
                *(uint2*)(col + i*2) = make_uint2(f2bf2(v.x, v.y), f2bf2(v.z, v.w));
            }
        } else {
#pragma unroll
            for (int i = 0; i < 16; i++) *(uint2*)(col + i*2) = make_uint2(0,0);
        }
    }
    CP_WAIT0();
    __syncthreads();
    float acc[8][4] = {};
    gemm_mma<68,68,8>(Ws, Xs, lane, mg, ng, acc);
    int nbase = ng*32 + (lane&3)*2;
    int ebase = mg*32 + (lane>>2);
#pragma unroll
    for (int mt = 0; mt < 2; mt++)
#pragma unroll
    for (int hf = 0; hf < 2; hf++) {
        int gr = rbase + ebase + mt*16 + hf*8;
        if (gr >= nrows) continue;
        int node = gr / nslots, slot = soff + gr % nslots;
        size_t ob = (size_t)node*576 + slot*64;
#pragma unroll
        for (int nt = 0; nt < 4; nt++) {
            int n = nbase + nt*8;
            float b0 = (slot == 0) ? bf2[n] : 0.f, b1 = (slot == 0) ? bf2[n+1] : 0.f;
            *(float2*)&out[ob + n] = make_float2(
                g_x1[ob + n]   + acc[mt*4+nt][hf*2+0] + b0,
                g_x1[ob + n+1] + acc[mt*4+nt][hf*2+1] + b1);
        }
    }
}

#define F_T1 469
#define F_GRID 1251
__global__ void __launch_bounds__(256) ffn1_mma()
{
    extern __shared__ uint32_t sm[];
    uint32_t* Xs = sm;            // 2304
    uint32_t* Ws = sm + 2304;     // 4608
    int b = blockIdx.x, deg, rbase, nslots, soff, nrows;
    if (b < F_T1) { deg=1; rbase=b*64;         nslots=3; soff=1; nrows=30000; }
    else          { deg=2; rbase=(b-F_T1)*64;  nslots=5; soff=4; nrows=50000; }
    int t = threadIdx.x, lane = t & 31, w = t >> 5, mg = w & 1, ng = w >> 1;
    cp_chunk<1152,256>(Ws, g_Wf1c + deg*4608, t);
    {
        int r = t >> 2, q = t & 3;
        int gr = rbase + r;
        uint32_t* col = Xs + r*36 + q*8;
        if (gr < nrows) {
            int node = gr / nslots, slot = soff + gr % nslots;
            const float4* yp = (const float4*)&g_yn[(size_t)node*576 + slot*64 + q*16];
#pragma unroll
            for (int i = 0; i < 4; i++) {
                float4 v = yp[i];
                *(uint2*)(col + i*2) = make_uint2(f2bf2(v.x, v.y), f2bf2(v.z, v.w));
            }
        } else {
#pragma unroll
            for (int i = 0; i < 4; i++) *(uint2*)(col + i*2) = make_uint2(0,0);
        }
    }
    CP_WAIT0();
    __syncthreads();
    float acc[8][4] = {};
    gemm_mma<36,36,4>(Ws, Xs, lane, mg, ng, acc);
    int nbase = ng*32 + (lane&3)*2;
    int ebase = mg*32 + (lane>>2);
#pragma unroll
    for (int mt = 0; mt < 2; mt++)
#pragma unroll
    for (int hf = 0; hf < 2; hf++) {
        int gr = rbase + ebase + mt*16 + hf*8;
        if (gr >= nrows) continue;
        int node = gr / nslots, slot = soff + gr % nslots;
        size_t hb = (size_t)node*1024 + (size_t)(slot-1)*128;
        size_t gsb = (size_t)node*128;
#pragma unroll
        for (int nt = 0; nt < 4; nt++) {
            int n = nbase + nt*8;
            float2 gs = *(const float2*)&g_gsig[gsb + n];
            *(float2*)&g_h[hb + n] = make_float2(
                acc[mt*4+nt][hf*2+0]*gs.x, acc[mt*4+nt][hf*2+1]*gs.y);
        }
    }
}

// ---------------- launch ----------------
extern "C" void kernel_launch(void* const* d_in, const int* in_sizes, int n_in,
                              void* d_out, int out_size)
{
    const float* x     = (const float*)d_in[0];
    const float* edist = (const float*)d_in[1];
    const float* rl    = (const float*)d_in[2];
    const float* semb  = (const float*)d_in[3];
    const float* temb  = (const float*)d_in[4];
    const float* W1    = (const float*)d_in[5];
    const float* b1    = (const float*)d_in[6];
    const float* W2    = (const float*)d_in[7];
    const float* b2    = (const float*)d_in[8];
    const float* Wc1   = (const float*)d_in[9];
    const float* Wm0   = (const float*)d_in[10];
    const float* lng   = (const float*)d_in[11];
    const float* lnb   = (const float*)d_in[12];
    const float* adot  = (const float*)d_in[13];
    const float* Wxj   = (const float*)d_in[14];
    const float* Wc2   = (const float*)d_in[15];
    const float* Wp    = (const float*)d_in[16];
    const float* bp    = (const float*)d_in[17];
    const float* Wg    = (const float*)d_in[18];
    const float* bg    = (const float*)d_in[19];
    const float* Wf1   = (const float*)d_in[20];
    const float* Wf2   = (const float*)d_in[22];
    const float* bf2   = (const float*)d_in[23];
    const int*   anum  = (const int*)d_in[24];
    const int*   eidx  = (const int*)d_in[25];
    float* out = (float*)d_out;

    float *p_xn, *p_x1, *p_yn;
    cudaGetSymbolAddress((void**)&p_xn, g_xn);
    cudaGetSymbolAddress((void**)&p_x1, g_x1);
    cudaGetSymbolAddress((void**)&p_yn, g_yn);

    static bool attr_set = false;
    if (!attr_set) {
        cudaFuncSetAttribute(rad_kernel,   cudaFuncAttributeMaxDynamicSharedMemorySize, 91136);
        cudaFuncSetAttribute(extra_kernel, cudaFuncAttributeMaxDynamicSharedMemorySize, 91136);
        cudaFuncSetAttribute(conv_kernel,  cudaFuncAttributeMaxDynamicSharedMemorySize, 113664);
        cudaFuncSetAttribute(proj_mma,     cudaFuncAttributeMaxDynamicSharedMemorySize, 52224);
        cudaFuncSetAttribute(ffn2_mma,     cudaFuncAttributeMaxDynamicSharedMemorySize, 52224);
        cudaFuncSetAttribute(ffn1_mma,     cudaFuncAttributeMaxDynamicSharedMemorySize, 27648);
        cudaFuncSetAttribute(xjp_mma,      cudaFuncAttributeMaxDynamicSharedMemorySize, 27648);
        cudaFuncSetAttribute(gate_mma,     cudaFuncAttributeMaxDynamicSharedMemorySize, 27648);
        attr_set = true;
    }

    wconv_kernel<<<(WCONV_N + 255)/256, 256>>>(W1, W2, Wm0, Wc1, Wc2, Wp, Wf1, Wf2, Wxj, Wg);
    zero_kernel<<<(NN*1152/4 + 255)/256, 256>>>();
    enorm_kernel<<<NN/4, 256>>>(x, p_xn);
    xjp_mma<<<XJ_GRID, 256, 27648>>>();
    rad_kernel<<<NE/128, 512, 91136>>>(edist, semb, temb, b1, b2, anum, eidx);
    extra_kernel<<<NE/128, 512, 91136>>>(lng, lnb, adot, eidx);
    conv_kernel<<<NE/128, 512, 113664>>>(rl, eidx);
    proj_mma<<<P_GRID, 256, 52224>>>(x, bp);
    enorm_kernel<<<NN/4, 256>>>(p_x1, p_yn);
    gate_mma<<<GATE_GRID, 256, 27648>>>(bg);
    ffn1_mma<<<F_GRID, 256, 27648>>>();
    ffn2_mma<<<P_GRID, 256, 52224>>>(bf2, out);
}